// round 2
// baseline (speedup 1.0000x reference)
#include <cuda_runtime.h>
#include <math.h>

#define NB 16
#define NN 8192
#define NC 256
#define NM 32
#define NCH 16
#define TOKCH (NN/NCH)

typedef unsigned long long ull;

// ---------------- scratch ----------------
__device__ float g_xln[NB*NN*NC];
__device__ float g_x2 [NB*NN*NC];
__device__ unsigned int g_bkt[NB*NN];
__device__ float g_poolp[NCH*NB*NM*NC];
__device__ float g_cntp [NCH*NB*NM];
__device__ float g_k[NB*NM*NC];
__device__ float g_v[NB*NM*NC];
__device__ float g_A[NB*NC*NC];

// ---------------- f32x2 helpers ----------------
__device__ __forceinline__ ull pk2(float lo, float hi){ ull r; asm("mov.b64 %0,{%1,%2};":"=l"(r):"f"(lo),"f"(hi)); return r; }
__device__ __forceinline__ void fma2(ull&d, ull a, ull b){ asm("fma.rn.f32x2 %0,%1,%2,%0;":"+l"(d):"l"(a),"l"(b)); }
__device__ __forceinline__ float2 up2(ull v){ float2 r; asm("mov.b64 {%0,%1},%2;":"=f"(r.x),"=f"(r.y):"l"(v)); return r; }
__device__ __forceinline__ ull add2(ull a, ull b){ ull r; asm("add.rn.f32x2 %0,%1,%2;":"=l"(r):"l"(a),"l"(b)); return r; }

// ---------------- kernel 1: LN1 + LSH bucket assignment ----------------
__global__ __launch_bounds__(256) void k_ln1(const float* __restrict__ x, const float* __restrict__ rot,
                                             const float* __restrict__ g1, const float* __restrict__ b1){
    __shared__ float rT[16*256];
    __shared__ float sg[256], sb[256];
    int tid = threadIdx.x;
    for (int i = tid; i < 4096; i += 256) rT[(i&15)*256 + (i>>4)] = rot[i];
    sg[tid] = g1[tid]; sb[tid] = b1[tid];
    __syncthreads();
    int w = tid>>5, lane = tid&31;
    int base = blockIdx.x*128 + w*16;
    for (int t0 = 0; t0 < 16; t0++){
        int row = base + t0;
        const float* xr = x + (size_t)row*NC;
        float xv[8], s = 0.f, sq = 0.f;
        #pragma unroll
        for (int j = 0; j < 8; j++){ float v = xr[lane+32*j]; xv[j] = v; s += v; sq += v*v; }
        #pragma unroll
        for (int o = 16; o; o >>= 1){ s += __shfl_xor_sync(~0u,s,o); sq += __shfl_xor_sync(~0u,sq,o); }
        float m = s*(1.f/256.f);
        float rs = rsqrtf(sq*(1.f/256.f) - m*m + 1e-5f);
        float r16[16];
        #pragma unroll
        for (int i = 0; i < 16; i++) r16[i] = 0.f;
        float* xo = g_xln + (size_t)row*NC;
        #pragma unroll
        for (int j = 0; j < 8; j++){
            int c = lane + 32*j;
            float xn = (xv[j]-m)*rs*sg[c] + sb[c];
            xo[c] = xn;
            #pragma unroll
            for (int i = 0; i < 16; i++) r16[i] += xn * rT[i*256 + c];
        }
        #pragma unroll
        for (int i = 0; i < 16; i++){
            #pragma unroll
            for (int o = 16; o; o >>= 1) r16[i] += __shfl_xor_sync(~0u, r16[i], o);
        }
        if (!lane){
            unsigned pkb = 0;
            #pragma unroll
            for (int h = 0; h < 4; h++){
                float best = r16[h*4]; int bi = 0;
                #pragma unroll
                for (int i = 1; i < 8; i++){
                    float v = (i < 4) ? r16[h*4+i] : -r16[h*4+i-4];
                    if (v > best){ best = v; bi = i; }
                }
                pkb |= (unsigned)bi << (8*h);
            }
            g_bkt[row] = pkb;
        }
    }
}

// ---------------- kernel 2: deterministic bucket pooling (per-chunk partials) ----------------
__global__ __launch_bounds__(128) void k_pool(){
    extern __shared__ float sp[];             // 4 warps * 32 buckets * 256 + 4*32 counts
    float* scnt = sp + 4*32*256;
    int tid = threadIdx.x, w = tid>>5, lane = tid&31;
    int ch = blockIdx.x, b = blockIdx.y;
    for (int i = tid; i < 4*32*256; i += 128) sp[i] = 0.f;
    if (tid < 128) scnt[tid] = 0.f;
    __syncthreads();
    float* myp = sp + w*32*256;
    float* myc = scnt + w*32;
    int n0 = ch*TOKCH + w*(TOKCH/4);
    for (int it = 0; it < TOKCH/4; it++){
        int row = b*NN + n0 + it;
        unsigned pkb = g_bkt[row];
        const float* xr = g_xln + (size_t)row*NC;
        float xv[8];
        #pragma unroll
        for (int j = 0; j < 8; j++) xv[j] = xr[lane+32*j];
        #pragma unroll
        for (int h = 0; h < 4; h++){
            int hm = h*8 + ((pkb >> (8*h)) & 255);
            float* dst = myp + hm*256;
            #pragma unroll
            for (int j = 0; j < 8; j++) dst[lane+32*j] += xv[j];
            if (!lane) myc[hm] += 1.f;
        }
    }
    __syncthreads();
    float* op = g_poolp + (size_t)(ch*NB + b)*NM*NC;
    for (int i = tid; i < NM*NC; i += 128)
        op[i] = sp[i] + sp[32*256+i] + sp[2*32*256+i] + sp[3*32*256+i];
    if (tid < NM)
        g_cntp[(ch*NB+b)*NM + tid] = scnt[tid] + scnt[32+tid] + scnt[64+tid] + scnt[96+tid];
}

// ---------------- kernel 3: pooled KV projection ----------------
__global__ __launch_bounds__(256) void k_kv(const float* __restrict__ kvw){
    __shared__ float rp[8*256];
    __shared__ float scn[8];
    int tid = threadIdx.x;
    int mg = blockIdx.x, b = blockIdx.y;
    if (tid < 8){
        float c = 0.f;
        for (int ch = 0; ch < NCH; ch++) c += g_cntp[(ch*NB+b)*NM + mg*8 + tid];
        scn[tid] = c;
    }
    __syncthreads();
    for (int i = tid; i < 8*256; i += 256){
        int mi = i>>8;
        float s = 0.f;
        for (int ch = 0; ch < NCH; ch++)
            s += g_poolp[((size_t)(ch*NB+b)*NM + mg*8 + mi)*NC + (i&255)];
        rp[i] = s / (scn[mi] + 1e-20f);
    }
    __syncthreads();
    int j = tid;
    ull acc[8];
    #pragma unroll
    for (int i = 0; i < 8; i++) acc[i] = pk2(0.f,0.f);
    for (int c = 0; c < 256; c++){
        float w0 = kvw[(size_t)c*512 + j];
        float w1 = kvw[(size_t)c*512 + 256 + j];
        ull wv = pk2(w0, w1);
        #pragma unroll
        for (int i = 0; i < 8; i++){ float a = rp[i*256+c]; fma2(acc[i], pk2(a,a), wv); }
    }
    #pragma unroll
    for (int i = 0; i < 8; i++){
        float2 f = up2(acc[i]);
        int m = mg*8 + i;
        g_k[((size_t)b*NM+m)*NC + j] = f.x;
        g_v[((size_t)b*NM+m)*NC + j] = f.y;
    }
}

// ---------------- kernel 4: A = scale * q_w @ k^T (per batch/head) ----------------
__global__ __launch_bounds__(256) void k_prep(const float* __restrict__ qw){
    __shared__ float ks[32*32];
    int c = threadIdx.x, b = blockIdx.x, h = blockIdx.y;
    for (int i = c; i < 1024; i += 256)
        ks[i] = g_k[((size_t)b*NM + (i>>5))*NC + h*32 + (i&31)];
    __syncthreads();
    float4 q4[8];
    const float4* qp = (const float4*)(qw + (size_t)c*NC + h*32);
    #pragma unroll
    for (int i = 0; i < 8; i++) q4[i] = qp[i];
    const ull* qu = (const ull*)q4;
    float* Ao = g_A + ((size_t)b*NC + c)*NC + h*32;
    const float scale = 0.17677669529663689f;   // 32^-0.5
    for (int m = 0; m < 32; m++){
        const ull* kr = (const ull*)(ks + m*32);
        ull acc = pk2(0.f,0.f);
        #pragma unroll
        for (int i = 0; i < 16; i++) fma2(acc, qu[i], kr[i]);
        float2 f = up2(acc);
        Ao[m] = (f.x + f.y) * scale;
    }
}

// ---------------- kernel 5: fused logits GEMM + softmax + PV + residual ----------------
__global__ __launch_bounds__(256) void k_qattn(const float* __restrict__ x){
    extern __shared__ float sm[];
    float* xln_s = sm;                 // 64 x 260
    float* v_s   = sm + 64*260;        // 8 heads x (32*36+4) = 8*1156
    float* cnt_s = v_s + 8*1156;       // 32
    int tid = threadIdx.x;
    int row0 = blockIdx.x*64;
    int b = row0 >> 13;
    for (int i = tid; i < 64*64; i += 256){
        int t = i>>6, c4 = i&63;
        float4 v = ((const float4*)(g_xln + (size_t)(row0+t)*NC))[c4];
        *(float4*)(xln_s + t*260 + c4*4) = v;
    }
    for (int i = tid; i < NM*NC; i += 256){
        int m = i>>8, cc = i&255, h = cc>>5, d = cc&31;
        v_s[h*1156 + m*36 + d] = g_v[((size_t)b*NM+m)*NC + cc];
    }
    if (tid < NM){
        float c = 0.f;
        for (int ch = 0; ch < NCH; ch++) c += g_cntp[(ch*NB+b)*NM + tid];
        cnt_s[tid] = c;
    }
    __syncthreads();
    int ty = tid>>4, tx = tid&15;
    const float* Ab = g_A + (size_t)b*NC*NC + tx*16;
    ull acc[4][8];
    #pragma unroll
    for (int i = 0; i < 4; i++)
        #pragma unroll
        for (int j = 0; j < 8; j++) acc[i][j] = pk2(0.f,0.f);
    const float* as = xln_s + ty*4*260;
    #pragma unroll 2
    for (int c = 0; c < 256; c++){
        ull av[4];
        #pragma unroll
        for (int i = 0; i < 4; i++){ float a = as[i*260 + c]; av[i] = pk2(a,a); }
        const ulonglong2* bp = (const ulonglong2*)(Ab + (size_t)c*NC);
        ulonglong2 u0 = bp[0], u1 = bp[1], u2 = bp[2], u3 = bp[3];
        ull bu[8] = {u0.x,u0.y,u1.x,u1.y,u2.x,u2.y,u3.x,u3.y};
        #pragma unroll
        for (int i = 0; i < 4; i++)
            #pragma unroll
            for (int j = 0; j < 8; j++) fma2(acc[i][j], av[i], bu[j]);
    }
    int h = tx>>1, mb = (tx&1)*16;
    for (int i = 0; i < 4; i++){
        int row = row0 + ty*4 + i;
        float l[16];
        #pragma unroll
        for (int j = 0; j < 8; j++){ float2 f = up2(acc[i][j]); l[2*j] = f.x; l[2*j+1] = f.y; }
        float mx = -3.0e38f;
        #pragma unroll
        for (int j = 0; j < 16; j++) if (cnt_s[mb+j] >= 1.f && l[j] > mx) mx = l[j];
        mx = fmaxf(mx, __shfl_xor_sync(~0u, mx, 1));
        float e[16], ssum = 0.f;
        #pragma unroll
        for (int j = 0; j < 16; j++){ e[j] = (cnt_s[mb+j] >= 1.f) ? expf(l[j]-mx) : 0.f; ssum += e[j]; }
        ssum += __shfl_xor_sync(~0u, ssum, 1);
        float inv = 1.f/ssum;
        ull oacc[16];
        #pragma unroll
        for (int q = 0; q < 16; q++) oacc[q] = pk2(0.f,0.f);
        #pragma unroll
        for (int j = 0; j < 16; j++){
            float p = e[j]*inv;
            ull pv = pk2(p,p);
            const ulonglong2* vr = (const ulonglong2*)(v_s + h*1156 + (mb+j)*36);
            #pragma unroll
            for (int q = 0; q < 8; q++){ ulonglong2 u = vr[q]; fma2(oacc[2*q], pv, u.x); fma2(oacc[2*q+1], pv, u.y); }
        }
        #pragma unroll
        for (int q = 0; q < 16; q++){
            ull o = __shfl_xor_sync(~0u, oacc[q], 1);
            oacc[q] = add2(oacc[q], o);
        }
        if (!(tx&1)){
            const float4* xr = (const float4*)(x + (size_t)row*NC + h*32);
            float4* xo = (float4*)(g_x2 + (size_t)row*NC + h*32);
            #pragma unroll
            for (int q = 0; q < 8; q++){
                float2 f0 = up2(oacc[2*q]), f1 = up2(oacc[2*q+1]);
                float4 xv = xr[q];
                float4 r; r.x = xv.x+f0.x; r.y = xv.y+f0.y; r.z = xv.z+f1.x; r.w = xv.w+f1.y;
                xo[q] = r;
            }
        }
    }
}

// ---------------- kernel 6: fused LN2 + MLP(GELU) + residual ----------------
__global__ __launch_bounds__(256,1) void k_mlp(const float* __restrict__ ng2, const float* __restrict__ nb2,
                                               const float* __restrict__ w1, const float* __restrict__ b1v,
                                               const float* __restrict__ w2, const float* __restrict__ b2v,
                                               float* __restrict__ out){
    extern __shared__ float sm[];
    float* y_s = sm;            // 64 x 260
    float* h_s = sm + 64*260;   // 64 x 260
    int tid = threadIdx.x;
    int row0 = blockIdx.x*64;
    int w = tid>>5, lane = tid&31;
    float g2r[8], b2r[8];
    #pragma unroll
    for (int j = 0; j < 8; j++){ g2r[j] = ng2[lane+32*j]; b2r[j] = nb2[lane+32*j]; }
    for (int it = 0; it < 8; it++){
        int t = w*8 + it;
        const float* xr = g_x2 + (size_t)(row0+t)*NC;
        float xv[8], s = 0.f, sq = 0.f;
        #pragma unroll
        for (int j = 0; j < 8; j++){ float v = xr[lane+32*j]; xv[j] = v; s += v; sq += v*v; }
        #pragma unroll
        for (int o = 16; o; o >>= 1){ s += __shfl_xor_sync(~0u,s,o); sq += __shfl_xor_sync(~0u,sq,o); }
        float m = s*(1.f/256.f);
        float rs = rsqrtf(sq*(1.f/256.f) - m*m + 1e-5f);
        #pragma unroll
        for (int j = 0; j < 8; j++){
            int cc = lane+32*j;
            y_s[t*260 + cc] = (xv[j]-m)*rs*g2r[j] + b2r[j];
        }
    }
    __syncthreads();
    int ty = tid>>4, tx = tid&15;
    const float* as = y_s + ty*4*260;
    const float* hs2 = h_s + ty*4*260;
    ull acc2[4][8];
    #pragma unroll
    for (int i = 0; i < 4; i++)
        #pragma unroll
        for (int j = 0; j < 8; j++) acc2[i][j] = pk2(0.f,0.f);
    for (int ck = 0; ck < 4; ck++){
        ull acc1[4][8];
        #pragma unroll
        for (int i = 0; i < 4; i++)
            #pragma unroll
            for (int j = 0; j < 8; j++) acc1[i][j] = pk2(0.f,0.f);
        const float* Bw = w1 + ck*256 + tx*16;
        #pragma unroll 2
        for (int c = 0; c < 256; c++){
            ull av[4];
            #pragma unroll
            for (int i = 0; i < 4; i++){ float a = as[i*260 + c]; av[i] = pk2(a,a); }
            const ulonglong2* bp = (const ulonglong2*)(Bw + (size_t)c*1024);
            ulonglong2 u0 = bp[0], u1 = bp[1], u2 = bp[2], u3 = bp[3];
            ull bu[8] = {u0.x,u0.y,u1.x,u1.y,u2.x,u2.y,u3.x,u3.y};
            #pragma unroll
            for (int i = 0; i < 4; i++)
                #pragma unroll
                for (int j = 0; j < 8; j++) fma2(acc1[i][j], av[i], bu[j]);
        }
        float bb[16];
        const float* b1p = b1v + ck*256 + tx*16;
        #pragma unroll
        for (int j = 0; j < 16; j++) bb[j] = b1p[j];
        __syncthreads();   // previous chunk's GEMM2 done with h_s
        #pragma unroll
        for (int i = 0; i < 4; i++){
            float hv[16];
            #pragma unroll
            for (int j = 0; j < 8; j++){ float2 f = up2(acc1[i][j]); hv[2*j] = f.x + bb[2*j]; hv[2*j+1] = f.y + bb[2*j+1]; }
            #pragma unroll
            for (int j = 0; j < 16; j++){ float u = hv[j]; hv[j] = 0.5f*u*(1.f + erff(u*0.70710678118654752f)); }
            float4* hp = (float4*)(h_s + (ty*4+i)*260 + tx*16);
            #pragma unroll
            for (int q = 0; q < 4; q++) hp[q] = make_float4(hv[4*q],hv[4*q+1],hv[4*q+2],hv[4*q+3]);
        }
        __syncthreads();
        const float* Bw2 = w2 + (size_t)ck*256*256 + tx*16;
        #pragma unroll 2
        for (int c = 0; c < 256; c++){
            ull av[4];
            #pragma unroll
            for (int i = 0; i < 4; i++){ float a = hs2[i*260 + c]; av[i] = pk2(a,a); }
            const ulonglong2* bp = (const ulonglong2*)(Bw2 + (size_t)c*256);
            ulonglong2 u0 = bp[0], u1 = bp[1], u2 = bp[2], u3 = bp[3];
            ull bu[8] = {u0.x,u0.y,u1.x,u1.y,u2.x,u2.y,u3.x,u3.y};
            #pragma unroll
            for (int i = 0; i < 4; i++)
                #pragma unroll
                for (int j = 0; j < 8; j++) fma2(acc2[i][j], av[i], bu[j]);
        }
    }
    float bo[16];
    const float* b2p = b2v + tx*16;
    #pragma unroll
    for (int j = 0; j < 16; j++) bo[j] = b2p[j];
    for (int i = 0; i < 4; i++){
        int row = row0 + ty*4 + i;
        const float4* x2r = (const float4*)(g_x2 + (size_t)row*NC + tx*16);
        float4* op = (float4*)(out + (size_t)row*NC + tx*16);
        #pragma unroll
        for (int q = 0; q < 4; q++){
            float2 f0 = up2(acc2[i][2*q]), f1 = up2(acc2[i][2*q+1]);
            float4 xv = x2r[q];
            float4 r;
            r.x = xv.x + f0.x + bo[4*q+0];
            r.y = xv.y + f0.y + bo[4*q+1];
            r.z = xv.z + f1.x + bo[4*q+2];
            r.w = xv.w + f1.y + bo[4*q+3];
            op[q] = r;
        }
    }
}

// ---------------- launch ----------------
extern "C" void kernel_launch(void* const* d_in, const int* in_sizes, int n_in,
                              void* d_out, int out_size) {
    const float* x   = (const float*)d_in[0];
    const float* rot = (const float*)d_in[1];
    const float* n1g = (const float*)d_in[2];
    const float* n1b = (const float*)d_in[3];
    const float* qw  = (const float*)d_in[4];
    const float* kvw = (const float*)d_in[5];
    const float* n2g = (const float*)d_in[6];
    const float* n2b = (const float*)d_in[7];
    const float* w1  = (const float*)d_in[8];
    const float* b1  = (const float*)d_in[9];
    const float* w2  = (const float*)d_in[10];
    const float* b2  = (const float*)d_in[11];
    float* out = (float*)d_out;

    const int POOL_SM = (4*32*256 + 128)*4;                 // 131584
    const int QSM     = (64*260 + 8*1156 + 32)*4;           // 103680
    const int MSM     = (2*64*260)*4;                       // 133120
    cudaFuncSetAttribute(k_pool,  cudaFuncAttributeMaxDynamicSharedMemorySize, POOL_SM);
    cudaFuncSetAttribute(k_qattn, cudaFuncAttributeMaxDynamicSharedMemorySize, QSM);
    cudaFuncSetAttribute(k_mlp,   cudaFuncAttributeMaxDynamicSharedMemorySize, MSM);

    k_ln1<<<(NB*NN)/128, 256>>>(x, rot, n1g, n1b);
    k_pool<<<dim3(NCH, NB), 128, POOL_SM>>>();
    k_kv<<<dim3(4, NB), 256>>>(kvw);
    k_prep<<<dim3(NB, 8), 256>>>(qw);
    k_qattn<<<(NB*NN)/64, 256, QSM>>>(x);
    k_mlp<<<(NB*NN)/64, 256, MSM>>>(n2g, n2b, w1, b1, w2, b2, out);
}

// round 3
// speedup vs baseline: 1.0014x; 1.0014x over previous
#include <cuda_runtime.h>
#include <math.h>

#define NB 16
#define NN 8192
#define NC 256
#define NM 32
#define NCH 16
#define TOKCH (NN/NCH)

typedef unsigned long long ull;

// ---------------- scratch ----------------
__device__ float g_xln[NB*NN*NC];
__device__ float g_x2 [NB*NN*NC];
__device__ unsigned int g_bkt[NB*NN];
__device__ float g_poolp[NCH*NB*NM*NC];
__device__ float g_cntp [NCH*NB*NM];
__device__ float g_k[NB*NM*NC];
__device__ float g_v[NB*NM*NC];
__device__ float g_A[NB*NC*NC];

// ---------------- f32x2 helpers ----------------
__device__ __forceinline__ ull pk2(float lo, float hi){ ull r; asm("mov.b64 %0,{%1,%2};":"=l"(r):"f"(lo),"f"(hi)); return r; }
__device__ __forceinline__ void fma2(ull&d, ull a, ull b){ asm("fma.rn.f32x2 %0,%1,%2,%0;":"+l"(d):"l"(a),"l"(b)); }
__device__ __forceinline__ float2 up2(ull v){ float2 r; asm("mov.b64 {%0,%1},%2;":"=f"(r.x),"=f"(r.y):"l"(v)); return r; }
__device__ __forceinline__ ull add2(ull a, ull b){ ull r; asm("add.rn.f32x2 %0,%1,%2;":"=l"(r):"l"(a),"l"(b)); return r; }

// ---------------- kernel 1: LN1 + LSH bucket assignment ----------------
__global__ __launch_bounds__(256) void k_ln1(const float* __restrict__ x, const float* __restrict__ rot,
                                             const float* __restrict__ g1, const float* __restrict__ b1){
    __shared__ float rT[16*256];
    __shared__ float sg[256], sb[256];
    int tid = threadIdx.x;
    for (int i = tid; i < 4096; i += 256) rT[(i&15)*256 + (i>>4)] = rot[i];
    sg[tid] = g1[tid]; sb[tid] = b1[tid];
    __syncthreads();
    int w = tid>>5, lane = tid&31;
    int base = blockIdx.x*128 + w*16;
    for (int t0 = 0; t0 < 16; t0++){
        int row = base + t0;
        const float* xr = x + (size_t)row*NC;
        float xv[8], s = 0.f, sq = 0.f;
        #pragma unroll
        for (int j = 0; j < 8; j++){ float v = xr[lane+32*j]; xv[j] = v; s += v; sq += v*v; }
        #pragma unroll
        for (int o = 16; o; o >>= 1){ s += __shfl_xor_sync(~0u,s,o); sq += __shfl_xor_sync(~0u,sq,o); }
        float m = s*(1.f/256.f);
        float rs = rsqrtf(sq*(1.f/256.f) - m*m + 1e-5f);
        float r16[16];
        #pragma unroll
        for (int i = 0; i < 16; i++) r16[i] = 0.f;
        float* xo = g_xln + (size_t)row*NC;
        #pragma unroll
        for (int j = 0; j < 8; j++){
            int c = lane + 32*j;
            float xn = (xv[j]-m)*rs*sg[c] + sb[c];
            xo[c] = xn;
            #pragma unroll
            for (int i = 0; i < 16; i++) r16[i] += xn * rT[i*256 + c];
        }
        #pragma unroll
        for (int i = 0; i < 16; i++){
            #pragma unroll
            for (int o = 16; o; o >>= 1) r16[i] += __shfl_xor_sync(~0u, r16[i], o);
        }
        if (!lane){
            unsigned pkb = 0;
            #pragma unroll
            for (int h = 0; h < 4; h++){
                float best = r16[h*4]; int bi = 0;
                #pragma unroll
                for (int i = 1; i < 8; i++){
                    float v = (i < 4) ? r16[h*4+i] : -r16[h*4+i-4];
                    if (v > best){ best = v; bi = i; }
                }
                pkb |= (unsigned)bi << (8*h);
            }
            g_bkt[row] = pkb;
        }
    }
}

// ---------------- kernel 2: deterministic bucket pooling (per-chunk partials) ----------------
__global__ __launch_bounds__(128) void k_pool(){
    extern __shared__ float sp[];             // 4 warps * 32 buckets * 256 + 4*32 counts
    float* scnt = sp + 4*32*256;
    int tid = threadIdx.x, w = tid>>5, lane = tid&31;
    int ch = blockIdx.x, b = blockIdx.y;
    for (int i = tid; i < 4*32*256; i += 128) sp[i] = 0.f;
    if (tid < 128) scnt[tid] = 0.f;
    __syncthreads();
    float* myp = sp + w*32*256;
    float* myc = scnt + w*32;
    int n0 = ch*TOKCH + w*(TOKCH/4);
    for (int it = 0; it < TOKCH/4; it++){
        int row = b*NN + n0 + it;
        unsigned pkb = g_bkt[row];
        const float* xr = g_xln + (size_t)row*NC;
        float xv[8];
        #pragma unroll
        for (int j = 0; j < 8; j++) xv[j] = xr[lane+32*j];
        #pragma unroll
        for (int h = 0; h < 4; h++){
            int hm = h*8 + ((pkb >> (8*h)) & 255);
            float* dst = myp + hm*256;
            #pragma unroll
            for (int j = 0; j < 8; j++) dst[lane+32*j] += xv[j];
            if (!lane) myc[hm] += 1.f;
        }
    }
    __syncthreads();
    float* op = g_poolp + (size_t)(ch*NB + b)*NM*NC;
    for (int i = tid; i < NM*NC; i += 128)
        op[i] = sp[i] + sp[32*256+i] + sp[2*32*256+i] + sp[3*32*256+i];
    if (tid < NM)
        g_cntp[(ch*NB+b)*NM + tid] = scnt[tid] + scnt[32+tid] + scnt[64+tid] + scnt[96+tid];
}

// ---------------- kernel 3: pooled KV projection ----------------
__global__ __launch_bounds__(256) void k_kv(const float* __restrict__ kvw){
    __shared__ float rp[8*256];
    __shared__ float scn[8];
    int tid = threadIdx.x;
    int mg = blockIdx.x, b = blockIdx.y;
    if (tid < 8){
        float c = 0.f;
        for (int ch = 0; ch < NCH; ch++) c += g_cntp[(ch*NB+b)*NM + mg*8 + tid];
        scn[tid] = c;
    }
    __syncthreads();
    for (int i = tid; i < 8*256; i += 256){
        int mi = i>>8;
        float s = 0.f;
        for (int ch = 0; ch < NCH; ch++)
            s += g_poolp[((size_t)(ch*NB+b)*NM + mg*8 + mi)*NC + (i&255)];
        rp[i] = s / (scn[mi] + 1e-20f);
    }
    __syncthreads();
    int j = tid;
    ull acc[8];
    #pragma unroll
    for (int i = 0; i < 8; i++) acc[i] = pk2(0.f,0.f);
    for (int c = 0; c < 256; c++){
        float w0 = kvw[(size_t)c*512 + j];
        float w1 = kvw[(size_t)c*512 + 256 + j];
        ull wv = pk2(w0, w1);
        #pragma unroll
        for (int i = 0; i < 8; i++){ float a = rp[i*256+c]; fma2(acc[i], pk2(a,a), wv); }
    }
    #pragma unroll
    for (int i = 0; i < 8; i++){
        float2 f = up2(acc[i]);
        int m = mg*8 + i;
        g_k[((size_t)b*NM+m)*NC + j] = f.x;
        g_v[((size_t)b*NM+m)*NC + j] = f.y;
    }
}

// ---------------- kernel 4: A = scale * q_w @ k^T (per batch/head) ----------------
__global__ __launch_bounds__(256) void k_prep(const float* __restrict__ qw){
    __shared__ float ks[32*32];
    int c = threadIdx.x, b = blockIdx.x, h = blockIdx.y;
    for (int i = c; i < 1024; i += 256)
        ks[i] = g_k[((size_t)b*NM + (i>>5))*NC + h*32 + (i&31)];
    __syncthreads();
    float4 q4[8];
    const float4* qp = (const float4*)(qw + (size_t)c*NC + h*32);
    #pragma unroll
    for (int i = 0; i < 8; i++) q4[i] = qp[i];
    const ull* qu = (const ull*)q4;
    float* Ao = g_A + ((size_t)b*NC + c)*NC + h*32;
    const float scale = 0.17677669529663689f;   // 32^-0.5
    for (int m = 0; m < 32; m++){
        const ull* kr = (const ull*)(ks + m*32);
        ull acc = pk2(0.f,0.f);
        #pragma unroll
        for (int i = 0; i < 16; i++) fma2(acc, qu[i], kr[i]);
        float2 f = up2(acc);
        Ao[m] = (f.x + f.y) * scale;
    }
}

// ---------------- kernel 5: fused logits GEMM + softmax + PV + residual ----------------
__global__ __launch_bounds__(256) void k_qattn(const float* __restrict__ x){
    extern __shared__ float sm[];
    float* xln_s = sm;                 // 64 x 260
    float* v_s   = sm + 64*260;        // 8 heads x (32*36+4) = 8*1156
    float* cnt_s = v_s + 8*1156;       // 32
    int tid = threadIdx.x;
    int row0 = blockIdx.x*64;
    int b = row0 >> 13;
    for (int i = tid; i < 64*64; i += 256){
        int t = i>>6, c4 = i&63;
        float4 v = ((const float4*)(g_xln + (size_t)(row0+t)*NC))[c4];
        *(float4*)(xln_s + t*260 + c4*4) = v;
    }
    for (int i = tid; i < NM*NC; i += 256){
        int m = i>>8, cc = i&255, h = cc>>5, d = cc&31;
        v_s[h*1156 + m*36 + d] = g_v[((size_t)b*NM+m)*NC + cc];
    }
    if (tid < NM){
        float c = 0.f;
        for (int ch = 0; ch < NCH; ch++) c += g_cntp[(ch*NB+b)*NM + tid];
        cnt_s[tid] = c;
    }
    __syncthreads();
    int ty = tid>>4, tx = tid&15;
    const float* Ab = g_A + (size_t)b*NC*NC + tx*16;
    ull acc[4][8];
    #pragma unroll
    for (int i = 0; i < 4; i++)
        #pragma unroll
        for (int j = 0; j < 8; j++) acc[i][j] = pk2(0.f,0.f);
    const float* as = xln_s + ty*4*260;
    #pragma unroll 2
    for (int c = 0; c < 256; c++){
        ull av[4];
        #pragma unroll
        for (int i = 0; i < 4; i++){ float a = as[i*260 + c]; av[i] = pk2(a,a); }
        const ulonglong2* bp = (const ulonglong2*)(Ab + (size_t)c*NC);
        ulonglong2 u0 = bp[0], u1 = bp[1], u2 = bp[2], u3 = bp[3];
        ull bu[8] = {u0.x,u0.y,u1.x,u1.y,u2.x,u2.y,u3.x,u3.y};
        #pragma unroll
        for (int i = 0; i < 4; i++)
            #pragma unroll
            for (int j = 0; j < 8; j++) fma2(acc[i][j], av[i], bu[j]);
    }
    int h = tx>>1, mb = (tx&1)*16;
    for (int i = 0; i < 4; i++){
        int row = row0 + ty*4 + i;
        float l[16];
        #pragma unroll
        for (int j = 0; j < 8; j++){ float2 f = up2(acc[i][j]); l[2*j] = f.x; l[2*j+1] = f.y; }
        float mx = -3.0e38f;
        #pragma unroll
        for (int j = 0; j < 16; j++) if (cnt_s[mb+j] >= 1.f && l[j] > mx) mx = l[j];
        mx = fmaxf(mx, __shfl_xor_sync(~0u, mx, 1));
        float e[16], ssum = 0.f;
        #pragma unroll
        for (int j = 0; j < 16; j++){ e[j] = (cnt_s[mb+j] >= 1.f) ? expf(l[j]-mx) : 0.f; ssum += e[j]; }
        ssum += __shfl_xor_sync(~0u, ssum, 1);
        float inv = 1.f/ssum;
        ull oacc[16];
        #pragma unroll
        for (int q = 0; q < 16; q++) oacc[q] = pk2(0.f,0.f);
        #pragma unroll
        for (int j = 0; j < 16; j++){
            float p = e[j]*inv;
            ull pv = pk2(p,p);
            const ulonglong2* vr = (const ulonglong2*)(v_s + h*1156 + (mb+j)*36);
            #pragma unroll
            for (int q = 0; q < 8; q++){ ulonglong2 u = vr[q]; fma2(oacc[2*q], pv, u.x); fma2(oacc[2*q+1], pv, u.y); }
        }
        #pragma unroll
        for (int q = 0; q < 16; q++){
            ull o = __shfl_xor_sync(~0u, oacc[q], 1);
            oacc[q] = add2(oacc[q], o);
        }
        if (!(tx&1)){
            const float4* xr = (const float4*)(x + (size_t)row*NC + h*32);
            float4* xo = (float4*)(g_x2 + (size_t)row*NC + h*32);
            #pragma unroll
            for (int q = 0; q < 8; q++){
                float2 f0 = up2(oacc[2*q]), f1 = up2(oacc[2*q+1]);
                float4 xv = xr[q];
                float4 r; r.x = xv.x+f0.x; r.y = xv.y+f0.y; r.z = xv.z+f1.x; r.w = xv.w+f1.y;
                xo[q] = r;
            }
        }
    }
}

// ---------------- kernel 6: fused LN2 + MLP(GELU) + residual ----------------
__global__ __launch_bounds__(256,1) void k_mlp(const float* __restrict__ ng2, const float* __restrict__ nb2,
                                               const float* __restrict__ w1, const float* __restrict__ b1v,
                                               const float* __restrict__ w2, const float* __restrict__ b2v,
                                               float* __restrict__ out){
    extern __shared__ float sm[];
    float* y_s = sm;            // 64 x 260
    float* h_s = sm + 64*260;   // 64 x 260
    int tid = threadIdx.x;
    int row0 = blockIdx.x*64;
    int w = tid>>5, lane = tid&31;
    float g2r[8], b2r[8];
    #pragma unroll
    for (int j = 0; j < 8; j++){ g2r[j] = ng2[lane+32*j]; b2r[j] = nb2[lane+32*j]; }
    for (int it = 0; it < 8; it++){
        int t = w*8 + it;
        const float* xr = g_x2 + (size_t)(row0+t)*NC;
        float xv[8], s = 0.f, sq = 0.f;
        #pragma unroll
        for (int j = 0; j < 8; j++){ float v = xr[lane+32*j]; xv[j] = v; s += v; sq += v*v; }
        #pragma unroll
        for (int o = 16; o; o >>= 1){ s += __shfl_xor_sync(~0u,s,o); sq += __shfl_xor_sync(~0u,sq,o); }
        float m = s*(1.f/256.f);
        float rs = rsqrtf(sq*(1.f/256.f) - m*m + 1e-5f);
        #pragma unroll
        for (int j = 0; j < 8; j++){
            int cc = lane+32*j;
            y_s[t*260 + cc] = (xv[j]-m)*rs*g2r[j] + b2r[j];
        }
    }
    __syncthreads();
    int ty = tid>>4, tx = tid&15;
    const float* as = y_s + ty*4*260;
    const float* hs2 = h_s + ty*4*260;
    ull acc2[4][8];
    #pragma unroll
    for (int i = 0; i < 4; i++)
        #pragma unroll
        for (int j = 0; j < 8; j++) acc2[i][j] = pk2(0.f,0.f);
    for (int ck = 0; ck < 4; ck++){
        ull acc1[4][8];
        #pragma unroll
        for (int i = 0; i < 4; i++)
            #pragma unroll
            for (int j = 0; j < 8; j++) acc1[i][j] = pk2(0.f,0.f);
        const float* Bw = w1 + ck*256 + tx*16;
        #pragma unroll 2
        for (int c = 0; c < 256; c++){
            ull av[4];
            #pragma unroll
            for (int i = 0; i < 4; i++){ float a = as[i*260 + c]; av[i] = pk2(a,a); }
            const ulonglong2* bp = (const ulonglong2*)(Bw + (size_t)c*1024);
            ulonglong2 u0 = bp[0], u1 = bp[1], u2 = bp[2], u3 = bp[3];
            ull bu[8] = {u0.x,u0.y,u1.x,u1.y,u2.x,u2.y,u3.x,u3.y};
            #pragma unroll
            for (int i = 0; i < 4; i++)
                #pragma unroll
                for (int j = 0; j < 8; j++) fma2(acc1[i][j], av[i], bu[j]);
        }
        float bb[16];
        const float* b1p = b1v + ck*256 + tx*16;
        #pragma unroll
        for (int j = 0; j < 16; j++) bb[j] = b1p[j];
        __syncthreads();   // previous chunk's GEMM2 done with h_s
        #pragma unroll
        for (int i = 0; i < 4; i++){
            float hv[16];
            #pragma unroll
            for (int j = 0; j < 8; j++){ float2 f = up2(acc1[i][j]); hv[2*j] = f.x + bb[2*j]; hv[2*j+1] = f.y + bb[2*j+1]; }
            #pragma unroll
            for (int j = 0; j < 16; j++){ float u = hv[j]; hv[j] = 0.5f*u*(1.f + erff(u*0.70710678118654752f)); }
            float4* hp = (float4*)(h_s + (ty*4+i)*260 + tx*16);
            #pragma unroll
            for (int q = 0; q < 4; q++) hp[q] = make_float4(hv[4*q],hv[4*q+1],hv[4*q+2],hv[4*q+3]);
        }
        __syncthreads();
        const float* Bw2 = w2 + (size_t)ck*256*256 + tx*16;
        #pragma unroll 2
        for (int c = 0; c < 256; c++){
            ull av[4];
            #pragma unroll
            for (int i = 0; i < 4; i++){ float a = hs2[i*260 + c]; av[i] = pk2(a,a); }
            const ulonglong2* bp = (const ulonglong2*)(Bw2 + (size_t)c*256);
            ulonglong2 u0 = bp[0], u1 = bp[1], u2 = bp[2], u3 = bp[3];
            ull bu[8] = {u0.x,u0.y,u1.x,u1.y,u2.x,u2.y,u3.x,u3.y};
            #pragma unroll
            for (int i = 0; i < 4; i++)
                #pragma unroll
                for (int j = 0; j < 8; j++) fma2(acc2[i][j], av[i], bu[j]);
        }
    }
    float bo[16];
    const float* b2p = b2v + tx*16;
    #pragma unroll
    for (int j = 0; j < 16; j++) bo[j] = b2p[j];
    for (int i = 0; i < 4; i++){
        int row = row0 + ty*4 + i;
        const float4* x2r = (const float4*)(g_x2 + (size_t)row*NC + tx*16);
        float4* op = (float4*)(out + (size_t)row*NC + tx*16);
        #pragma unroll
        for (int q = 0; q < 4; q++){
            float2 f0 = up2(acc2[i][2*q]), f1 = up2(acc2[i][2*q+1]);
            float4 xv = x2r[q];
            float4 r;
            r.x = xv.x + f0.x + bo[4*q+0];
            r.y = xv.y + f0.y + bo[4*q+1];
            r.z = xv.z + f1.x + bo[4*q+2];
            r.w = xv.w + f1.y + bo[4*q+3];
            op[q] = r;
        }
    }
}

// ---------------- launch ----------------
extern "C" void kernel_launch(void* const* d_in, const int* in_sizes, int n_in,
                              void* d_out, int out_size) {
    const float* x   = (const float*)d_in[0];
    const float* rot = (const float*)d_in[1];
    const float* n1g = (const float*)d_in[2];
    const float* n1b = (const float*)d_in[3];
    const float* qw  = (const float*)d_in[4];
    const float* kvw = (const float*)d_in[5];
    const float* n2g = (const float*)d_in[6];
    const float* n2b = (const float*)d_in[7];
    const float* w1  = (const float*)d_in[8];
    const float* b1  = (const float*)d_in[9];
    const float* w2  = (const float*)d_in[10];
    const float* b2  = (const float*)d_in[11];
    float* out = (float*)d_out;

    const int POOL_SM = (4*32*256 + 128)*4;                 // 131584
    const int QSM     = (64*260 + 8*1156 + 32)*4;           // 103680
    const int MSM     = (2*64*260)*4;                       // 133120
    cudaFuncSetAttribute(k_pool,  cudaFuncAttributeMaxDynamicSharedMemorySize, POOL_SM);
    cudaFuncSetAttribute(k_qattn, cudaFuncAttributeMaxDynamicSharedMemorySize, QSM);
    cudaFuncSetAttribute(k_mlp,   cudaFuncAttributeMaxDynamicSharedMemorySize, MSM);

    k_ln1<<<(NB*NN)/128, 256>>>(x, rot, n1g, n1b);
    k_pool<<<dim3(NCH, NB), 128, POOL_SM>>>();
    k_kv<<<dim3(4, NB), 256>>>(kvw);
    k_prep<<<dim3(NB, 8), 256>>>(qw);
    k_qattn<<<(NB*NN)/64, 256, QSM>>>(x);
    k_mlp<<<(NB*NN)/64, 256, MSM>>>(n2g, n2b, w1, b1, w2, b2, out);
}

// round 5
// speedup vs baseline: 4.1141x; 4.1084x over previous
#include <cuda_runtime.h>
#include <cuda_bf16.h>
#include <math.h>
#include <stdint.h>

#define NB 16
#define NN 8192
#define NC 256
#define NM 32
#define NCH 16
#define TOKCH (NN/NCH)

__device__ float g_xln[NB*NN*NC];
__device__ __nv_bfloat16 g_xh[NB*NN*NC], g_xl[NB*NN*NC];
__device__ unsigned int g_bkt[NB*NN];
__device__ float g_poolp[NCH*NB*NM*NC];
__device__ float g_cntp [NCH*NB*NM];
__device__ float g_k[NB*NM*NC];
__device__ float g_v[NB*NM*NC];
__device__ __nv_bfloat16 g_Abh[NB*NC*NC], g_Abl[NB*NC*NC];
__device__ float g_L [NB*NN*NC];
__device__ float g_x2[NB*NN*NC];
__device__ __nv_bfloat16 g_yh[NB*NN*NC], g_yl[NB*NN*NC];
__device__ __nv_bfloat16 g_hh[(size_t)NB*NN*1024], g_hl[(size_t)NB*NN*1024];
__device__ __nv_bfloat16 g_w1h[1024*256], g_w1l[1024*256];
__device__ __nv_bfloat16 g_w2h[256*1024], g_w2l[256*1024];

__device__ __forceinline__ uint32_t s2u(const void* p){
    uint32_t a; asm("{ .reg .u64 t; cvta.to.shared.u64 t, %1; cvt.u32.u64 %0, t; }" : "=r"(a) : "l"(p)); return a;
}
#define CPA(dst, src) asm volatile("cp.async.cg.shared.global [%0], [%1], 16;" :: "r"(dst), "l"(src))
#define CPCOMMIT()    asm volatile("cp.async.commit_group;" ::: "memory")
#define CPWAIT1()     asm volatile("cp.async.wait_group 1;" ::: "memory")
#define CPWAIT0()     asm volatile("cp.async.wait_group 0;" ::: "memory")
#define LDSM4(r, a) asm volatile("ldmatrix.sync.aligned.m8n8.x4.shared.b16 {%0,%1,%2,%3}, [%4];" \
    : "=r"((r)[0]), "=r"((r)[1]), "=r"((r)[2]), "=r"((r)[3]) : "r"(a))
#define MMA(d, a, b) asm volatile( \
    "mma.sync.aligned.m16n8k16.row.col.f32.bf16.bf16.f32 " \
    "{%0,%1,%2,%3}, {%4,%5,%6,%7}, {%8,%9}, {%0,%1,%2,%3};" \
    : "+f"((d)[0]), "+f"((d)[1]), "+f"((d)[2]), "+f"((d)[3]) \
    : "r"((a)[0]), "r"((a)[1]), "r"((a)[2]), "r"((a)[3]), "r"((b)[0]), "r"((b)[1]))

__device__ __forceinline__ void spl(float x, __nv_bfloat16&h, __nv_bfloat16&l){
    h = __float2bfloat16(x); l = __float2bfloat16(x - __bfloat162float(h));
}
__device__ __forceinline__ uint32_t pks(float f0, float f1, uint32_t& lo){
    __nv_bfloat16 h0,l0,h1,l1; spl(f0,h0,l0); spl(f1,h1,l1);
    lo = (uint32_t)__bfloat16_as_ushort(l0) | ((uint32_t)__bfloat16_as_ushort(l1)<<16);
    return (uint32_t)__bfloat16_as_ushort(h0) | ((uint32_t)__bfloat16_as_ushort(h1)<<16);
}
__device__ __forceinline__ float geluf(float u){ return 0.5f*u*(1.f + erff(u*0.70710678118654752f)); }
__device__ __forceinline__ float wsum(float v){
    #pragma unroll
    for (int o=16;o;o>>=1) v += __shfl_xor_sync(~0u,v,o);
    return v;
}

// ---- weight transpose + split ----
__global__ void k_prepw(const float* __restrict__ w1, const float* __restrict__ w2){
    int n = blockIdx.x, t = threadIdx.x;
    if (n < 1024){
        float v = w1[(size_t)t*1024 + n];
        spl(v, g_w1h[n*256+t], g_w1l[n*256+t]);
    } else {
        int n2 = n-1024;
        for (int k = t; k < 1024; k += 256){
            float v = w2[(size_t)k*256 + n2];
            spl(v, g_w2h[n2*1024+k], g_w2l[n2*1024+k]);
        }
    }
}

// ---- LN1 + LSH + split ----
__global__ __launch_bounds__(256) void k_ln1(const float* __restrict__ x, const float* __restrict__ rot,
                                             const float* __restrict__ g1, const float* __restrict__ b1){
    __shared__ float rT[16*256], sg[256], sb[256];
    int tid = threadIdx.x;
    for (int i = tid; i < 4096; i += 256) rT[(i&15)*256 + (i>>4)] = rot[i];
    sg[tid] = g1[tid]; sb[tid] = b1[tid];
    __syncthreads();
    int w = tid>>5, lane = tid&31;
    int base = blockIdx.x*128 + w*16;
    for (int t0 = 0; t0 < 16; t0++){
        int row = base + t0;
        const float* xr = x + (size_t)row*NC;
        float xv[8], s = 0.f, sq = 0.f;
        #pragma unroll
        for (int j = 0; j < 8; j++){ float v = xr[lane+32*j]; xv[j] = v; s += v; sq += v*v; }
        s = wsum(s); sq = wsum(sq);
        float m = s*(1.f/256.f);
        float rs = rsqrtf(sq*(1.f/256.f) - m*m + 1e-5f);
        float r16[16];
        #pragma unroll
        for (int i = 0; i < 16; i++) r16[i] = 0.f;
        float* xo = g_xln + (size_t)row*NC;
        #pragma unroll
        for (int j = 0; j < 8; j++){
            int c = lane + 32*j;
            float xn = (xv[j]-m)*rs*sg[c] + sb[c];
            xo[c] = xn;
            size_t o = (size_t)row*NC + c;
            spl(xn, g_xh[o], g_xl[o]);
            #pragma unroll
            for (int i = 0; i < 16; i++) r16[i] += xn * rT[i*256 + c];
        }
        #pragma unroll
        for (int i = 0; i < 16; i++){
            #pragma unroll
            for (int o = 16; o; o >>= 1) r16[i] += __shfl_xor_sync(~0u, r16[i], o);
        }
        if (!lane){
            unsigned pkb = 0;
            #pragma unroll
            for (int h = 0; h < 4; h++){
                float best = r16[h*4]; int bi = 0;
                #pragma unroll
                for (int i = 1; i < 8; i++){
                    float v = (i < 4) ? r16[h*4+i] : -r16[h*4+i-4];
                    if (v > best){ best = v; bi = i; }
                }
                pkb |= (unsigned)bi << (8*h);
            }
            g_bkt[row] = pkb;
        }
    }
}

// ---- pooling ----
__global__ __launch_bounds__(128) void k_pool(){
    extern __shared__ float sp[];
    float* scnt = sp + 4*32*256;
    int tid = threadIdx.x, w = tid>>5, lane = tid&31;
    int ch = blockIdx.x, b = blockIdx.y;
    for (int i = tid; i < 4*32*256; i += 128) sp[i] = 0.f;
    if (tid < 128) scnt[tid] = 0.f;
    __syncthreads();
    float* myp = sp + w*32*256;
    float* myc = scnt + w*32;
    int n0 = ch*TOKCH + w*(TOKCH/4);
    for (int it = 0; it < TOKCH/4; it++){
        int row = b*NN + n0 + it;
        unsigned pkb = g_bkt[row];
        const float* xr = g_xln + (size_t)row*NC;
        float xv[8];
        #pragma unroll
        for (int j = 0; j < 8; j++) xv[j] = xr[lane+32*j];
        #pragma unroll
        for (int h = 0; h < 4; h++){
            int hm = h*8 + ((pkb >> (8*h)) & 255);
            float* dst = myp + hm*256;
            #pragma unroll
            for (int j = 0; j < 8; j++) dst[lane+32*j] += xv[j];
            if (!lane) myc[hm] += 1.f;
        }
    }
    __syncthreads();
    float* op = g_poolp + (size_t)(ch*NB + b)*NM*NC;
    for (int i = tid; i < NM*NC; i += 128)
        op[i] = sp[i] + sp[8192+i] + sp[16384+i] + sp[24576+i];
    if (tid < NM)
        g_cntp[(ch*NB+b)*NM + tid] = scnt[tid] + scnt[32+tid] + scnt[64+tid] + scnt[96+tid];
}

// ---- pooled KV projection ----
__global__ __launch_bounds__(256) void k_kv(const float* __restrict__ kvw){
    __shared__ float rp[8*256];
    __shared__ float scn[8];
    int tid = threadIdx.x;
    int mg = blockIdx.x, b = blockIdx.y;
    if (tid < 8){
        float c = 0.f;
        for (int ch = 0; ch < NCH; ch++) c += g_cntp[(ch*NB+b)*NM + mg*8 + tid];
        scn[tid] = c;
    }
    __syncthreads();
    for (int i = tid; i < 8*256; i += 256){
        int mi = i>>8;
        float s = 0.f;
        for (int ch = 0; ch < NCH; ch++)
            s += g_poolp[((size_t)(ch*NB+b)*NM + mg*8 + mi)*NC + (i&255)];
        rp[i] = s / (scn[mi] + 1e-20f);
    }
    __syncthreads();
    int j = tid;
    float aK[8], aV[8];
    #pragma unroll
    for (int i = 0; i < 8; i++){ aK[i] = 0.f; aV[i] = 0.f; }
    for (int c = 0; c < 256; c++){
        float w0 = kvw[(size_t)c*512 + j], w1 = kvw[(size_t)c*512 + 256 + j];
        #pragma unroll
        for (int i = 0; i < 8; i++){ float a = rp[i*256+c]; aK[i] = fmaf(a,w0,aK[i]); aV[i] = fmaf(a,w1,aV[i]); }
    }
    #pragma unroll
    for (int i = 0; i < 8; i++){
        int m = mg*8 + i;
        g_k[((size_t)b*NM+m)*NC + j] = aK[i];
        g_v[((size_t)b*NM+m)*NC + j] = aV[i];
    }
}

// ---- A^T = scale*(q_w@k^T)^T, split ----
__global__ __launch_bounds__(256) void k_prep(const float* __restrict__ qw){
    __shared__ float ks[32*32];
    int c = threadIdx.x, b = blockIdx.x, h = blockIdx.y;
    for (int i = c; i < 1024; i += 256)
        ks[i] = g_k[((size_t)b*NM + (i>>5))*NC + h*32 + (i&31)];
    __syncthreads();
    float q[32];
    const float* qp = qw + (size_t)c*NC + h*32;
    #pragma unroll
    for (int i = 0; i < 32; i++) q[i] = qp[i];
    for (int m = 0; m < 32; m++){
        float acc = 0.f;
        #pragma unroll
        for (int i = 0; i < 32; i++) acc = fmaf(q[i], ks[m*32+i], acc);
        size_t o = ((size_t)b*256 + h*32 + m)*256 + c;
        spl(acc*0.17677669529663689f, g_Abh[o], g_Abl[o]);
    }
}

// ---- HMMA split GEMM: D[128 x 128cols] = A[128xK] @ B[N x K]^T ----
template<int MODE, int KDIM>
__global__ __launch_bounds__(256,1) void k_gemm(const float* __restrict__ bias, float* __restrict__ outf){
    extern __shared__ char dsm[];
    uint32_t sb = s2u(dsm);
    int tid = threadIdx.x, w = tid>>5, lane = tid&31;
    size_t row0 = (size_t)blockIdx.y*128;
    int n0 = blockIdx.x*128;
    const __nv_bfloat16 *Ah, *Al, *Bh, *Bl;
    if (MODE==0){ Ah=g_xh; Al=g_xl; size_t b=row0>>13; Bh=g_Abh+b*65536; Bl=g_Abl+b*65536; }
    else if (MODE==1){ Ah=g_yh; Al=g_yl; Bh=g_w1h; Bl=g_w1l; }
    else { Ah=g_hh; Al=g_hl; Bh=g_w2h; Bl=g_w2l; }

    constexpr int KT = KDIM/32;
    int wm = w&3, wn = w>>2;

    float acc[2][8][4];
    #pragma unroll
    for (int i = 0; i < 2; i++)
        #pragma unroll
        for (int j = 0; j < 8; j++)
            #pragma unroll
            for (int q = 0; q < 4; q++) acc[i][j][q] = 0.f;

    auto load_stage = [&](int kt, int s){
        uint32_t base = sb + s*32768;
        #pragma unroll
        for (int it = 0; it < 8; it++){
            int i = tid + it*256;
            int r = (i>>3)&127, c = i&7;
            const __nv_bfloat16* src;
            uint32_t dst;
            if (i < 1024){
                src = ((c<4)?Ah:Al) + (row0 + r)*KDIM + kt*32 + (c&3)*8;
                dst = base + r*128 + (((c) ^ (r&7))<<4);
            } else {
                src = ((c<4)?Bh:Bl) + (size_t)(n0 + r)*KDIM + kt*32 + (c&3)*8;
                dst = base + 16384 + r*128 + (((c) ^ (r&7))<<4);
            }
            CPA(dst, src);
        }
        CPCOMMIT();
    };

    load_stage(0, 0);
    for (int kt = 0; kt < KT; kt++){
        int s = kt & 1;
        if (kt+1 < KT){ load_stage(kt+1, s^1); CPWAIT1(); }
        else CPWAIT0();
        __syncthreads();
        uint32_t As = sb + s*32768;
        uint32_t Bs = As + 16384;
        #pragma unroll
        for (int kk = 0; kk < 2; kk++){
            uint32_t ah[2][4], al[2][4], bhv[4][4], blv[4][4];
            #pragma unroll
            for (int mt = 0; mt < 2; mt++){
                int r = wm*32 + mt*16 + (lane&15);
                int ch = kk*2 + ((lane>>4)&1);
                LDSM4(ah[mt], As + r*128 + (((ch  ) ^ (r&7))<<4));
                LDSM4(al[mt], As + r*128 + (((ch+4) ^ (r&7))<<4));
            }
            #pragma unroll
            for (int nt2 = 0; nt2 < 4; nt2++){
                int r = wn*64 + nt2*16 + (lane&7) + ((lane>>4)&1)*8;
                int ch = kk*2 + ((lane>>3)&1);
                LDSM4(bhv[nt2], Bs + r*128 + (((ch  ) ^ (r&7))<<4));
                LDSM4(blv[nt2], Bs + r*128 + (((ch+4) ^ (r&7))<<4));
            }
            #pragma unroll
            for (int mt = 0; mt < 2; mt++)
                #pragma unroll
                for (int nt = 0; nt < 8; nt++){
                    uint32_t* bph = &bhv[nt>>1][(nt&1)*2];
                    uint32_t* bpl = &blv[nt>>1][(nt&1)*2];
                    MMA(acc[mt][nt], ah[mt], bph);
                    MMA(acc[mt][nt], ah[mt], bpl);
                    MMA(acc[mt][nt], al[mt], bph);
                }
        }
        __syncthreads();
    }

    int g = lane>>2, t = lane&3;
    #pragma unroll
    for (int mt = 0; mt < 2; mt++){
        size_t R0 = row0 + wm*32 + mt*16 + g;
        #pragma unroll
        for (int nt = 0; nt < 8; nt++){
            int C = n0 + wn*64 + nt*8 + t*2;
            float* d = acc[mt][nt];
            if (MODE == 0){
                *(float2*)(g_L + R0*256 + C)     = make_float2(d[0], d[1]);
                *(float2*)(g_L + (R0+8)*256 + C) = make_float2(d[2], d[3]);
            } else if (MODE == 1){
                float b0v = __ldg(bias + C), b1v = __ldg(bias + C + 1);
                uint32_t lo0, lo1;
                uint32_t hi0 = pks(geluf(d[0]+b0v), geluf(d[1]+b1v), lo0);
                uint32_t hi1 = pks(geluf(d[2]+b0v), geluf(d[3]+b1v), lo1);
                *(uint32_t*)(g_hh + R0*1024 + C)     = hi0;
                *(uint32_t*)(g_hl + R0*1024 + C)     = lo0;
                *(uint32_t*)(g_hh + (R0+8)*1024 + C) = hi1;
                *(uint32_t*)(g_hl + (R0+8)*1024 + C) = lo1;
            } else {
                float b0v = __ldg(bias + C), b1v = __ldg(bias + C + 1);
                float2 x0 = *(float2*)(g_x2 + R0*256 + C);
                float2 x1 = *(float2*)(g_x2 + (R0+8)*256 + C);
                *(float2*)(outf + R0*256 + C)     = make_float2(d[0]+b0v+x0.x, d[1]+b1v+x0.y);
                *(float2*)(outf + (R0+8)*256 + C) = make_float2(d[2]+b0v+x1.x, d[3]+b1v+x1.y);
            }
        }
    }
}

// ---- softmax + PV + residual + LN2 + split ----
__global__ __launch_bounds__(256) void k_soft(const float* __restrict__ x,
                                              const float* __restrict__ g2, const float* __restrict__ b2){
    __shared__ float v_s[32*256];
    __shared__ float cnt_s[32];
    int tid = threadIdx.x, w = tid>>5, lane = tid&31;
    int row0 = blockIdx.x*128;
    int b = blockIdx.x >> 6;
    for (int i = tid; i < 8192; i += 256) v_s[i] = g_v[(size_t)b*8192 + i];
    if (tid < 32){
        float c = 0.f;
        for (int ch = 0; ch < NCH; ch++) c += g_cntp[(ch*NB+b)*NM + tid];
        cnt_s[tid] = c;
    }
    __syncthreads();
    float g2r[8], b2r[8];
    #pragma unroll
    for (int j = 0; j < 8; j++){ g2r[j] = g2[j*32+lane]; b2r[j] = b2[j*32+lane]; }
    bool valid = cnt_s[lane] >= 1.f;
    for (int t = 0; t < 16; t++){
        int row = row0 + w*16 + t;
        const float* Lr = g_L + (size_t)row*256;
        float out[8];
        #pragma unroll
        for (int j = 0; j < 8; j++){
            float l = Lr[j*32 + lane];
            float mxv = valid ? l : -3.0e38f;
            #pragma unroll
            for (int o = 16; o; o >>= 1) mxv = fmaxf(mxv, __shfl_xor_sync(~0u, mxv, o));
            float e = valid ? expf(l - mxv) : 0.f;
            float s = wsum(e);
            float p = e / s;
            float acc = 0.f;
            #pragma unroll
            for (int m = 0; m < 32; m++){
                float pm = __shfl_sync(~0u, p, m);
                acc = fmaf(pm, v_s[m*256 + j*32 + lane], acc);
            }
            out[j] = acc;
        }
        const float* xr = x + (size_t)row*256;
        float x2v[8], s = 0.f, sq = 0.f;
        #pragma unroll
        for (int j = 0; j < 8; j++){
            float v = xr[j*32+lane] + out[j];
            x2v[j] = v; s += v; sq += v*v;
        }
        s = wsum(s); sq = wsum(sq);
        float mu = s*(1.f/256.f);
        float rs = rsqrtf(sq*(1.f/256.f) - mu*mu + 1e-5f);
        #pragma unroll
        for (int j = 0; j < 8; j++){
            int c = j*32 + lane;
            size_t o = (size_t)row*256 + c;
            g_x2[o] = x2v[j];
            spl((x2v[j]-mu)*rs*g2r[j] + b2r[j], g_yh[o], g_yl[o]);
        }
    }
}

extern "C" void kernel_launch(void* const* d_in, const int* in_sizes, int n_in,
                              void* d_out, int out_size) {
    const float* x   = (const float*)d_in[0];
    const float* rot = (const float*)d_in[1];
    const float* n1g = (const float*)d_in[2];
    const float* n1b = (const float*)d_in[3];
    const float* qw  = (const float*)d_in[4];
    const float* kvw = (const float*)d_in[5];
    const float* n2g = (const float*)d_in[6];
    const float* n2b = (const float*)d_in[7];
    const float* w1  = (const float*)d_in[8];
    const float* b1  = (const float*)d_in[9];
    const float* w2  = (const float*)d_in[10];
    const float* b2  = (const float*)d_in[11];
    float* out = (float*)d_out;

    const int POOL_SM = (4*32*256 + 128)*4;
    const int GSM = 65536;
    cudaFuncSetAttribute(k_pool, cudaFuncAttributeMaxDynamicSharedMemorySize, POOL_SM);
    cudaFuncSetAttribute((const void*)k_gemm<0,256>,  cudaFuncAttributeMaxDynamicSharedMemorySize, GSM);
    cudaFuncSetAttribute((const void*)k_gemm<1,256>,  cudaFuncAttributeMaxDynamicSharedMemorySize, GSM);
    cudaFuncSetAttribute((const void*)k_gemm<2,1024>, cudaFuncAttributeMaxDynamicSharedMemorySize, GSM);

    k_prepw<<<1280, 256>>>(w1, w2);
    k_ln1<<<(NB*NN)/128, 256>>>(x, rot, n1g, n1b);
    k_pool<<<dim3(NCH, NB), 128, POOL_SM>>>();
    k_kv<<<dim3(4, NB), 256>>>(kvw);
    k_prep<<<dim3(NB, 8), 256>>>(qw);
    k_gemm<0,256><<<dim3(2, (NB*NN)/128), 256, GSM>>>(nullptr, nullptr);
    k_soft<<<(NB*NN)/128, 256>>>(x, n2g, n2b);
    k_gemm<1,256><<<dim3(8, (NB*NN)/128), 256, GSM>>>(b1, nullptr);
    k_gemm<2,1024><<<dim3(2, (NB*NN)/128), 256, GSM>>>(b2, out);
}

// round 6
// speedup vs baseline: 4.1256x; 1.0028x over previous
#include <cuda_runtime.h>
#include <cuda_bf16.h>
#include <math.h>
#include <stdint.h>

#define NB 16
#define NN 8192
#define NC 256
#define NM 32
#define NCH 16
#define TOKCH (NN/NCH)

__device__ __nv_bfloat16 g_xh[NB*NN*NC], g_xl[NB*NN*NC];
__device__ unsigned int g_bkt[NB*NN];
__device__ float g_poolp[NCH*NB*NM*NC];
__device__ float g_cntp [NCH*NB*NM];
__device__ float g_k[NB*NM*NC];
__device__ float g_v[NB*NM*NC];
__device__ __nv_bfloat16 g_Abh[NB*NC*NC], g_Abl[NB*NC*NC];
__device__ float g_x2[NB*NN*NC];
__device__ __nv_bfloat16 g_yh[NB*NN*NC], g_yl[NB*NN*NC];
__device__ __nv_bfloat16 g_hh[(size_t)NB*NN*1024], g_hl[(size_t)NB*NN*1024];
__device__ __nv_bfloat16 g_w1h[1024*256], g_w1l[1024*256];
__device__ __nv_bfloat16 g_w2h[256*1024], g_w2l[256*1024];

__device__ __forceinline__ uint32_t s2u(const void* p){
    uint32_t a; asm("{ .reg .u64 t; cvta.to.shared.u64 t, %1; cvt.u32.u64 %0, t; }" : "=r"(a) : "l"(p)); return a;
}
#define CPA(dst, src) asm volatile("cp.async.cg.shared.global [%0], [%1], 16;" :: "r"(dst), "l"(src))
#define CPCOMMIT()    asm volatile("cp.async.commit_group;" ::: "memory")
#define CPWAIT1()     asm volatile("cp.async.wait_group 1;" ::: "memory")
#define CPWAIT0()     asm volatile("cp.async.wait_group 0;" ::: "memory")
#define LDSM4(r, a) asm volatile("ldmatrix.sync.aligned.m8n8.x4.shared.b16 {%0,%1,%2,%3}, [%4];" \
    : "=r"((r)[0]), "=r"((r)[1]), "=r"((r)[2]), "=r"((r)[3]) : "r"(a))
#define MMA(d, a, b) asm volatile( \
    "mma.sync.aligned.m16n8k16.row.col.f32.bf16.bf16.f32 " \
    "{%0,%1,%2,%3}, {%4,%5,%6,%7}, {%8,%9}, {%0,%1,%2,%3};" \
    : "+f"((d)[0]), "+f"((d)[1]), "+f"((d)[2]), "+f"((d)[3]) \
    : "r"((a)[0]), "r"((a)[1]), "r"((a)[2]), "r"((a)[3]), "r"((b)[0]), "r"((b)[1]))

__device__ __forceinline__ void spl(float x, __nv_bfloat16&h, __nv_bfloat16&l){
    h = __float2bfloat16(x); l = __float2bfloat16(x - __bfloat162float(h));
}
__device__ __forceinline__ uint32_t pks(float f0, float f1, uint32_t& lo){
    __nv_bfloat16 h0,l0,h1,l1; spl(f0,h0,l0); spl(f1,h1,l1);
    lo = (uint32_t)__bfloat16_as_ushort(l0) | ((uint32_t)__bfloat16_as_ushort(l1)<<16);
    return (uint32_t)__bfloat16_as_ushort(h0) | ((uint32_t)__bfloat16_as_ushort(h1)<<16);
}
__device__ __forceinline__ float geluf(float u){ return 0.5f*u*(1.f + erff(u*0.70710678118654752f)); }
__device__ __forceinline__ float wsum(float v){
    #pragma unroll
    for (int o=16;o;o>>=1) v += __shfl_xor_sync(~0u,v,o);
    return v;
}

// ---- weight transpose + split ----
__global__ void k_prepw(const float* __restrict__ w1, const float* __restrict__ w2){
    int n = blockIdx.x, t = threadIdx.x;
    if (n < 1024){
        float v = w1[(size_t)t*1024 + n];
        spl(v, g_w1h[n*256+t], g_w1l[n*256+t]);
    } else {
        int n2 = n-1024;
        for (int k = t; k < 1024; k += 256){
            float v = w2[(size_t)k*256 + n2];
            spl(v, g_w2h[n2*1024+k], g_w2l[n2*1024+k]);
        }
    }
}

// ---- LN1 + LSH + split ----
__global__ __launch_bounds__(256) void k_ln1(const float* __restrict__ x, const float* __restrict__ rot,
                                             const float* __restrict__ g1, const float* __restrict__ b1){
    __shared__ float rT[16*256], sg[256], sb[256];
    int tid = threadIdx.x;
    for (int i = tid; i < 4096; i += 256) rT[(i&15)*256 + (i>>4)] = rot[i];
    sg[tid] = g1[tid]; sb[tid] = b1[tid];
    __syncthreads();
    int w = tid>>5, lane = tid&31;
    int base = blockIdx.x*128 + w*16;
    for (int t0 = 0; t0 < 16; t0++){
        int row = base + t0;
        const float* xr = x + (size_t)row*NC;
        float xv[8], s = 0.f, sq = 0.f;
        #pragma unroll
        for (int j = 0; j < 8; j++){ float v = xr[lane+32*j]; xv[j] = v; s += v; sq += v*v; }
        s = wsum(s); sq = wsum(sq);
        float m = s*(1.f/256.f);
        float rs = rsqrtf(sq*(1.f/256.f) - m*m + 1e-5f);
        float r16[16];
        #pragma unroll
        for (int i = 0; i < 16; i++) r16[i] = 0.f;
        #pragma unroll
        for (int j = 0; j < 8; j++){
            int c = lane + 32*j;
            float xn = (xv[j]-m)*rs*sg[c] + sb[c];
            size_t o = (size_t)row*NC + c;
            spl(xn, g_xh[o], g_xl[o]);
            #pragma unroll
            for (int i = 0; i < 16; i++) r16[i] += xn * rT[i*256 + c];
        }
        #pragma unroll
        for (int i = 0; i < 16; i++){
            #pragma unroll
            for (int o = 16; o; o >>= 1) r16[i] += __shfl_xor_sync(~0u, r16[i], o);
        }
        if (!lane){
            unsigned pkb = 0;
            #pragma unroll
            for (int h = 0; h < 4; h++){
                float best = r16[h*4]; int bi = 0;
                #pragma unroll
                for (int i = 1; i < 8; i++){
                    float v = (i < 4) ? r16[h*4+i] : -r16[h*4+i-4];
                    if (v > best){ best = v; bi = i; }
                }
                pkb |= (unsigned)bi << (8*h);
            }
            g_bkt[row] = pkb;
        }
    }
}

// ---- pooling (reads split x) ----
__global__ __launch_bounds__(128) void k_pool(){
    extern __shared__ float sp[];
    float* scnt = sp + 4*32*256;
    int tid = threadIdx.x, w = tid>>5, lane = tid&31;
    int ch = blockIdx.x, b = blockIdx.y;
    for (int i = tid; i < 4*32*256; i += 128) sp[i] = 0.f;
    if (tid < 128) scnt[tid] = 0.f;
    __syncthreads();
    float* myp = sp + w*32*256;
    float* myc = scnt + w*32;
    int n0 = ch*TOKCH + w*(TOKCH/4);
    for (int it = 0; it < TOKCH/4; it++){
        int row = b*NN + n0 + it;
        unsigned pkb = g_bkt[row];
        const __nv_bfloat16* xhp = g_xh + (size_t)row*NC;
        const __nv_bfloat16* xlp = g_xl + (size_t)row*NC;
        float xv[8];
        #pragma unroll
        for (int j = 0; j < 8; j++){
            int c = lane+32*j;
            xv[j] = __bfloat162float(xhp[c]) + __bfloat162float(xlp[c]);
        }
        #pragma unroll
        for (int h = 0; h < 4; h++){
            int hm = h*8 + ((pkb >> (8*h)) & 255);
            float* dst = myp + hm*256;
            #pragma unroll
            for (int j = 0; j < 8; j++) dst[lane+32*j] += xv[j];
            if (!lane) myc[hm] += 1.f;
        }
    }
    __syncthreads();
    float* op = g_poolp + (size_t)(ch*NB + b)*NM*NC;
    for (int i = tid; i < NM*NC; i += 128)
        op[i] = sp[i] + sp[8192+i] + sp[16384+i] + sp[24576+i];
    if (tid < NM)
        g_cntp[(ch*NB+b)*NM + tid] = scnt[tid] + scnt[32+tid] + scnt[64+tid] + scnt[96+tid];
}

// ---- pooled KV projection (512 threads, one output col each) ----
__global__ __launch_bounds__(512) void k_kv(const float* __restrict__ kvw){
    __shared__ float rp[8*256];
    __shared__ float scn[8];
    int tid = threadIdx.x;
    int mg = blockIdx.x, b = blockIdx.y;
    if (tid < 8){
        float c = 0.f;
        for (int ch = 0; ch < NCH; ch++) c += g_cntp[(ch*NB+b)*NM + mg*8 + tid];
        scn[tid] = c;
    }
    __syncthreads();
    for (int i = tid; i < 8*256; i += 512){
        int mi = i>>8;
        float s = 0.f;
        #pragma unroll 4
        for (int ch = 0; ch < NCH; ch++)
            s += g_poolp[((size_t)(ch*NB+b)*NM + mg*8 + mi)*NC + (i&255)];
        rp[i] = s / (scn[mi] + 1e-20f);
    }
    __syncthreads();
    int j = tid;
    float a8[8];
    #pragma unroll
    for (int i = 0; i < 8; i++) a8[i] = 0.f;
    #pragma unroll 4
    for (int c = 0; c < 256; c++){
        float wv = __ldg(kvw + (size_t)c*512 + j);
        #pragma unroll
        for (int i = 0; i < 8; i++) a8[i] = fmaf(rp[i*256+c], wv, a8[i]);
    }
    float* dst = (j < 256) ? g_k : g_v;
    int jj = j & 255;
    #pragma unroll
    for (int i = 0; i < 8; i++)
        dst[((size_t)b*NM + mg*8 + i)*NC + jj] = a8[i];
}

// ---- A^T = scale*(q_w@k^T)^T, split ----
__global__ __launch_bounds__(256) void k_prep(const float* __restrict__ qw){
    __shared__ float ks[32*32];
    int c = threadIdx.x, b = blockIdx.x, h = blockIdx.y;
    for (int i = c; i < 1024; i += 256)
        ks[i] = g_k[((size_t)b*NM + (i>>5))*NC + h*32 + (i&31)];
    __syncthreads();
    float q[32];
    const float* qp = qw + (size_t)c*NC + h*32;
    #pragma unroll
    for (int i = 0; i < 32; i++) q[i] = qp[i];
    for (int m = 0; m < 32; m++){
        float acc = 0.f;
        #pragma unroll
        for (int i = 0; i < 32; i++) acc = fmaf(q[i], ks[m*32+i], acc);
        size_t o = ((size_t)b*256 + h*32 + m)*256 + c;
        spl(acc*0.17677669529663689f, g_Abh[o], g_Abl[o]);
    }
}

// ---- fused: logits HMMA GEMM + softmax + PV + residual + LN2 + split ----
// smem: [0,133120) logits 128x260 f32 (phase2) / GEMM stages 2x48KB (phase1)
//       [133120,165888) v_s 32x256 f32; [165888,166016) cnt
__global__ __launch_bounds__(256,1) void k_attn(const float* __restrict__ x,
                                                const float* __restrict__ g2, const float* __restrict__ b2){
    extern __shared__ char dsm[];
    uint32_t sb = s2u(dsm);
    float* Ls   = (float*)dsm;
    float* v_s  = (float*)(dsm + 133120);
    float* cnt_s= (float*)(dsm + 165888);
    int tid = threadIdx.x, w = tid>>5, lane = tid&31;
    size_t row0 = (size_t)blockIdx.x*128;
    int b = blockIdx.x >> 6;
    const __nv_bfloat16 *Bh = g_Abh + (size_t)b*65536, *Bl = g_Abl + (size_t)b*65536;

    for (int i = tid; i < 8192; i += 256) v_s[i] = g_v[(size_t)b*8192 + i];
    if (tid < 32){
        float c = 0.f;
        for (int ch = 0; ch < NCH; ch++) c += g_cntp[(ch*NB+b)*NM + tid];
        cnt_s[tid] = c;
    }

    int wm = w&3, wn = w>>2;  // warp tile 32(m) x 128(n)
    float acc[2][16][4];
    #pragma unroll
    for (int i = 0; i < 2; i++)
        #pragma unroll
        for (int j = 0; j < 16; j++)
            #pragma unroll
            for (int q = 0; q < 4; q++) acc[i][j][q] = 0.f;

    auto load_stage = [&](int kt, int s){
        uint32_t base = sb + s*49152;
        #pragma unroll
        for (int it = 0; it < 12; it++){
            int i = tid + it*256;
            const __nv_bfloat16* src; uint32_t dst;
            if (i < 1024){
                int r = i>>3, c = i&7;
                src = ((c<4)?g_xh:g_xl) + (row0 + r)*NC + kt*32 + (c&3)*8;
                dst = base + r*128 + ((c ^ (r&7))<<4);
            } else {
                int jx = i - 1024;
                int r = jx>>3, c = jx&7;
                src = ((c<4)?Bh:Bl) + (size_t)r*NC + kt*32 + (c&3)*8;
                dst = base + 16384 + r*128 + ((c ^ (r&7))<<4);
            }
            CPA(dst, src);
        }
        CPCOMMIT();
    };

    load_stage(0, 0);
    for (int kt = 0; kt < 8; kt++){
        int s = kt & 1;
        if (kt+1 < 8){ load_stage(kt+1, s^1); CPWAIT1(); }
        else CPWAIT0();
        __syncthreads();
        uint32_t As = sb + s*49152;
        uint32_t Bs = As + 16384;
        #pragma unroll
        for (int kk = 0; kk < 2; kk++){
            uint32_t ah[2][4], al[2][4];
            #pragma unroll
            for (int mt = 0; mt < 2; mt++){
                int r = wm*32 + mt*16 + (lane&15);
                int ch = kk*2 + ((lane>>4)&1);
                LDSM4(ah[mt], As + r*128 + (((ch  ) ^ (r&7))<<4));
                LDSM4(al[mt], As + r*128 + (((ch+4) ^ (r&7))<<4));
            }
            #pragma unroll
            for (int nt2 = 0; nt2 < 8; nt2++){
                uint32_t bh[4], bl[4];
                int r = wn*128 + nt2*16 + (lane&7) + ((lane>>4)&1)*8;
                int ch = kk*2 + ((lane>>3)&1);
                LDSM4(bh, Bs + r*128 + (((ch  ) ^ (r&7))<<4));
                LDSM4(bl, Bs + r*128 + (((ch+4) ^ (r&7))<<4));
                #pragma unroll
                for (int mt = 0; mt < 2; mt++)
                    #pragma unroll
                    for (int hf = 0; hf < 2; hf++){
                        float* d = acc[mt][nt2*2+hf];
                        MMA(d, ah[mt], &bh[hf*2]);
                        MMA(d, ah[mt], &bl[hf*2]);
                        MMA(d, al[mt], &bh[hf*2]);
                    }
            }
        }
        __syncthreads();
    }

    // dump acc -> Ls
    int g = lane>>2, t4 = lane&3;
    #pragma unroll
    for (int mt = 0; mt < 2; mt++){
        int R = wm*32 + mt*16 + g;
        #pragma unroll
        for (int nt = 0; nt < 16; nt++){
            int C = wn*128 + nt*8 + t4*2;
            float* d = acc[mt][nt];
            *(float2*)(Ls + R*260 + C)     = make_float2(d[0], d[1]);
            *(float2*)(Ls + (R+8)*260 + C) = make_float2(d[2], d[3]);
        }
    }
    __syncthreads();

    // phase 2: per-head softmax + PV + residual + LN2
    float g2r[8], b2r[8];
    #pragma unroll
    for (int j = 0; j < 8; j++){ g2r[j] = g2[j*32+lane]; b2r[j] = b2[j*32+lane]; }
    bool valid = cnt_s[lane] >= 1.f;
    for (int t = 0; t < 16; t++){
        int rloc = w*16 + t;
        size_t row = row0 + rloc;
        float out[8];
        #pragma unroll
        for (int j = 0; j < 8; j++){
            float l = Ls[rloc*260 + j*32 + lane];
            float mxv = valid ? l : -3.0e38f;
            #pragma unroll
            for (int o = 16; o; o >>= 1) mxv = fmaxf(mxv, __shfl_xor_sync(~0u, mxv, o));
            float e = valid ? expf(l - mxv) : 0.f;
            float s = wsum(e);
            float p = e / s;
            float accv = 0.f;
            #pragma unroll
            for (int m = 0; m < 32; m++){
                float pm = __shfl_sync(~0u, p, m);
                accv = fmaf(pm, v_s[m*256 + j*32 + lane], accv);
            }
            out[j] = accv;
        }
        const float* xr = x + row*256;
        float x2v[8], s = 0.f, sq = 0.f;
        #pragma unroll
        for (int j = 0; j < 8; j++){
            float v = xr[j*32+lane] + out[j];
            x2v[j] = v; s += v; sq += v*v;
        }
        s = wsum(s); sq = wsum(sq);
        float mu = s*(1.f/256.f);
        float rs = rsqrtf(sq*(1.f/256.f) - mu*mu + 1e-5f);
        #pragma unroll
        for (int j = 0; j < 8; j++){
            int c = j*32 + lane;
            size_t o = row*256 + c;
            g_x2[o] = x2v[j];
            spl((x2v[j]-mu)*rs*g2r[j] + b2r[j], g_yh[o], g_yl[o]);
        }
    }
}

// ---- HMMA split GEMM (MLP1 / MLP2) ----
template<int MODE, int KDIM>
__global__ __launch_bounds__(256,1) void k_gemm(const float* __restrict__ bias, float* __restrict__ outf){
    extern __shared__ char dsm[];
    uint32_t sb = s2u(dsm);
    int tid = threadIdx.x, w = tid>>5, lane = tid&31;
    size_t row0 = (size_t)blockIdx.y*128;
    int n0 = blockIdx.x*128;
    const __nv_bfloat16 *Ah, *Al, *Bh, *Bl;
    if (MODE==1){ Ah=g_yh; Al=g_yl; Bh=g_w1h; Bl=g_w1l; }
    else { Ah=g_hh; Al=g_hl; Bh=g_w2h; Bl=g_w2l; }

    constexpr int KT = KDIM/32;
    int wm = w&3, wn = w>>2;

    float acc[2][8][4];
    #pragma unroll
    for (int i = 0; i < 2; i++)
        #pragma unroll
        for (int j = 0; j < 8; j++)
            #pragma unroll
            for (int q = 0; q < 4; q++) acc[i][j][q] = 0.f;

    auto load_stage = [&](int kt, int s){
        uint32_t base = sb + s*32768;
        #pragma unroll
        for (int it = 0; it < 8; it++){
            int i = tid + it*256;
            int r = (i>>3)&127, c = i&7;
            const __nv_bfloat16* src;
            uint32_t dst;
            if (i < 1024){
                src = ((c<4)?Ah:Al) + (row0 + r)*KDIM + kt*32 + (c&3)*8;
                dst = base + r*128 + ((c ^ (r&7))<<4);
            } else {
                src = ((c<4)?Bh:Bl) + (size_t)(n0 + r)*KDIM + kt*32 + (c&3)*8;
                dst = base + 16384 + r*128 + ((c ^ (r&7))<<4);
            }
            CPA(dst, src);
        }
        CPCOMMIT();
    };

    load_stage(0, 0);
    for (int kt = 0; kt < KT; kt++){
        int s = kt & 1;
        if (kt+1 < KT){ load_stage(kt+1, s^1); CPWAIT1(); }
        else CPWAIT0();
        __syncthreads();
        uint32_t As = sb + s*32768;
        uint32_t Bs = As + 16384;
        #pragma unroll
        for (int kk = 0; kk < 2; kk++){
            uint32_t ah[2][4], al[2][4], bhv[4][4], blv[4][4];
            #pragma unroll
            for (int mt = 0; mt < 2; mt++){
                int r = wm*32 + mt*16 + (lane&15);
                int ch = kk*2 + ((lane>>4)&1);
                LDSM4(ah[mt], As + r*128 + (((ch  ) ^ (r&7))<<4));
                LDSM4(al[mt], As + r*128 + (((ch+4) ^ (r&7))<<4));
            }
            #pragma unroll
            for (int nt2 = 0; nt2 < 4; nt2++){
                int r = wn*64 + nt2*16 + (lane&7) + ((lane>>4)&1)*8;
                int ch = kk*2 + ((lane>>3)&1);
                LDSM4(bhv[nt2], Bs + r*128 + (((ch  ) ^ (r&7))<<4));
                LDSM4(blv[nt2], Bs + r*128 + (((ch+4) ^ (r&7))<<4));
            }
            #pragma unroll
            for (int mt = 0; mt < 2; mt++)
                #pragma unroll
                for (int nt = 0; nt < 8; nt++){
                    uint32_t* bph = &bhv[nt>>1][(nt&1)*2];
                    uint32_t* bpl = &blv[nt>>1][(nt&1)*2];
                    MMA(acc[mt][nt], ah[mt], bph);
                    MMA(acc[mt][nt], ah[mt], bpl);
                    MMA(acc[mt][nt], al[mt], bph);
                }
        }
        __syncthreads();
    }

    int g = lane>>2, t = lane&3;
    #pragma unroll
    for (int mt = 0; mt < 2; mt++){
        size_t R0 = row0 + wm*32 + mt*16 + g;
        #pragma unroll
        for (int nt = 0; nt < 8; nt++){
            int C = n0 + wn*64 + nt*8 + t*2;
            float* d = acc[mt][nt];
            if (MODE == 1){
                float b0v = __ldg(bias + C), b1v = __ldg(bias + C + 1);
                uint32_t lo0, lo1;
                uint32_t hi0 = pks(geluf(d[0]+b0v), geluf(d[1]+b1v), lo0);
                uint32_t hi1 = pks(geluf(d[2]+b0v), geluf(d[3]+b1v), lo1);
                *(uint32_t*)(g_hh + R0*1024 + C)     = hi0;
                *(uint32_t*)(g_hl + R0*1024 + C)     = lo0;
                *(uint32_t*)(g_hh + (R0+8)*1024 + C) = hi1;
                *(uint32_t*)(g_hl + (R0+8)*1024 + C) = lo1;
            } else {
                float b0v = __ldg(bias + C), b1v = __ldg(bias + C + 1);
                float2 x0 = *(float2*)(g_x2 + R0*256 + C);
                float2 x1 = *(float2*)(g_x2 + (R0+8)*256 + C);
                *(float2*)(outf + R0*256 + C)     = make_float2(d[0]+b0v+x0.x, d[1]+b1v+x0.y);
                *(float2*)(outf + (R0+8)*256 + C) = make_float2(d[2]+b0v+x1.x, d[3]+b1v+x1.y);
            }
        }
    }
}

extern "C" void kernel_launch(void* const* d_in, const int* in_sizes, int n_in,
                              void* d_out, int out_size) {
    const float* x   = (const float*)d_in[0];
    const float* rot = (const float*)d_in[1];
    const float* n1g = (const float*)d_in[2];
    const float* n1b = (const float*)d_in[3];
    const float* qw  = (const float*)d_in[4];
    const float* kvw = (const float*)d_in[5];
    const float* n2g = (const float*)d_in[6];
    const float* n2b = (const float*)d_in[7];
    const float* w1  = (const float*)d_in[8];
    const float* b1  = (const float*)d_in[9];
    const float* w2  = (const float*)d_in[10];
    const float* b2  = (const float*)d_in[11];
    float* out = (float*)d_out;

    const int POOL_SM = (4*32*256 + 128)*4;
    const int GSM = 65536;
    const int ASM = 166016;
    cudaFuncSetAttribute(k_pool, cudaFuncAttributeMaxDynamicSharedMemorySize, POOL_SM);
    cudaFuncSetAttribute(k_attn, cudaFuncAttributeMaxDynamicSharedMemorySize, ASM);
    cudaFuncSetAttribute((const void*)k_gemm<1,256>,  cudaFuncAttributeMaxDynamicSharedMemorySize, GSM);
    cudaFuncSetAttribute((const void*)k_gemm<2,1024>, cudaFuncAttributeMaxDynamicSharedMemorySize, GSM);

    k_prepw<<<1280, 256>>>(w1, w2);
    k_ln1<<<(NB*NN)/128, 256>>>(x, rot, n1g, n1b);
    k_pool<<<dim3(NCH, NB), 128, POOL_SM>>>();
    k_kv<<<dim3(4, NB), 512>>>(kvw);
    k_prep<<<dim3(NB, 8), 256>>>(qw);
    k_attn<<<(NB*NN)/128, 256, ASM>>>(x, n2g, n2b);
    k_gemm<1,256><<<dim3(8, (NB*NN)/128), 256, GSM>>>(b1, nullptr);
    k_gemm<2,1024><<<dim3(2, (NB*NN)/128), 256, GSM>>>(b2, out);
}

// round 8
// speedup vs baseline: 5.1230x; 1.2418x over previous
#include <cuda_runtime.h>
#include <cuda_bf16.h>
#include <cuda_fp16.h>
#include <math.h>
#include <stdint.h>

#define NB 16
#define NN 8192
#define NC 256
#define NM 32
#define NCH 16
#define TOKCH (NN/NCH)

__device__ __nv_bfloat16 g_xh[NB*NN*NC], g_xl[NB*NN*NC];
__device__ unsigned int g_bkt[NB*NN];
__device__ float g_poolp[NCH*NB*NM*NC];
__device__ float g_cntp [NCH*NB*NM];
__device__ float g_k[NB*NM*NC];
__device__ float g_v[NB*NM*NC];
__device__ __nv_bfloat16 g_Abh[NB*NC*NC], g_Abl[NB*NC*NC];
__device__ float g_x2[NB*NN*NC];
__device__ __nv_bfloat16 g_yh[NB*NN*NC], g_yl[NB*NN*NC];
__device__ __half g_h[(size_t)NB*NN*1024];
__device__ __nv_bfloat16 g_w1h[1024*256], g_w1l[1024*256];
__device__ __half g_w2hh[256*1024];

__device__ __forceinline__ uint32_t s2u(const void* p){
    uint32_t a; asm("{ .reg .u64 t; cvta.to.shared.u64 t, %1; cvt.u32.u64 %0, t; }" : "=r"(a) : "l"(p)); return a;
}
#define CPA(dst, src) asm volatile("cp.async.cg.shared.global [%0], [%1], 16;" :: "r"(dst), "l"(src))
#define CPCOMMIT()    asm volatile("cp.async.commit_group;" ::: "memory")
#define CPWAIT1()     asm volatile("cp.async.wait_group 1;" ::: "memory")
#define CPWAIT0()     asm volatile("cp.async.wait_group 0;" ::: "memory")
#define LDSM4(r, a) asm volatile("ldmatrix.sync.aligned.m8n8.x4.shared.b16 {%0,%1,%2,%3}, [%4];" \
    : "=r"((r)[0]), "=r"((r)[1]), "=r"((r)[2]), "=r"((r)[3]) : "r"(a))
#define MMAB(d, a, b) asm volatile( \
    "mma.sync.aligned.m16n8k16.row.col.f32.bf16.bf16.f32 " \
    "{%0,%1,%2,%3}, {%4,%5,%6,%7}, {%8,%9}, {%0,%1,%2,%3};" \
    : "+f"((d)[0]), "+f"((d)[1]), "+f"((d)[2]), "+f"((d)[3]) \
    : "r"((a)[0]), "r"((a)[1]), "r"((a)[2]), "r"((a)[3]), "r"((b)[0]), "r"((b)[1]))
#define MMAH(d, a, b) asm volatile( \
    "mma.sync.aligned.m16n8k16.row.col.f32.f16.f16.f32 " \
    "{%0,%1,%2,%3}, {%4,%5,%6,%7}, {%8,%9}, {%0,%1,%2,%3};" \
    : "+f"((d)[0]), "+f"((d)[1]), "+f"((d)[2]), "+f"((d)[3]) \
    : "r"((a)[0]), "r"((a)[1]), "r"((a)[2]), "r"((a)[3]), "r"((b)[0]), "r"((b)[1]))

__device__ __forceinline__ void spl(float x, __nv_bfloat16&h, __nv_bfloat16&l){
    h = __float2bfloat16(x); l = __float2bfloat16(x - __bfloat162float(h));
}
__device__ __forceinline__ uint32_t pkh(float f0, float f1){
    __half2 h = __floats2half2_rn(f0, f1);
    return *(uint32_t*)&h;
}
__device__ __forceinline__ float geluf(float u){ return 0.5f*u*(1.f + erff(u*0.70710678118654752f)); }
__device__ __forceinline__ float wsum(float v){
    #pragma unroll
    for (int o=16;o;o>>=1) v += __shfl_xor_sync(~0u,v,o);
    return v;
}

// ---- weight transpose + split: w1 -> bf16 hi/lo, w2 -> fp16 ----
__global__ void k_prepw(const float* __restrict__ w1, const float* __restrict__ w2){
    int n = blockIdx.x, t = threadIdx.x;
    if (n < 1024){
        float v = w1[(size_t)t*1024 + n];
        spl(v, g_w1h[n*256+t], g_w1l[n*256+t]);
    } else {
        int n2 = n-1024;
        for (int k = t; k < 1024; k += 256){
            float v = w2[(size_t)k*256 + n2];
            g_w2hh[n2*1024+k] = __float2half(v);
        }
    }
}

// ---- LN1 + LSH + split ----
__global__ __launch_bounds__(256) void k_ln1(const float* __restrict__ x, const float* __restrict__ rot,
                                             const float* __restrict__ g1, const float* __restrict__ b1){
    __shared__ float rT[16*256], sg[256], sb[256];
    int tid = threadIdx.x;
    for (int i = tid; i < 4096; i += 256) rT[(i&15)*256 + (i>>4)] = rot[i];
    sg[tid] = g1[tid]; sb[tid] = b1[tid];
    __syncthreads();
    int w = tid>>5, lane = tid&31;
    int base = blockIdx.x*128 + w*16;
    for (int t0 = 0; t0 < 16; t0++){
        int row = base + t0;
        const float* xr = x + (size_t)row*NC;
        float xv[8], s = 0.f, sq = 0.f;
        #pragma unroll
        for (int j = 0; j < 8; j++){ float v = xr[lane+32*j]; xv[j] = v; s += v; sq += v*v; }
        s = wsum(s); sq = wsum(sq);
        float m = s*(1.f/256.f);
        float rs = rsqrtf(sq*(1.f/256.f) - m*m + 1e-5f);
        float r16[16];
        #pragma unroll
        for (int i = 0; i < 16; i++) r16[i] = 0.f;
        #pragma unroll
        for (int j = 0; j < 8; j++){
            int c = lane + 32*j;
            float xn = (xv[j]-m)*rs*sg[c] + sb[c];
            size_t o = (size_t)row*NC + c;
            spl(xn, g_xh[o], g_xl[o]);
            #pragma unroll
            for (int i = 0; i < 16; i++) r16[i] += xn * rT[i*256 + c];
        }
        #pragma unroll
        for (int i = 0; i < 16; i++){
            #pragma unroll
            for (int o = 16; o; o >>= 1) r16[i] += __shfl_xor_sync(~0u, r16[i], o);
        }
        if (!lane){
            unsigned pkb = 0;
            #pragma unroll
            for (int h = 0; h < 4; h++){
                float best = r16[h*4]; int bi = 0;
                #pragma unroll
                for (int i = 1; i < 8; i++){
                    float v = (i < 4) ? r16[h*4+i] : -r16[h*4+i-4];
                    if (v > best){ best = v; bi = i; }
                }
                pkb |= (unsigned)bi << (8*h);
            }
            g_bkt[row] = pkb;
        }
    }
}

// ---- pooling (reads split x) ----
__global__ __launch_bounds__(128) void k_pool(){
    extern __shared__ float sp[];
    float* scnt = sp + 4*32*256;
    int tid = threadIdx.x, w = tid>>5, lane = tid&31;
    int ch = blockIdx.x, b = blockIdx.y;
    for (int i = tid; i < 4*32*256; i += 128) sp[i] = 0.f;
    if (tid < 128) scnt[tid] = 0.f;
    __syncthreads();
    float* myp = sp + w*32*256;
    float* myc = scnt + w*32;
    int n0 = ch*TOKCH + w*(TOKCH/4);
    for (int it = 0; it < TOKCH/4; it++){
        int row = b*NN + n0 + it;
        unsigned pkb = g_bkt[row];
        const __nv_bfloat16* xhp = g_xh + (size_t)row*NC;
        const __nv_bfloat16* xlp = g_xl + (size_t)row*NC;
        float xv[8];
        #pragma unroll
        for (int j = 0; j < 8; j++){
            int c = lane+32*j;
            xv[j] = __bfloat162float(xhp[c]) + __bfloat162float(xlp[c]);
        }
        #pragma unroll
        for (int h = 0; h < 4; h++){
            int hm = h*8 + ((pkb >> (8*h)) & 255);
            float* dst = myp + hm*256;
            #pragma unroll
            for (int j = 0; j < 8; j++) dst[lane+32*j] += xv[j];
            if (!lane) myc[hm] += 1.f;
        }
    }
    __syncthreads();
    float* op = g_poolp + (size_t)(ch*NB + b)*NM*NC;
    for (int i = tid; i < NM*NC; i += 128)
        op[i] = sp[i] + sp[8192+i] + sp[16384+i] + sp[24576+i];
    if (tid < NM)
        g_cntp[(ch*NB+b)*NM + tid] = scnt[tid] + scnt[32+tid] + scnt[64+tid] + scnt[96+tid];
}

// ---- pooled KV projection ----
__global__ __launch_bounds__(512) void k_kv(const float* __restrict__ kvw){
    __shared__ float rp[8*256];
    __shared__ float scn[8];
    int tid = threadIdx.x;
    int mg = blockIdx.x, b = blockIdx.y;
    if (tid < 8){
        float c = 0.f;
        for (int ch = 0; ch < NCH; ch++) c += g_cntp[(ch*NB+b)*NM + mg*8 + tid];
        scn[tid] = c;
    }
    __syncthreads();
    for (int i = tid; i < 8*256; i += 512){
        int mi = i>>8;
        float s = 0.f;
        #pragma unroll 4
        for (int ch = 0; ch < NCH; ch++)
            s += g_poolp[((size_t)(ch*NB+b)*NM + mg*8 + mi)*NC + (i&255)];
        rp[i] = s / (scn[mi] + 1e-20f);
    }
    __syncthreads();
    int j = tid;
    float a8[8];
    #pragma unroll
    for (int i = 0; i < 8; i++) a8[i] = 0.f;
    #pragma unroll 4
    for (int c = 0; c < 256; c++){
        float wv = __ldg(kvw + (size_t)c*512 + j);
        #pragma unroll
        for (int i = 0; i < 8; i++) a8[i] = fmaf(rp[i*256+c], wv, a8[i]);
    }
    float* dst = (j < 256) ? g_k : g_v;
    int jj = j & 255;
    #pragma unroll
    for (int i = 0; i < 8; i++)
        dst[((size_t)b*NM + mg*8 + i)*NC + jj] = a8[i];
}

// ---- A^T = scale*(q_w@k^T)^T, split ----
__global__ __launch_bounds__(256) void k_prep(const float* __restrict__ qw){
    __shared__ float ks[32*32];
    int c = threadIdx.x, b = blockIdx.x, h = blockIdx.y;
    for (int i = c; i < 1024; i += 256)
        ks[i] = g_k[((size_t)b*NM + (i>>5))*NC + h*32 + (i&31)];
    __syncthreads();
    float q[32];
    const float* qp = qw + (size_t)c*NC + h*32;
    #pragma unroll
    for (int i = 0; i < 32; i++) q[i] = qp[i];
    for (int m = 0; m < 32; m++){
        float acc = 0.f;
        #pragma unroll
        for (int i = 0; i < 32; i++) acc = fmaf(q[i], ks[m*32+i], acc);
        size_t o = ((size_t)b*256 + h*32 + m)*256 + c;
        spl(acc*0.17677669529663689f, g_Abh[o], g_Abl[o]);
    }
}

// ---- fused: logits HMMA GEMM (bf16 3-pass) + softmax + PV + residual + LN2 + split ----
__global__ __launch_bounds__(256,1) void k_attn(const float* __restrict__ x,
                                                const float* __restrict__ g2, const float* __restrict__ b2){
    extern __shared__ char dsm[];
    uint32_t sb = s2u(dsm);
    float* Ls   = (float*)dsm;
    float* v_s  = (float*)(dsm + 133120);
    float* cnt_s= (float*)(dsm + 165888);
    int tid = threadIdx.x, w = tid>>5, lane = tid&31;
    size_t row0 = (size_t)blockIdx.x*128;
    int b = blockIdx.x >> 6;
    const __nv_bfloat16 *Bh = g_Abh + (size_t)b*65536, *Bl = g_Abl + (size_t)b*65536;

    for (int i = tid; i < 8192; i += 256) v_s[i] = g_v[(size_t)b*8192 + i];
    if (tid < 32){
        float c = 0.f;
        for (int ch = 0; ch < NCH; ch++) c += g_cntp[(ch*NB+b)*NM + tid];
        cnt_s[tid] = c;
    }

    int wm = w&3, wn = w>>2;
    float acc[2][16][4];
    #pragma unroll
    for (int i = 0; i < 2; i++)
        #pragma unroll
        for (int j = 0; j < 16; j++)
            #pragma unroll
            for (int q = 0; q < 4; q++) acc[i][j][q] = 0.f;

    auto load_stage = [&](int kt, int s){
        uint32_t base = sb + s*49152;
        #pragma unroll
        for (int it = 0; it < 12; it++){
            int i = tid + it*256;
            const __nv_bfloat16* src; uint32_t dst;
            if (i < 1024){
                int r = i>>3, c = i&7;
                src = ((c<4)?g_xh:g_xl) + (row0 + r)*NC + kt*32 + (c&3)*8;
                dst = base + r*128 + ((c ^ (r&7))<<4);
            } else {
                int jx = i - 1024;
                int r = jx>>3, c = jx&7;
                src = ((c<4)?Bh:Bl) + (size_t)r*NC + kt*32 + (c&3)*8;
                dst = base + 16384 + r*128 + ((c ^ (r&7))<<4);
            }
            CPA(dst, src);
        }
        CPCOMMIT();
    };

    load_stage(0, 0);
    for (int kt = 0; kt < 8; kt++){
        int s = kt & 1;
        if (kt+1 < 8){ load_stage(kt+1, s^1); CPWAIT1(); }
        else CPWAIT0();
        __syncthreads();
        uint32_t As = sb + s*49152;
        uint32_t Bs = As + 16384;
        #pragma unroll
        for (int kk = 0; kk < 2; kk++){
            uint32_t ah[2][4], al[2][4];
            #pragma unroll
            for (int mt = 0; mt < 2; mt++){
                int r = wm*32 + mt*16 + (lane&15);
                int ch = kk*2 + ((lane>>4)&1);
                LDSM4(ah[mt], As + r*128 + (((ch  ) ^ (r&7))<<4));
                LDSM4(al[mt], As + r*128 + (((ch+4) ^ (r&7))<<4));
            }
            #pragma unroll
            for (int nt2 = 0; nt2 < 8; nt2++){
                uint32_t bh[4], bl[4];
                int r = wn*128 + nt2*16 + (lane&7) + ((lane>>4)&1)*8;
                int ch = kk*2 + ((lane>>3)&1);
                LDSM4(bh, Bs + r*128 + (((ch  ) ^ (r&7))<<4));
                LDSM4(bl, Bs + r*128 + (((ch+4) ^ (r&7))<<4));
                #pragma unroll
                for (int mt = 0; mt < 2; mt++)
                    #pragma unroll
                    for (int hf = 0; hf < 2; hf++){
                        float* d = acc[mt][nt2*2+hf];
                        MMAB(d, ah[mt], &bh[hf*2]);
                        MMAB(d, ah[mt], &bl[hf*2]);
                        MMAB(d, al[mt], &bh[hf*2]);
                    }
            }
        }
        __syncthreads();
    }

    int g = lane>>2, t4 = lane&3;
    #pragma unroll
    for (int mt = 0; mt < 2; mt++){
        int R = wm*32 + mt*16 + g;
        #pragma unroll
        for (int nt = 0; nt < 16; nt++){
            int C = wn*128 + nt*8 + t4*2;
            float* d = acc[mt][nt];
            *(float2*)(Ls + R*260 + C)     = make_float2(d[0], d[1]);
            *(float2*)(Ls + (R+8)*260 + C) = make_float2(d[2], d[3]);
        }
    }
    __syncthreads();

    float g2r[8], b2r[8];
    #pragma unroll
    for (int j = 0; j < 8; j++){ g2r[j] = g2[j*32+lane]; b2r[j] = b2[j*32+lane]; }
    bool valid = cnt_s[lane] >= 1.f;
    for (int t = 0; t < 16; t++){
        int rloc = w*16 + t;
        size_t row = row0 + rloc;
        float out[8];
        #pragma unroll
        for (int j = 0; j < 8; j++){
            float l = Ls[rloc*260 + j*32 + lane];
            float mxv = valid ? l : -3.0e38f;
            #pragma unroll
            for (int o = 16; o; o >>= 1) mxv = fmaxf(mxv, __shfl_xor_sync(~0u, mxv, o));
            float e = valid ? expf(l - mxv) : 0.f;
            float s = wsum(e);
            float p = e / s;
            float accv = 0.f;
            #pragma unroll
            for (int m = 0; m < 32; m++){
                float pm = __shfl_sync(~0u, p, m);
                accv = fmaf(pm, v_s[m*256 + j*32 + lane], accv);
            }
            out[j] = accv;
        }
        const float* xr = x + row*256;
        float x2v[8], s = 0.f, sq = 0.f;
        #pragma unroll
        for (int j = 0; j < 8; j++){
            float v = xr[j*32+lane] + out[j];
            x2v[j] = v; s += v; sq += v*v;
        }
        s = wsum(s); sq = wsum(sq);
        float mu = s*(1.f/256.f);
        float rs = rsqrtf(sq*(1.f/256.f) - mu*mu + 1e-5f);
        #pragma unroll
        for (int j = 0; j < 8; j++){
            int c = j*32 + lane;
            size_t o = row*256 + c;
            g_x2[o] = x2v[j];
            spl((x2v[j]-mu)*rs*g2r[j] + b2r[j], g_yh[o], g_yl[o]);
        }
    }
}

// ---- MLP1: bf16 3-pass HMMA, epilogue -> fp16 h ----
__global__ __launch_bounds__(256,1) void k_gemm1(const float* __restrict__ bias){
    extern __shared__ char dsm[];
    uint32_t sb = s2u(dsm);
    int tid = threadIdx.x, w = tid>>5, lane = tid&31;
    size_t row0 = (size_t)blockIdx.y*128;
    int n0 = blockIdx.x*128;
    const __nv_bfloat16 *Ah=g_yh, *Al=g_yl, *Bh=g_w1h, *Bl=g_w1l;
    int wm = w&3, wn = w>>2;

    float acc[2][8][4];
    #pragma unroll
    for (int i = 0; i < 2; i++)
        #pragma unroll
        for (int j = 0; j < 8; j++)
            #pragma unroll
            for (int q = 0; q < 4; q++) acc[i][j][q] = 0.f;

    auto load_stage = [&](int kt, int s){
        uint32_t base = sb + s*32768;
        #pragma unroll
        for (int it = 0; it < 8; it++){
            int i = tid + it*256;
            int r = (i>>3)&127, c = i&7;
            const __nv_bfloat16* src;
            uint32_t dst;
            if (i < 1024){
                src = ((c<4)?Ah:Al) + (row0 + r)*256 + kt*32 + (c&3)*8;
                dst = base + r*128 + ((c ^ (r&7))<<4);
            } else {
                src = ((c<4)?Bh:Bl) + (size_t)(n0 + r)*256 + kt*32 + (c&3)*8;
                dst = base + 16384 + r*128 + ((c ^ (r&7))<<4);
            }
            CPA(dst, src);
        }
        CPCOMMIT();
    };

    load_stage(0, 0);
    for (int kt = 0; kt < 8; kt++){
        int s = kt & 1;
        if (kt+1 < 8){ load_stage(kt+1, s^1); CPWAIT1(); }
        else CPWAIT0();
        __syncthreads();
        uint32_t As = sb + s*32768;
        uint32_t Bs = As + 16384;
        #pragma unroll
        for (int kk = 0; kk < 2; kk++){
            uint32_t ah[2][4], al[2][4], bhv[4][4], blv[4][4];
            #pragma unroll
            for (int mt = 0; mt < 2; mt++){
                int r = wm*32 + mt*16 + (lane&15);
                int ch = kk*2 + ((lane>>4)&1);
                LDSM4(ah[mt], As + r*128 + (((ch  ) ^ (r&7))<<4));
                LDSM4(al[mt], As + r*128 + (((ch+4) ^ (r&7))<<4));
            }
            #pragma unroll
            for (int nt2 = 0; nt2 < 4; nt2++){
                int r = wn*64 + nt2*16 + (lane&7) + ((lane>>4)&1)*8;
                int ch = kk*2 + ((lane>>3)&1);
                LDSM4(bhv[nt2], Bs + r*128 + (((ch  ) ^ (r&7))<<4));
                LDSM4(blv[nt2], Bs + r*128 + (((ch+4) ^ (r&7))<<4));
            }
            #pragma unroll
            for (int mt = 0; mt < 2; mt++)
                #pragma unroll
                for (int nt = 0; nt < 8; nt++){
                    uint32_t* bph = &bhv[nt>>1][(nt&1)*2];
                    uint32_t* bpl = &blv[nt>>1][(nt&1)*2];
                    MMAB(acc[mt][nt], ah[mt], bph);
                    MMAB(acc[mt][nt], ah[mt], bpl);
                    MMAB(acc[mt][nt], al[mt], bph);
                }
        }
        __syncthreads();
    }

    int g = lane>>2, t = lane&3;
    #pragma unroll
    for (int mt = 0; mt < 2; mt++){
        size_t R0 = row0 + wm*32 + mt*16 + g;
        #pragma unroll
        for (int nt = 0; nt < 8; nt++){
            int C = n0 + wn*64 + nt*8 + t*2;
            float* d = acc[mt][nt];
            float b0v = __ldg(bias + C), b1v = __ldg(bias + C + 1);
            *(uint32_t*)(g_h + R0*1024 + C)     = pkh(geluf(d[0]+b0v), geluf(d[1]+b1v));
            *(uint32_t*)(g_h + (R0+8)*1024 + C) = pkh(geluf(d[2]+b0v), geluf(d[3]+b1v));
        }
    }
}

// ---- MLP2: fp16 single-pass HMMA + bias + residual ----
__global__ __launch_bounds__(256,1) void k_gemm2f(const float* __restrict__ bias, float* __restrict__ outf){
    extern __shared__ char dsm[];
    uint32_t sb = s2u(dsm);
    int tid = threadIdx.x, w = tid>>5, lane = tid&31;
    size_t row0 = (size_t)blockIdx.y*128;
    int n0 = blockIdx.x*128;
    int wm = w&3, wn = w>>2;

    float acc[2][8][4];
    #pragma unroll
    for (int i = 0; i < 2; i++)
        #pragma unroll
        for (int j = 0; j < 8; j++)
            #pragma unroll
            for (int q = 0; q < 4; q++) acc[i][j][q] = 0.f;

    auto load_stage = [&](int kt, int s){
        uint32_t base = sb + s*32768;
        #pragma unroll
        for (int it = 0; it < 8; it++){
            int i = tid + it*256;
            int r = (i>>3)&127, c = i&7;
            const __half* src;
            uint32_t dst;
            if (i < 1024){
                src = g_h + (row0 + r)*1024 + kt*64 + c*8;
                dst = base + r*128 + ((c ^ (r&7))<<4);
            } else {
                src = g_w2hh + (size_t)(n0 + r)*1024 + kt*64 + c*8;
                dst = base + 16384 + r*128 + ((c ^ (r&7))<<4);
            }
            CPA(dst, src);
        }
        CPCOMMIT();
    };

    load_stage(0, 0);
    for (int kt = 0; kt < 16; kt++){
        int s = kt & 1;
        if (kt+1 < 16){ load_stage(kt+1, s^1); CPWAIT1(); }
        else CPWAIT0();
        __syncthreads();
        uint32_t As = sb + s*32768;
        uint32_t Bs = As + 16384;
        #pragma unroll
        for (int kk = 0; kk < 4; kk++){
            uint32_t ah[2][4], bhv[4][4];
            #pragma unroll
            for (int mt = 0; mt < 2; mt++){
                int r = wm*32 + mt*16 + (lane&15);
                int ch = kk*2 + ((lane>>4)&1);
                LDSM4(ah[mt], As + r*128 + ((ch ^ (r&7))<<4));
            }
            #pragma unroll
            for (int nt2 = 0; nt2 < 4; nt2++){
                int r = wn*64 + nt2*16 + (lane&7) + ((lane>>4)&1)*8;
                int ch = kk*2 + ((lane>>3)&1);
                LDSM4(bhv[nt2], Bs + r*128 + ((ch ^ (r&7))<<4));
            }
            #pragma unroll
            for (int mt = 0; mt < 2; mt++)
                #pragma unroll
                for (int nt = 0; nt < 8; nt++)
                    MMAH(acc[mt][nt], ah[mt], &bhv[nt>>1][(nt&1)*2]);
        }
        __syncthreads();
    }

    int g = lane>>2, t = lane&3;
    #pragma unroll
    for (int mt = 0; mt < 2; mt++){
        size_t R0 = row0 + wm*32 + mt*16 + g;
        #pragma unroll
        for (int nt = 0; nt < 8; nt++){
            int C = n0 + wn*64 + nt*8 + t*2;
            float* d = acc[mt][nt];
            float b0v = __ldg(bias + C), b1v = __ldg(bias + C + 1);
            float2 x0 = *(float2*)(g_x2 + R0*256 + C);
            float2 x1 = *(float2*)(g_x2 + (R0+8)*256 + C);
            *(float2*)(outf + R0*256 + C)     = make_float2(d[0]+b0v+x0.x, d[1]+b1v+x0.y);
            *(float2*)(outf + (R0+8)*256 + C) = make_float2(d[2]+b0v+x1.x, d[3]+b1v+x1.y);
        }
    }
}

extern "C" void kernel_launch(void* const* d_in, const int* in_sizes, int n_in,
                              void* d_out, int out_size) {
    const float* x   = (const float*)d_in[0];
    const float* rot = (const float*)d_in[1];
    const float* n1g = (const float*)d_in[2];
    const float* n1b = (const float*)d_in[3];
    const float* qw  = (const float*)d_in[4];
    const float* kvw = (const float*)d_in[5];
    const float* n2g = (const float*)d_in[6];
    const float* n2b = (const float*)d_in[7];
    const float* w1  = (const float*)d_in[8];
    const float* b1  = (const float*)d_in[9];
    const float* w2  = (const float*)d_in[10];
    const float* b2  = (const float*)d_in[11];
    float* out = (float*)d_out;

    const int POOL_SM = (4*32*256 + 128)*4;
    const int GSM = 65536;
    const int ASM = 166016;
    cudaFuncSetAttribute(k_pool, cudaFuncAttributeMaxDynamicSharedMemorySize, POOL_SM);
    cudaFuncSetAttribute(k_attn, cudaFuncAttributeMaxDynamicSharedMemorySize, ASM);
    cudaFuncSetAttribute(k_gemm1, cudaFuncAttributeMaxDynamicSharedMemorySize, GSM);
    cudaFuncSetAttribute(k_gemm2f, cudaFuncAttributeMaxDynamicSharedMemorySize, GSM);

    k_prepw<<<1280, 256>>>(w1, w2);
    k_ln1<<<(NB*NN)/128, 256>>>(x, rot, n1g, n1b);
    k_pool<<<dim3(NCH, NB), 128, POOL_SM>>>();
    k_kv<<<dim3(4, NB), 512>>>(kvw);
    k_prep<<<dim3(NB, 8), 256>>>(qw);
    k_attn<<<(NB*NN)/128, 256, ASM>>>(x, n2g, n2b);
    k_gemm1<<<dim3(8, (NB*NN)/128), 256, GSM>>>(b1);
    k_gemm2f<<<dim3(2, (NB*NN)/128), 256, GSM>>>(b2, out);
}

// round 9
// speedup vs baseline: 6.5075x; 1.2703x over previous
#include <cuda_runtime.h>
#include <cuda_bf16.h>
#include <cuda_fp16.h>
#include <math.h>
#include <stdint.h>

#define NB 16
#define NN 8192
#define NC 256
#define NM 32
#define NCH 16
#define TOKCH (NN/NCH)

__device__ __nv_bfloat16 g_xh[NB*NN*NC], g_xl[NB*NN*NC];
__device__ unsigned int g_bkt[NB*NN];
__device__ float g_poolp[NCH*NB*NM*NC];
__device__ float g_cntp [NCH*NB*NM];
__device__ float g_k[NB*NM*NC];
__device__ float g_v[NB*NM*NC];
__device__ __nv_bfloat16 g_Abh[NB*NC*NC], g_Abl[NB*NC*NC];
__device__ float g_x2[NB*NN*NC];
__device__ __half g_y[NB*NN*NC];
__device__ __half g_h[(size_t)NB*NN*1024];
__device__ __half g_w1hh[1024*256];
__device__ __half g_w2hh[256*1024];

__device__ __forceinline__ uint32_t s2u(const void* p){
    uint32_t a; asm("{ .reg .u64 t; cvta.to.shared.u64 t, %1; cvt.u32.u64 %0, t; }" : "=r"(a) : "l"(p)); return a;
}
#define CPA(dst, src) asm volatile("cp.async.cg.shared.global [%0], [%1], 16;" :: "r"(dst), "l"(src))
#define CPCOMMIT()    asm volatile("cp.async.commit_group;" ::: "memory")
#define CPWAIT1()     asm volatile("cp.async.wait_group 1;" ::: "memory")
#define CPWAIT0()     asm volatile("cp.async.wait_group 0;" ::: "memory")
#define LDSM4(r, a) asm volatile("ldmatrix.sync.aligned.m8n8.x4.shared.b16 {%0,%1,%2,%3}, [%4];" \
    : "=r"((r)[0]), "=r"((r)[1]), "=r"((r)[2]), "=r"((r)[3]) : "r"(a))
#define MMAB(d, a, b) asm volatile( \
    "mma.sync.aligned.m16n8k16.row.col.f32.bf16.bf16.f32 " \
    "{%0,%1,%2,%3}, {%4,%5,%6,%7}, {%8,%9}, {%0,%1,%2,%3};" \
    : "+f"((d)[0]), "+f"((d)[1]), "+f"((d)[2]), "+f"((d)[3]) \
    : "r"((a)[0]), "r"((a)[1]), "r"((a)[2]), "r"((a)[3]), "r"((b)[0]), "r"((b)[1]))
#define MMAH(d, a, b) asm volatile( \
    "mma.sync.aligned.m16n8k16.row.col.f32.f16.f16.f32 " \
    "{%0,%1,%2,%3}, {%4,%5,%6,%7}, {%8,%9}, {%0,%1,%2,%3};" \
    : "+f"((d)[0]), "+f"((d)[1]), "+f"((d)[2]), "+f"((d)[3]) \
    : "r"((a)[0]), "r"((a)[1]), "r"((a)[2]), "r"((a)[3]), "r"((b)[0]), "r"((b)[1]))

__device__ __forceinline__ void spl(float x, __nv_bfloat16&h, __nv_bfloat16&l){
    h = __float2bfloat16(x); l = __float2bfloat16(x - __bfloat162float(h));
}
__device__ __forceinline__ uint32_t pkh(float f0, float f1){
    __half2 h = __floats2half2_rn(f0, f1);
    return *(uint32_t*)&h;
}
__device__ __forceinline__ float geluf(float u){ return 0.5f*u*(1.f + erff(u*0.70710678118654752f)); }
__device__ __forceinline__ float wsum(float v){
    #pragma unroll
    for (int o=16;o;o>>=1) v += __shfl_xor_sync(~0u,v,o);
    return v;
}

// ---- weight transpose: w1 -> fp16, w2 -> fp16 ----
__global__ void k_prepw(const float* __restrict__ w1, const float* __restrict__ w2){
    int n = blockIdx.x, t = threadIdx.x;
    if (n < 1024){
        float v = w1[(size_t)t*1024 + n];
        g_w1hh[n*256+t] = __float2half(v);
    } else {
        int n2 = n-1024;
        for (int k = t; k < 1024; k += 256){
            float v = w2[(size_t)k*256 + n2];
            g_w2hh[n2*1024+k] = __float2half(v);
        }
    }
}

// ---- LN1 + LSH + split ----
__global__ __launch_bounds__(256) void k_ln1(const float* __restrict__ x, const float* __restrict__ rot,
                                             const float* __restrict__ g1, const float* __restrict__ b1){
    __shared__ float rT[16*256], sg[256], sb[256];
    int tid = threadIdx.x;
    for (int i = tid; i < 4096; i += 256) rT[(i&15)*256 + (i>>4)] = rot[i];
    sg[tid] = g1[tid]; sb[tid] = b1[tid];
    __syncthreads();
    int w = tid>>5, lane = tid&31;
    int base = blockIdx.x*128 + w*16;
    for (int t0 = 0; t0 < 16; t0++){
        int row = base + t0;
        const float* xr = x + (size_t)row*NC;
        float xv[8], s = 0.f, sq = 0.f;
        #pragma unroll
        for (int j = 0; j < 8; j++){ float v = xr[lane+32*j]; xv[j] = v; s += v; sq += v*v; }
        s = wsum(s); sq = wsum(sq);
        float m = s*(1.f/256.f);
        float rs = rsqrtf(sq*(1.f/256.f) - m*m + 1e-5f);
        float r16[16];
        #pragma unroll
        for (int i = 0; i < 16; i++) r16[i] = 0.f;
        #pragma unroll
        for (int j = 0; j < 8; j++){
            int c = lane + 32*j;
            float xn = (xv[j]-m)*rs*sg[c] + sb[c];
            size_t o = (size_t)row*NC + c;
            spl(xn, g_xh[o], g_xl[o]);
            #pragma unroll
            for (int i = 0; i < 16; i++) r16[i] += xn * rT[i*256 + c];
        }
        #pragma unroll
        for (int i = 0; i < 16; i++){
            #pragma unroll
            for (int o = 16; o; o >>= 1) r16[i] += __shfl_xor_sync(~0u, r16[i], o);
        }
        if (!lane){
            unsigned pkb = 0;
            #pragma unroll
            for (int h = 0; h < 4; h++){
                float best = r16[h*4]; int bi = 0;
                #pragma unroll
                for (int i = 1; i < 8; i++){
                    float v = (i < 4) ? r16[h*4+i] : -r16[h*4+i-4];
                    if (v > best){ best = v; bi = i; }
                }
                pkb |= (unsigned)bi << (8*h);
            }
            g_bkt[row] = pkb;
        }
    }
}

// ---- pooling (reads split x) ----
__global__ __launch_bounds__(128) void k_pool(){
    extern __shared__ float sp[];
    float* scnt = sp + 4*32*256;
    int tid = threadIdx.x, w = tid>>5, lane = tid&31;
    int ch = blockIdx.x, b = blockIdx.y;
    for (int i = tid; i < 4*32*256; i += 128) sp[i] = 0.f;
    if (tid < 128) scnt[tid] = 0.f;
    __syncthreads();
    float* myp = sp + w*32*256;
    float* myc = scnt + w*32;
    int n0 = ch*TOKCH + w*(TOKCH/4);
    for (int it = 0; it < TOKCH/4; it++){
        int row = b*NN + n0 + it;
        unsigned pkb = g_bkt[row];
        const __nv_bfloat16* xhp = g_xh + (size_t)row*NC;
        const __nv_bfloat16* xlp = g_xl + (size_t)row*NC;
        float xv[8];
        #pragma unroll
        for (int j = 0; j < 8; j++){
            int c = lane+32*j;
            xv[j] = __bfloat162float(xhp[c]) + __bfloat162float(xlp[c]);
        }
        #pragma unroll
        for (int h = 0; h < 4; h++){
            int hm = h*8 + ((pkb >> (8*h)) & 255);
            float* dst = myp + hm*256;
            #pragma unroll
            for (int j = 0; j < 8; j++) dst[lane+32*j] += xv[j];
            if (!lane) myc[hm] += 1.f;
        }
    }
    __syncthreads();
    float* op = g_poolp + (size_t)(ch*NB + b)*NM*NC;
    for (int i = tid; i < NM*NC; i += 128)
        op[i] = sp[i] + sp[8192+i] + sp[16384+i] + sp[24576+i];
    if (tid < NM)
        g_cntp[(ch*NB+b)*NM + tid] = scnt[tid] + scnt[32+tid] + scnt[64+tid] + scnt[96+tid];
}

// ---- pooled KV projection: 256 blocks, 2 m-rows each ----
__global__ __launch_bounds__(512) void k_kv(const float* __restrict__ kvw){
    __shared__ float rp[2*256];
    __shared__ float scn[2];
    int tid = threadIdx.x;
    int mg = blockIdx.x, b = blockIdx.y;   // mg in 0..15, 2 m per block
    if (tid < 2){
        float c = 0.f;
        for (int ch = 0; ch < NCH; ch++) c += g_cntp[(ch*NB+b)*NM + mg*2 + tid];
        scn[tid] = c;
    }
    __syncthreads();
    if (tid < 512){
        int mi = tid>>8;
        float s = 0.f;
        #pragma unroll 4
        for (int ch = 0; ch < NCH; ch++)
            s += g_poolp[((size_t)(ch*NB+b)*NM + mg*2 + mi)*NC + (tid&255)];
        rp[tid] = s / (scn[mi] + 1e-20f);
    }
    __syncthreads();
    int j = tid;
    float a0 = 0.f, a1 = 0.f;
    #pragma unroll 8
    for (int c = 0; c < 256; c++){
        float wv = __ldg(kvw + (size_t)c*512 + j);
        a0 = fmaf(rp[c], wv, a0);
        a1 = fmaf(rp[256+c], wv, a1);
    }
    float* dst = (j < 256) ? g_k : g_v;
    int jj = j & 255;
    dst[((size_t)b*NM + mg*2 + 0)*NC + jj] = a0;
    dst[((size_t)b*NM + mg*2 + 1)*NC + jj] = a1;
}

// ---- A^T = scale*(q_w@k^T)^T, split ----
__global__ __launch_bounds__(256) void k_prep(const float* __restrict__ qw){
    __shared__ float ks[32*32];
    int c = threadIdx.x, b = blockIdx.x, h = blockIdx.y;
    for (int i = c; i < 1024; i += 256)
        ks[i] = g_k[((size_t)b*NM + (i>>5))*NC + h*32 + (i&31)];
    __syncthreads();
    float q[32];
    const float* qp = qw + (size_t)c*NC + h*32;
    #pragma unroll
    for (int i = 0; i < 32; i++) q[i] = qp[i];
    for (int m = 0; m < 32; m++){
        float acc = 0.f;
        #pragma unroll
        for (int i = 0; i < 32; i++) acc = fmaf(q[i], ks[m*32+i], acc);
        size_t o = ((size_t)b*256 + h*32 + m)*256 + c;
        spl(acc*0.17677669529663689f, g_Abh[o], g_Abl[o]);
    }
}

// ---- fused: logits HMMA GEMM (bf16 3-pass) + softmax + PV + residual + LN2 -> fp16 y ----
__global__ __launch_bounds__(256,1) void k_attn(const float* __restrict__ x,
                                                const float* __restrict__ g2, const float* __restrict__ b2){
    extern __shared__ char dsm[];
    uint32_t sb = s2u(dsm);
    float* Ls   = (float*)dsm;
    float* v_s  = (float*)(dsm + 133120);
    float* cnt_s= (float*)(dsm + 165888);
    int tid = threadIdx.x, w = tid>>5, lane = tid&31;
    size_t row0 = (size_t)blockIdx.x*128;
    int b = blockIdx.x >> 6;
    const __nv_bfloat16 *Bh = g_Abh + (size_t)b*65536, *Bl = g_Abl + (size_t)b*65536;

    for (int i = tid; i < 8192; i += 256) v_s[i] = g_v[(size_t)b*8192 + i];
    if (tid < 32){
        float c = 0.f;
        for (int ch = 0; ch < NCH; ch++) c += g_cntp[(ch*NB+b)*NM + tid];
        cnt_s[tid] = c;
    }

    int wm = w&3, wn = w>>2;
    float acc[2][16][4];
    #pragma unroll
    for (int i = 0; i < 2; i++)
        #pragma unroll
        for (int j = 0; j < 16; j++)
            #pragma unroll
            for (int q = 0; q < 4; q++) acc[i][j][q] = 0.f;

    auto load_stage = [&](int kt, int s){
        uint32_t base = sb + s*49152;
        #pragma unroll
        for (int it = 0; it < 12; it++){
            int i = tid + it*256;
            const __nv_bfloat16* src; uint32_t dst;
            if (i < 1024){
                int r = i>>3, c = i&7;
                src = ((c<4)?g_xh:g_xl) + (row0 + r)*NC + kt*32 + (c&3)*8;
                dst = base + r*128 + ((c ^ (r&7))<<4);
            } else {
                int jx = i - 1024;
                int r = jx>>3, c = jx&7;
                src = ((c<4)?Bh:Bl) + (size_t)r*NC + kt*32 + (c&3)*8;
                dst = base + 16384 + r*128 + ((c ^ (r&7))<<4);
            }
            CPA(dst, src);
        }
        CPCOMMIT();
    };

    load_stage(0, 0);
    for (int kt = 0; kt < 8; kt++){
        int s = kt & 1;
        if (kt+1 < 8){ load_stage(kt+1, s^1); CPWAIT1(); }
        else CPWAIT0();
        __syncthreads();
        uint32_t As = sb + s*49152;
        uint32_t Bs = As + 16384;
        #pragma unroll
        for (int kk = 0; kk < 2; kk++){
            uint32_t ah[2][4], al[2][4];
            #pragma unroll
            for (int mt = 0; mt < 2; mt++){
                int r = wm*32 + mt*16 + (lane&15);
                int ch = kk*2 + ((lane>>4)&1);
                LDSM4(ah[mt], As + r*128 + (((ch  ) ^ (r&7))<<4));
                LDSM4(al[mt], As + r*128 + (((ch+4) ^ (r&7))<<4));
            }
            #pragma unroll
            for (int nt2 = 0; nt2 < 8; nt2++){
                uint32_t bh[4], bl[4];
                int r = wn*128 + nt2*16 + (lane&7) + ((lane>>4)&1)*8;
                int ch = kk*2 + ((lane>>3)&1);
                LDSM4(bh, Bs + r*128 + (((ch  ) ^ (r&7))<<4));
                LDSM4(bl, Bs + r*128 + (((ch+4) ^ (r&7))<<4));
                #pragma unroll
                for (int mt = 0; mt < 2; mt++)
                    #pragma unroll
                    for (int hf = 0; hf < 2; hf++){
                        float* d = acc[mt][nt2*2+hf];
                        MMAB(d, ah[mt], &bh[hf*2]);
                        MMAB(d, ah[mt], &bl[hf*2]);
                        MMAB(d, al[mt], &bh[hf*2]);
                    }
            }
        }
        __syncthreads();
    }

    int g = lane>>2, t4 = lane&3;
    #pragma unroll
    for (int mt = 0; mt < 2; mt++){
        int R = wm*32 + mt*16 + g;
        #pragma unroll
        for (int nt = 0; nt < 16; nt++){
            int C = wn*128 + nt*8 + t4*2;
            float* d = acc[mt][nt];
            *(float2*)(Ls + R*260 + C)     = make_float2(d[0], d[1]);
            *(float2*)(Ls + (R+8)*260 + C) = make_float2(d[2], d[3]);
        }
    }
    __syncthreads();

    float g2r[8], b2r[8];
    #pragma unroll
    for (int j = 0; j < 8; j++){ g2r[j] = g2[j*32+lane]; b2r[j] = b2[j*32+lane]; }
    bool valid = cnt_s[lane] >= 1.f;
    for (int t = 0; t < 16; t++){
        int rloc = w*16 + t;
        size_t row = row0 + rloc;
        float out[8];
        #pragma unroll
        for (int j = 0; j < 8; j++){
            float l = Ls[rloc*260 + j*32 + lane];
            float mxv = valid ? l : -3.0e38f;
            #pragma unroll
            for (int o = 16; o; o >>= 1) mxv = fmaxf(mxv, __shfl_xor_sync(~0u, mxv, o));
            float e = valid ? expf(l - mxv) : 0.f;
            float s = wsum(e);
            float p = e / s;
            float accv = 0.f;
            #pragma unroll
            for (int m = 0; m < 32; m++){
                float pm = __shfl_sync(~0u, p, m);
                accv = fmaf(pm, v_s[m*256 + j*32 + lane], accv);
            }
            out[j] = accv;
        }
        const float* xr = x + row*256;
        float x2v[8], s = 0.f, sq = 0.f;
        #pragma unroll
        for (int j = 0; j < 8; j++){
            float v = xr[j*32+lane] + out[j];
            x2v[j] = v; s += v; sq += v*v;
        }
        s = wsum(s); sq = wsum(sq);
        float mu = s*(1.f/256.f);
        float rs = rsqrtf(sq*(1.f/256.f) - mu*mu + 1e-5f);
        #pragma unroll
        for (int j = 0; j < 8; j++){
            int c = j*32 + lane;
            size_t o = row*256 + c;
            g_x2[o] = x2v[j];
            g_y[o] = __float2half((x2v[j]-mu)*rs*g2r[j] + b2r[j]);
        }
    }
}

// ---- fp16 single-pass HMMA GEMM (MLP1 / MLP2) ----
template<int MODE, int KDIM>
__global__ __launch_bounds__(256,1) void k_gemmf(const float* __restrict__ bias, float* __restrict__ outf){
    extern __shared__ char dsm[];
    uint32_t sb = s2u(dsm);
    int tid = threadIdx.x, w = tid>>5, lane = tid&31;
    size_t row0 = (size_t)blockIdx.y*128;
    int n0 = blockIdx.x*128;
    const __half *Ah, *Bh;
    if (MODE==1){ Ah=g_y; Bh=g_w1hh; }
    else { Ah=g_h; Bh=g_w2hh; }
    constexpr int KT = KDIM/64;
    int wm = w&3, wn = w>>2;

    float acc[2][8][4];
    #pragma unroll
    for (int i = 0; i < 2; i++)
        #pragma unroll
        for (int j = 0; j < 8; j++)
            #pragma unroll
            for (int q = 0; q < 4; q++) acc[i][j][q] = 0.f;

    auto load_stage = [&](int kt, int s){
        uint32_t base = sb + s*32768;
        #pragma unroll
        for (int it = 0; it < 8; it++){
            int i = tid + it*256;
            int r = (i>>3)&127, c = i&7;
            const __half* src;
            uint32_t dst;
            if (i < 1024){
                src = Ah + (row0 + r)*KDIM + kt*64 + c*8;
                dst = base + r*128 + ((c ^ (r&7))<<4);
            } else {
                src = Bh + (size_t)(n0 + r)*KDIM + kt*64 + c*8;
                dst = base + 16384 + r*128 + ((c ^ (r&7))<<4);
            }
            CPA(dst, src);
        }
        CPCOMMIT();
    };

    load_stage(0, 0);
    for (int kt = 0; kt < KT; kt++){
        int s = kt & 1;
        if (kt+1 < KT){ load_stage(kt+1, s^1); CPWAIT1(); }
        else CPWAIT0();
        __syncthreads();
        uint32_t As = sb + s*32768;
        uint32_t Bs = As + 16384;
        #pragma unroll
        for (int kk = 0; kk < 4; kk++){
            uint32_t ah[2][4], bhv[4][4];
            #pragma unroll
            for (int mt = 0; mt < 2; mt++){
                int r = wm*32 + mt*16 + (lane&15);
                int ch = kk*2 + ((lane>>4)&1);
                LDSM4(ah[mt], As + r*128 + ((ch ^ (r&7))<<4));
            }
            #pragma unroll
            for (int nt2 = 0; nt2 < 4; nt2++){
                int r = wn*64 + nt2*16 + (lane&7) + ((lane>>4)&1)*8;
                int ch = kk*2 + ((lane>>3)&1);
                LDSM4(bhv[nt2], Bs + r*128 + ((ch ^ (r&7))<<4));
            }
            #pragma unroll
            for (int mt = 0; mt < 2; mt++)
                #pragma unroll
                for (int nt = 0; nt < 8; nt++)
                    MMAH(acc[mt][nt], ah[mt], &bhv[nt>>1][(nt&1)*2]);
        }
        __syncthreads();
    }

    int g = lane>>2, t = lane&3;
    #pragma unroll
    for (int mt = 0; mt < 2; mt++){
        size_t R0 = row0 + wm*32 + mt*16 + g;
        #pragma unroll
        for (int nt = 0; nt < 8; nt++){
            int C = n0 + wn*64 + nt*8 + t*2;
            float* d = acc[mt][nt];
            float b0v = __ldg(bias + C), b1v = __ldg(bias + C + 1);
            if (MODE == 1){
                *(uint32_t*)(g_h + R0*1024 + C)     = pkh(geluf(d[0]+b0v), geluf(d[1]+b1v));
                *(uint32_t*)(g_h + (R0+8)*1024 + C) = pkh(geluf(d[2]+b0v), geluf(d[3]+b1v));
            } else {
                float2 x0 = *(float2*)(g_x2 + R0*256 + C);
                float2 x1 = *(float2*)(g_x2 + (R0+8)*256 + C);
                *(float2*)(outf + R0*256 + C)     = make_float2(d[0]+b0v+x0.x, d[1]+b1v+x0.y);
                *(float2*)(outf + (R0+8)*256 + C) = make_float2(d[2]+b0v+x1.x, d[3]+b1v+x1.y);
            }
        }
    }
}

extern "C" void kernel_launch(void* const* d_in, const int* in_sizes, int n_in,
                              void* d_out, int out_size) {
    const float* x   = (const float*)d_in[0];
    const float* rot = (const float*)d_in[1];
    const float* n1g = (const float*)d_in[2];
    const float* n1b = (const float*)d_in[3];
    const float* qw  = (const float*)d_in[4];
    const float* kvw = (const float*)d_in[5];
    const float* n2g = (const float*)d_in[6];
    const float* n2b = (const float*)d_in[7];
    const float* w1  = (const float*)d_in[8];
    const float* b1  = (const float*)d_in[9];
    const float* w2  = (const float*)d_in[10];
    const float* b2  = (const float*)d_in[11];
    float* out = (float*)d_out;

    const int POOL_SM = (4*32*256 + 128)*4;
    const int GSM = 65536;
    const int ASM = 166016;
    cudaFuncSetAttribute(k_pool, cudaFuncAttributeMaxDynamicSharedMemorySize, POOL_SM);
    cudaFuncSetAttribute(k_attn, cudaFuncAttributeMaxDynamicSharedMemorySize, ASM);
    cudaFuncSetAttribute((const void*)k_gemmf<1,256>,  cudaFuncAttributeMaxDynamicSharedMemorySize, GSM);
    cudaFuncSetAttribute((const void*)k_gemmf<2,1024>, cudaFuncAttributeMaxDynamicSharedMemorySize, GSM);

    k_prepw<<<1280, 256>>>(w1, w2);
    k_ln1<<<(NB*NN)/128, 256>>>(x, rot, n1g, n1b);
    k_pool<<<dim3(NCH, NB), 128, POOL_SM>>>();
    k_kv<<<dim3(16, NB), 512>>>(kvw);
    k_prep<<<dim3(NB, 8), 256>>>(qw);
    k_attn<<<(NB*NN)/128, 256, ASM>>>(x, n2g, n2b);
    k_gemmf<1,256><<<dim3(8, (NB*NN)/128), 256, GSM>>>(b1, nullptr);
    k_gemmf<2,1024><<<dim3(2, (NB*NN)/128), 256, GSM>>>(b2, out);
}

// round 10
// speedup vs baseline: 6.8730x; 1.0562x over previous
#include <cuda_runtime.h>
#include <cuda_bf16.h>
#include <cuda_fp16.h>
#include <math.h>
#include <stdint.h>

#define NB 16
#define NN 8192
#define NC 256
#define NM 32
#define NCH 16
#define TOKCH (NN/NCH)

__device__ __nv_bfloat16 g_xh[NB*NN*NC], g_xl[NB*NN*NC];
__device__ unsigned int g_bkt[NB*NN];
__device__ float g_poolp[NCH*NB*NM*NC];
__device__ float g_cntp [NCH*NB*NM];
__device__ float g_k[NB*NM*NC];
__device__ float g_v[NB*NM*NC];
__device__ __nv_bfloat16 g_Abh[NB*NC*NC], g_Abl[NB*NC*NC];
__device__ float g_x2[NB*NN*NC];
__device__ __half g_y[NB*NN*NC];
__device__ __half g_w1hh[1024*256];
__device__ __half g_w2hh[256*1024];

__device__ __forceinline__ uint32_t s2u(const void* p){
    uint32_t a; asm("{ .reg .u64 t; cvta.to.shared.u64 t, %1; cvt.u32.u64 %0, t; }" : "=r"(a) : "l"(p)); return a;
}
#define CPA(dst, src) asm volatile("cp.async.cg.shared.global [%0], [%1], 16;" :: "r"(dst), "l"(src))
#define CPCOMMIT()    asm volatile("cp.async.commit_group;" ::: "memory")
#define CPWAIT1()     asm volatile("cp.async.wait_group 1;" ::: "memory")
#define CPWAIT0()     asm volatile("cp.async.wait_group 0;" ::: "memory")
#define LDSM4(r, a) asm volatile("ldmatrix.sync.aligned.m8n8.x4.shared.b16 {%0,%1,%2,%3}, [%4];" \
    : "=r"((r)[0]), "=r"((r)[1]), "=r"((r)[2]), "=r"((r)[3]) : "r"(a))
#define MMAB(d, a, b) asm volatile( \
    "mma.sync.aligned.m16n8k16.row.col.f32.bf16.bf16.f32 " \
    "{%0,%1,%2,%3}, {%4,%5,%6,%7}, {%8,%9}, {%0,%1,%2,%3};" \
    : "+f"((d)[0]), "+f"((d)[1]), "+f"((d)[2]), "+f"((d)[3]) \
    : "r"((a)[0]), "r"((a)[1]), "r"((a)[2]), "r"((a)[3]), "r"((b)[0]), "r"((b)[1]))
#define MMAH(d, a, b) asm volatile( \
    "mma.sync.aligned.m16n8k16.row.col.f32.f16.f16.f32 " \
    "{%0,%1,%2,%3}, {%4,%5,%6,%7}, {%8,%9}, {%0,%1,%2,%3};" \
    : "+f"((d)[0]), "+f"((d)[1]), "+f"((d)[2]), "+f"((d)[3]) \
    : "r"((a)[0]), "r"((a)[1]), "r"((a)[2]), "r"((a)[3]), "r"((b)[0]), "r"((b)[1]))

__device__ __forceinline__ void spl(float x, __nv_bfloat16&h, __nv_bfloat16&l){
    h = __float2bfloat16(x); l = __float2bfloat16(x - __bfloat162float(h));
}
__device__ __forceinline__ uint32_t pkh(float f0, float f1){
    __half2 h = __floats2half2_rn(f0, f1);
    return *(uint32_t*)&h;
}
__device__ __forceinline__ float geluf(float u){ return 0.5f*u*(1.f + erff(u*0.70710678118654752f)); }
__device__ __forceinline__ float wsum(float v){
    #pragma unroll
    for (int o=16;o;o>>=1) v += __shfl_xor_sync(~0u,v,o);
    return v;
}

// ---- weight transpose: w1 -> fp16 [n][k], w2 -> fp16 [n][k] ----
__global__ void k_prepw(const float* __restrict__ w1, const float* __restrict__ w2){
    int n = blockIdx.x, t = threadIdx.x;
    if (n < 1024){
        float v = w1[(size_t)t*1024 + n];
        g_w1hh[n*256+t] = __float2half(v);
    } else {
        int n2 = n-1024;
        for (int k = t; k < 1024; k += 256){
            float v = w2[(size_t)k*256 + n2];
            g_w2hh[n2*1024+k] = __float2half(v);
        }
    }
}

// ---- LN1 + LSH + split ----
__global__ __launch_bounds__(256) void k_ln1(const float* __restrict__ x, const float* __restrict__ rot,
                                             const float* __restrict__ g1, const float* __restrict__ b1){
    __shared__ float rT[16*256], sg[256], sb[256];
    int tid = threadIdx.x;
    for (int i = tid; i < 4096; i += 256) rT[(i&15)*256 + (i>>4)] = rot[i];
    sg[tid] = g1[tid]; sb[tid] = b1[tid];
    __syncthreads();
    int w = tid>>5, lane = tid&31;
    int base = blockIdx.x*128 + w*16;
    for (int t0 = 0; t0 < 16; t0++){
        int row = base + t0;
        const float* xr = x + (size_t)row*NC;
        float xv[8], s = 0.f, sq = 0.f;
        #pragma unroll
        for (int j = 0; j < 8; j++){ float v = xr[lane+32*j]; xv[j] = v; s += v; sq += v*v; }
        s = wsum(s); sq = wsum(sq);
        float m = s*(1.f/256.f);
        float rs = rsqrtf(sq*(1.f/256.f) - m*m + 1e-5f);
        float r16[16];
        #pragma unroll
        for (int i = 0; i < 16; i++) r16[i] = 0.f;
        #pragma unroll
        for (int j = 0; j < 8; j++){
            int c = lane + 32*j;
            float xn = (xv[j]-m)*rs*sg[c] + sb[c];
            size_t o = (size_t)row*NC + c;
            spl(xn, g_xh[o], g_xl[o]);
            #pragma unroll
            for (int i = 0; i < 16; i++) r16[i] += xn * rT[i*256 + c];
        }
        #pragma unroll
        for (int i = 0; i < 16; i++){
            #pragma unroll
            for (int o = 16; o; o >>= 1) r16[i] += __shfl_xor_sync(~0u, r16[i], o);
        }
        if (!lane){
            unsigned pkb = 0;
            #pragma unroll
            for (int h = 0; h < 4; h++){
                float best = r16[h*4]; int bi = 0;
                #pragma unroll
                for (int i = 1; i < 8; i++){
                    float v = (i < 4) ? r16[h*4+i] : -r16[h*4+i-4];
                    if (v > best){ best = v; bi = i; }
                }
                pkb |= (unsigned)bi << (8*h);
            }
            g_bkt[row] = pkb;
        }
    }
}

// ---- pooling ----
__global__ __launch_bounds__(128) void k_pool(){
    extern __shared__ float sp[];
    float* scnt = sp + 4*32*256;
    int tid = threadIdx.x, w = tid>>5, lane = tid&31;
    int ch = blockIdx.x, b = blockIdx.y;
    for (int i = tid; i < 4*32*256; i += 128) sp[i] = 0.f;
    if (tid < 128) scnt[tid] = 0.f;
    __syncthreads();
    float* myp = sp + w*32*256;
    float* myc = scnt + w*32;
    int n0 = ch*TOKCH + w*(TOKCH/4);
    for (int it = 0; it < TOKCH/4; it++){
        int row = b*NN + n0 + it;
        unsigned pkb = g_bkt[row];
        const __nv_bfloat16* xhp = g_xh + (size_t)row*NC;
        const __nv_bfloat16* xlp = g_xl + (size_t)row*NC;
        float xv[8];
        #pragma unroll
        for (int j = 0; j < 8; j++){
            int c = lane+32*j;
            xv[j] = __bfloat162float(xhp[c]) + __bfloat162float(xlp[c]);
        }
        #pragma unroll
        for (int h = 0; h < 4; h++){
            int hm = h*8 + ((pkb >> (8*h)) & 255);
            float* dst = myp + hm*256;
            #pragma unroll
            for (int j = 0; j < 8; j++) dst[lane+32*j] += xv[j];
            if (!lane) myc[hm] += 1.f;
        }
    }
    __syncthreads();
    float* op = g_poolp + (size_t)(ch*NB + b)*NM*NC;
    for (int i = tid; i < NM*NC; i += 128)
        op[i] = sp[i] + sp[8192+i] + sp[16384+i] + sp[24576+i];
    if (tid < NM)
        g_cntp[(ch*NB+b)*NM + tid] = scnt[tid] + scnt[32+tid] + scnt[64+tid] + scnt[96+tid];
}

// ---- pooled KV projection ----
__global__ __launch_bounds__(512) void k_kv(const float* __restrict__ kvw){
    __shared__ float rp[2*256];
    __shared__ float scn[2];
    int tid = threadIdx.x;
    int mg = blockIdx.x, b = blockIdx.y;
    if (tid < 2){
        float c = 0.f;
        for (int ch = 0; ch < NCH; ch++) c += g_cntp[(ch*NB+b)*NM + mg*2 + tid];
        scn[tid] = c;
    }
    __syncthreads();
    if (tid < 512){
        int mi = tid>>8;
        float s = 0.f;
        #pragma unroll 4
        for (int ch = 0; ch < NCH; ch++)
            s += g_poolp[((size_t)(ch*NB+b)*NM + mg*2 + mi)*NC + (tid&255)];
        rp[tid] = s / (scn[mi] + 1e-20f);
    }
    __syncthreads();
    int j = tid;
    float a0 = 0.f, a1 = 0.f;
    #pragma unroll 8
    for (int c = 0; c < 256; c++){
        float wv = __ldg(kvw + (size_t)c*512 + j);
        a0 = fmaf(rp[c], wv, a0);
        a1 = fmaf(rp[256+c], wv, a1);
    }
    float* dst = (j < 256) ? g_k : g_v;
    int jj = j & 255;
    dst[((size_t)b*NM + mg*2 + 0)*NC + jj] = a0;
    dst[((size_t)b*NM + mg*2 + 1)*NC + jj] = a1;
}

// ---- A^T = scale*(q_w@k^T)^T, split ----
__global__ __launch_bounds__(256) void k_prep(const float* __restrict__ qw){
    __shared__ float ks[32*32];
    int c = threadIdx.x, b = blockIdx.x, h = blockIdx.y;
    for (int i = c; i < 1024; i += 256)
        ks[i] = g_k[((size_t)b*NM + (i>>5))*NC + h*32 + (i&31)];
    __syncthreads();
    float q[32];
    const float* qp = qw + (size_t)c*NC + h*32;
    #pragma unroll
    for (int i = 0; i < 32; i++) q[i] = qp[i];
    for (int m = 0; m < 32; m++){
        float acc = 0.f;
        #pragma unroll
        for (int i = 0; i < 32; i++) acc = fmaf(q[i], ks[m*32+i], acc);
        size_t o = ((size_t)b*256 + h*32 + m)*256 + c;
        spl(acc*0.17677669529663689f, g_Abh[o], g_Abl[o]);
    }
}

// ---- fused: logits HMMA GEMM (bf16 3-pass) + softmax + PV + residual + LN2 -> fp16 y ----
__global__ __launch_bounds__(256,1) void k_attn(const float* __restrict__ x,
                                                const float* __restrict__ g2, const float* __restrict__ b2){
    extern __shared__ char dsm[];
    uint32_t sb = s2u(dsm);
    float* Ls   = (float*)dsm;
    float* v_s  = (float*)(dsm + 133120);
    float* cnt_s= (float*)(dsm + 165888);
    int tid = threadIdx.x, w = tid>>5, lane = tid&31;
    size_t row0 = (size_t)blockIdx.x*128;
    int b = blockIdx.x >> 6;
    const __nv_bfloat16 *Bh = g_Abh + (size_t)b*65536, *Bl = g_Abl + (size_t)b*65536;

    for (int i = tid; i < 8192; i += 256) v_s[i] = g_v[(size_t)b*8192 + i];
    if (tid < 32){
        float c = 0.f;
        for (int ch = 0; ch < NCH; ch++) c += g_cntp[(ch*NB+b)*NM + tid];
        cnt_s[tid] = c;
    }

    int wm = w&3, wn = w>>2;
    float acc[2][16][4];
    #pragma unroll
    for (int i = 0; i < 2; i++)
        #pragma unroll
        for (int j = 0; j < 16; j++)
            #pragma unroll
            for (int q = 0; q < 4; q++) acc[i][j][q] = 0.f;

    auto load_stage = [&](int kt, int s){
        uint32_t base = sb + s*49152;
        #pragma unroll
        for (int it = 0; it < 12; it++){
            int i = tid + it*256;
            const __nv_bfloat16* src; uint32_t dst;
            if (i < 1024){
                int r = i>>3, c = i&7;
                src = ((c<4)?g_xh:g_xl) + (row0 + r)*NC + kt*32 + (c&3)*8;
                dst = base + r*128 + ((c ^ (r&7))<<4);
            } else {
                int jx = i - 1024;
                int r = jx>>3, c = jx&7;
                src = ((c<4)?Bh:Bl) + (size_t)r*NC + kt*32 + (c&3)*8;
                dst = base + 16384 + r*128 + ((c ^ (r&7))<<4);
            }
            CPA(dst, src);
        }
        CPCOMMIT();
    };

    load_stage(0, 0);
    for (int kt = 0; kt < 8; kt++){
        int s = kt & 1;
        if (kt+1 < 8){ load_stage(kt+1, s^1); CPWAIT1(); }
        else CPWAIT0();
        __syncthreads();
        uint32_t As = sb + s*49152;
        uint32_t Bs = As + 16384;
        #pragma unroll
        for (int kk = 0; kk < 2; kk++){
            uint32_t ah[2][4], al[2][4];
            #pragma unroll
            for (int mt = 0; mt < 2; mt++){
                int r = wm*32 + mt*16 + (lane&15);
                int ch = kk*2 + ((lane>>4)&1);
                LDSM4(ah[mt], As + r*128 + (((ch  ) ^ (r&7))<<4));
                LDSM4(al[mt], As + r*128 + (((ch+4) ^ (r&7))<<4));
            }
            #pragma unroll
            for (int nt2 = 0; nt2 < 8; nt2++){
                uint32_t bh[4], bl[4];
                int r = wn*128 + nt2*16 + (lane&7) + ((lane>>4)&1)*8;
                int ch = kk*2 + ((lane>>3)&1);
                LDSM4(bh, Bs + r*128 + (((ch  ) ^ (r&7))<<4));
                LDSM4(bl, Bs + r*128 + (((ch+4) ^ (r&7))<<4));
                #pragma unroll
                for (int mt = 0; mt < 2; mt++)
                    #pragma unroll
                    for (int hf = 0; hf < 2; hf++){
                        float* d = acc[mt][nt2*2+hf];
                        MMAB(d, ah[mt], &bh[hf*2]);
                        MMAB(d, ah[mt], &bl[hf*2]);
                        MMAB(d, al[mt], &bh[hf*2]);
                    }
            }
        }
        __syncthreads();
    }

    int g = lane>>2, t4 = lane&3;
    #pragma unroll
    for (int mt = 0; mt < 2; mt++){
        int R = wm*32 + mt*16 + g;
        #pragma unroll
        for (int nt = 0; nt < 16; nt++){
            int C = wn*128 + nt*8 + t4*2;
            float* d = acc[mt][nt];
            *(float2*)(Ls + R*260 + C)     = make_float2(d[0], d[1]);
            *(float2*)(Ls + (R+8)*260 + C) = make_float2(d[2], d[3]);
        }
    }
    __syncthreads();

    float g2r[8], b2r[8];
    #pragma unroll
    for (int j = 0; j < 8; j++){ g2r[j] = g2[j*32+lane]; b2r[j] = b2[j*32+lane]; }
    bool valid = cnt_s[lane] >= 1.f;
    for (int t = 0; t < 16; t++){
        int rloc = w*16 + t;
        size_t row = row0 + rloc;
        float out[8];
        #pragma unroll
        for (int j = 0; j < 8; j++){
            float l = Ls[rloc*260 + j*32 + lane];
            float mxv = valid ? l : -3.0e38f;
            #pragma unroll
            for (int o = 16; o; o >>= 1) mxv = fmaxf(mxv, __shfl_xor_sync(~0u, mxv, o));
            float e = valid ? expf(l - mxv) : 0.f;
            float s = wsum(e);
            float p = e / s;
            float accv = 0.f;
            #pragma unroll
            for (int m = 0; m < 32; m++){
                float pm = __shfl_sync(~0u, p, m);
                accv = fmaf(pm, v_s[m*256 + j*32 + lane], accv);
            }
            out[j] = accv;
        }
        const float* xr = x + row*256;
        float x2v[8], s = 0.f, sq = 0.f;
        #pragma unroll
        for (int j = 0; j < 8; j++){
            float v = xr[j*32+lane] + out[j];
            x2v[j] = v; s += v; sq += v*v;
        }
        s = wsum(s); sq = wsum(sq);
        float mu = s*(1.f/256.f);
        float rs = rsqrtf(sq*(1.f/256.f) - mu*mu + 1e-5f);
        #pragma unroll
        for (int j = 0; j < 8; j++){
            int c = j*32 + lane;
            size_t o = row*256 + c;
            g_x2[o] = x2v[j];
            g_y[o] = __float2half((x2v[j]-mu)*rs*g2r[j] + b2r[j]);
        }
    }
}

// ---- fused MLP: y(128x256) -> h chunks (smem) -> out(128x256) + bias + residual ----
// smem: ys[0,64K) 4 k-stages of 128x64; wbuf[64K,128K); hs[128K,160K) 2 sub-tiles 128x64
__global__ __launch_bounds__(256,1) void k_mlp(const float* __restrict__ b1v,
                                               const float* __restrict__ b2v,
                                               float* __restrict__ outf){
    extern __shared__ char dsm[];
    uint32_t sb = s2u(dsm);
    uint32_t ysb = sb, wbb = sb + 65536, hbb = sb + 131072;
    int tid = threadIdx.x, w = tid>>5, lane = tid&31;
    size_t row0 = (size_t)blockIdx.x*128;
    int wm = w&3;
    int wn1 = w>>2;   // MLP1 n-group (64 wide of 128)
    int wn2 = w>>2;   // MLP2 n-group (128 wide of 256)

    // load y tile: 4 stages x (128 rows x 64 k)
    #pragma unroll
    for (int it = 0; it < 16; it++){
        int i = tid + it*256;          // 0..4095
        int kt = i>>10, rem = i&1023;
        int r = rem>>3, c = rem&7;
        const __half* src = g_y + (row0 + r)*256 + kt*64 + c*8;
        uint32_t dst = ysb + kt*16384 + r*128 + ((c ^ (r&7))<<4);
        CPA(dst, src);
    }
    CPCOMMIT();
    CPWAIT0();
    __syncthreads();

    float acc2[2][16][4];
    #pragma unroll
    for (int i = 0; i < 2; i++)
        #pragma unroll
        for (int j = 0; j < 16; j++)
            #pragma unroll
            for (int q = 0; q < 4; q++) acc2[i][j][q] = 0.f;

    auto load_w1 = [&](int nc, int kt, int s){
        uint32_t base = wbb + s*16384;
        #pragma unroll
        for (int it = 0; it < 4; it++){
            int i = tid + it*256;       // 0..1023
            int r = i>>3, c = i&7;      // r = local n row 0..127
            const __half* src = g_w1hh + (size_t)(nc*128 + r)*256 + kt*64 + c*8;
            uint32_t dst = base + r*128 + ((c ^ (r&7))<<4);
            CPA(dst, src);
        }
        CPCOMMIT();
    };
    auto load_w2 = [&](int nc, int ks, int s){
        uint32_t base = wbb + s*32768;
        #pragma unroll
        for (int it = 0; it < 8; it++){
            int i = tid + it*256;       // 0..2047
            int r = i>>3, c = i&7;      // r = out col 0..255
            const __half* src = g_w2hh + (size_t)r*1024 + nc*128 + ks*64 + c*8;
            uint32_t dst = base + r*128 + ((c ^ (r&7))<<4);
            CPA(dst, src);
        }
        CPCOMMIT();
    };

    int g = lane>>2, t4 = lane&3;

    for (int nc = 0; nc < 8; nc++){
        // ---------- MLP1: acc1 = y @ w1[nc-chunk]^T ----------
        float acc1[2][8][4];
        #pragma unroll
        for (int i = 0; i < 2; i++)
            #pragma unroll
            for (int j = 0; j < 8; j++)
                #pragma unroll
                for (int q = 0; q < 4; q++) acc1[i][j][q] = 0.f;

        load_w1(nc, 0, 0);
        for (int kt = 0; kt < 4; kt++){
            int s = kt & 1;
            if (kt+1 < 4){ load_w1(nc, kt+1, s^1); CPWAIT1(); }
            else CPWAIT0();
            __syncthreads();
            uint32_t As = ysb + kt*16384;
            uint32_t Bs = wbb + s*16384;
            #pragma unroll
            for (int kk = 0; kk < 4; kk++){
                uint32_t ah[2][4], bhv[4][4];
                #pragma unroll
                for (int mt = 0; mt < 2; mt++){
                    int r = wm*32 + mt*16 + (lane&15);
                    int ch = kk*2 + ((lane>>4)&1);
                    LDSM4(ah[mt], As + r*128 + ((ch ^ (r&7))<<4));
                }
                #pragma unroll
                for (int nt2 = 0; nt2 < 4; nt2++){
                    int r = wn1*64 + nt2*16 + (lane&7) + ((lane>>4)&1)*8;
                    int ch = kk*2 + ((lane>>3)&1);
                    LDSM4(bhv[nt2], Bs + r*128 + ((ch ^ (r&7))<<4));
                }
                #pragma unroll
                for (int mt = 0; mt < 2; mt++)
                    #pragma unroll
                    for (int nt = 0; nt < 8; nt++)
                        MMAH(acc1[mt][nt], ah[mt], &bhv[nt>>1][(nt&1)*2]);
            }
            __syncthreads();
        }

        // ---------- gelu + bias -> hs (swizzled fp16) ----------
        #pragma unroll
        for (int mt = 0; mt < 2; mt++){
            int R = wm*32 + mt*16 + g;
            #pragma unroll
            for (int nt = 0; nt < 8; nt++){
                int cl = wn1*64 + nt*8 + t4*2;
                int Cg = nc*128 + cl;
                float b0v = __ldg(b1v + Cg), b1vv = __ldg(b1v + Cg + 1);
                float* d = acc1[mt][nt];
                uint32_t base = hbb + wn1*16384 + ((nt ^ (R&7))<<4) + t4*4;
                uint32_t base8 = hbb + wn1*16384 + ((nt ^ ((R+8)&7))<<4) + t4*4;
                *(uint32_t*)(dsm + (base  - sb) + R*128)     = pkh(geluf(d[0]+b0v), geluf(d[1]+b1vv));
                *(uint32_t*)(dsm + (base8 - sb) + (R+8)*128) = pkh(geluf(d[2]+b0v), geluf(d[3]+b1vv));
            }
        }
        __syncthreads();

        // ---------- MLP2 partial: acc2 += h_chunk @ w2[k-chunk]^T ----------
        load_w2(nc, 0, 0);
        for (int ks = 0; ks < 2; ks++){
            int s = ks & 1;
            if (ks+1 < 2){ load_w2(nc, ks+1, s^1); CPWAIT1(); }
            else CPWAIT0();
            __syncthreads();
            uint32_t As = hbb + ks*16384;
            uint32_t Bs = wbb + s*32768;
            #pragma unroll
            for (int kk = 0; kk < 4; kk++){
                uint32_t ah[2][4];
                #pragma unroll
                for (int mt = 0; mt < 2; mt++){
                    int r = wm*32 + mt*16 + (lane&15);
                    int ch = kk*2 + ((lane>>4)&1);
                    LDSM4(ah[mt], As + r*128 + ((ch ^ (r&7))<<4));
                }
                #pragma unroll
                for (int nt2 = 0; nt2 < 8; nt2++){
                    uint32_t bh[4];
                    int r = wn2*128 + nt2*16 + (lane&7) + ((lane>>4)&1)*8;
                    int ch = kk*2 + ((lane>>3)&1);
                    LDSM4(bh, Bs + r*128 + ((ch ^ (r&7))<<4));
                    #pragma unroll
                    for (int mt = 0; mt < 2; mt++)
                        #pragma unroll
                        for (int hf = 0; hf < 2; hf++)
                            MMAH(acc2[mt][nt2*2+hf], ah[mt], &bh[hf*2]);
                }
            }
            __syncthreads();
        }
    }

    // ---------- epilogue: + b2 + residual ----------
    #pragma unroll
    for (int mt = 0; mt < 2; mt++){
        size_t R0 = row0 + wm*32 + mt*16 + g;
        #pragma unroll
        for (int nt = 0; nt < 16; nt++){
            int C = wn2*128 + nt*8 + t4*2;
            float* d = acc2[mt][nt];
            float b0v = __ldg(b2v + C), b1vv = __ldg(b2v + C + 1);
            float2 x0 = *(float2*)(g_x2 + R0*256 + C);
            float2 x1 = *(float2*)(g_x2 + (R0+8)*256 + C);
            *(float2*)(outf + R0*256 + C)     = make_float2(d[0]+b0v+x0.x, d[1]+b1vv+x0.y);
            *(float2*)(outf + (R0+8)*256 + C) = make_float2(d[2]+b0v+x1.x, d[3]+b1vv+x1.y);
        }
    }
}

extern "C" void kernel_launch(void* const* d_in, const int* in_sizes, int n_in,
                              void* d_out, int out_size) {
    const float* x   = (const float*)d_in[0];
    const float* rot = (const float*)d_in[1];
    const float* n1g = (const float*)d_in[2];
    const float* n1b = (const float*)d_in[3];
    const float* qw  = (const float*)d_in[4];
    const float* kvw = (const float*)d_in[5];
    const float* n2g = (const float*)d_in[6];
    const float* n2b = (const float*)d_in[7];
    const float* w1  = (const float*)d_in[8];
    const float* b1  = (const float*)d_in[9];
    const float* w2  = (const float*)d_in[10];
    const float* b2  = (const float*)d_in[11];
    float* out = (float*)d_out;

    const int POOL_SM = (4*32*256 + 128)*4;
    const int ASM = 166016;
    const int MSM = 163840;
    cudaFuncSetAttribute(k_pool, cudaFuncAttributeMaxDynamicSharedMemorySize, POOL_SM);
    cudaFuncSetAttribute(k_attn, cudaFuncAttributeMaxDynamicSharedMemorySize, ASM);
    cudaFuncSetAttribute(k_mlp,  cudaFuncAttributeMaxDynamicSharedMemorySize, MSM);

    k_prepw<<<1280, 256>>>(w1, w2);
    k_ln1<<<(NB*NN)/128, 256>>>(x, rot, n1g, n1b);
    k_pool<<<dim3(NCH, NB), 128, POOL_SM>>>();
    k_kv<<<dim3(16, NB), 512>>>(kvw);
    k_prep<<<dim3(NB, 8), 256>>>(qw);
    k_attn<<<(NB*NN)/128, 256, ASM>>>(x, n2g, n2b);
    k_mlp<<<(NB*NN)/128, 256, MSM>>>(b1, b2, out);
}

// round 11
// speedup vs baseline: 7.0859x; 1.0310x over previous
#include <cuda_runtime.h>
#include <cuda_fp16.h>
#include <math.h>
#include <stdint.h>

#define NB 16
#define NN 8192
#define NC 256
#define NM 32
#define NCH 16
#define TOKCH (NN/NCH)

__device__ __half g_xq[NB*NN*NC];
__device__ unsigned int g_bkt[NB*NN];
__device__ float g_poolp[NCH*NB*NM*NC];
__device__ float g_cntp [NCH*NB*NM];
__device__ float g_k[NB*NM*NC];
__device__ float g_v[NB*NM*NC];
__device__ __half g_Aq[NB*NC*NC];
__device__ float g_x2[NB*NN*NC];
__device__ __half g_y[NB*NN*NC];
__device__ __half g_w1hh[1024*256];
__device__ __half g_w2hh[256*1024];

__device__ __forceinline__ uint32_t s2u(const void* p){
    uint32_t a; asm("{ .reg .u64 t; cvta.to.shared.u64 t, %1; cvt.u32.u64 %0, t; }" : "=r"(a) : "l"(p)); return a;
}
#define CPA(dst, src) asm volatile("cp.async.cg.shared.global [%0], [%1], 16;" :: "r"(dst), "l"(src))
#define CPCOMMIT()    asm volatile("cp.async.commit_group;" ::: "memory")
#define CPWAIT1()     asm volatile("cp.async.wait_group 1;" ::: "memory")
#define CPWAIT0()     asm volatile("cp.async.wait_group 0;" ::: "memory")
#define LDSM4(r, a) asm volatile("ldmatrix.sync.aligned.m8n8.x4.shared.b16 {%0,%1,%2,%3}, [%4];" \
    : "=r"((r)[0]), "=r"((r)[1]), "=r"((r)[2]), "=r"((r)[3]) : "r"(a))
#define MMAH(d, a, b) asm volatile( \
    "mma.sync.aligned.m16n8k16.row.col.f32.f16.f16.f32 " \
    "{%0,%1,%2,%3}, {%4,%5,%6,%7}, {%8,%9}, {%0,%1,%2,%3};" \
    : "+f"((d)[0]), "+f"((d)[1]), "+f"((d)[2]), "+f"((d)[3]) \
    : "r"((a)[0]), "r"((a)[1]), "r"((a)[2]), "r"((a)[3]), "r"((b)[0]), "r"((b)[1]))

__device__ __forceinline__ uint32_t pkh(float f0, float f1){
    __half2 h = __floats2half2_rn(f0, f1);
    return *(uint32_t*)&h;
}
__device__ __forceinline__ float geluf(float u){ return 0.5f*u*(1.f + erff(u*0.70710678118654752f)); }
__device__ __forceinline__ float wsum(float v){
    #pragma unroll
    for (int o=16;o;o>>=1) v += __shfl_xor_sync(~0u,v,o);
    return v;
}

// ---- weight transpose: w1 -> fp16 [n][k], w2 -> fp16 [n][k] ----
__global__ void k_prepw(const float* __restrict__ w1, const float* __restrict__ w2){
    int n = blockIdx.x, t = threadIdx.x;
    if (n < 1024){
        float v = w1[(size_t)t*1024 + n];
        g_w1hh[n*256+t] = __float2half(v);
    } else {
        int n2 = n-1024;
        for (int k = t; k < 1024; k += 256){
            float v = w2[(size_t)k*256 + n2];
            g_w2hh[n2*1024+k] = __float2half(v);
        }
    }
}

// ---- LN1 + LSH + fp16 x ----
__global__ __launch_bounds__(256) void k_ln1(const float* __restrict__ x, const float* __restrict__ rot,
                                             const float* __restrict__ g1, const float* __restrict__ b1){
    __shared__ float rT[16*256], sg[256], sb[256];
    int tid = threadIdx.x;
    for (int i = tid; i < 4096; i += 256) rT[(i&15)*256 + (i>>4)] = rot[i];
    sg[tid] = g1[tid]; sb[tid] = b1[tid];
    __syncthreads();
    int w = tid>>5, lane = tid&31;
    int base = blockIdx.x*128 + w*16;
    for (int t0 = 0; t0 < 16; t0++){
        int row = base + t0;
        const float* xr = x + (size_t)row*NC;
        float xv[8], s = 0.f, sq = 0.f;
        #pragma unroll
        for (int j = 0; j < 8; j++){ float v = xr[lane+32*j]; xv[j] = v; s += v; sq += v*v; }
        s = wsum(s); sq = wsum(sq);
        float m = s*(1.f/256.f);
        float rs = rsqrtf(sq*(1.f/256.f) - m*m + 1e-5f);
        float r16[16];
        #pragma unroll
        for (int i = 0; i < 16; i++) r16[i] = 0.f;
        #pragma unroll
        for (int j = 0; j < 8; j++){
            int c = lane + 32*j;
            float xn = (xv[j]-m)*rs*sg[c] + sb[c];
            g_xq[(size_t)row*NC + c] = __float2half(xn);
            #pragma unroll
            for (int i = 0; i < 16; i++) r16[i] += xn * rT[i*256 + c];
        }
        #pragma unroll
        for (int i = 0; i < 16; i++){
            #pragma unroll
            for (int o = 16; o; o >>= 1) r16[i] += __shfl_xor_sync(~0u, r16[i], o);
        }
        if (!lane){
            unsigned pkb = 0;
            #pragma unroll
            for (int h = 0; h < 4; h++){
                float best = r16[h*4]; int bi = 0;
                #pragma unroll
                for (int i = 1; i < 8; i++){
                    float v = (i < 4) ? r16[h*4+i] : -r16[h*4+i-4];
                    if (v > best){ best = v; bi = i; }
                }
                pkb |= (unsigned)bi << (8*h);
            }
            g_bkt[row] = pkb;
        }
    }
}

// ---- pooling (reads fp16 x) ----
__global__ __launch_bounds__(128) void k_pool(){
    extern __shared__ float sp[];
    float* scnt = sp + 4*32*256;
    int tid = threadIdx.x, w = tid>>5, lane = tid&31;
    int ch = blockIdx.x, b = blockIdx.y;
    for (int i = tid; i < 4*32*256; i += 128) sp[i] = 0.f;
    if (tid < 128) scnt[tid] = 0.f;
    __syncthreads();
    float* myp = sp + w*32*256;
    float* myc = scnt + w*32;
    int n0 = ch*TOKCH + w*(TOKCH/4);
    for (int it = 0; it < TOKCH/4; it++){
        int row = b*NN + n0 + it;
        unsigned pkb = g_bkt[row];
        const __half* xhp = g_xq + (size_t)row*NC;
        float xv[8];
        #pragma unroll
        for (int j = 0; j < 8; j++) xv[j] = __half2float(xhp[lane+32*j]);
        #pragma unroll
        for (int h = 0; h < 4; h++){
            int hm = h*8 + ((pkb >> (8*h)) & 255);
            float* dst = myp + hm*256;
            #pragma unroll
            for (int j = 0; j < 8; j++) dst[lane+32*j] += xv[j];
            if (!lane) myc[hm] += 1.f;
        }
    }
    __syncthreads();
    float* op = g_poolp + (size_t)(ch*NB + b)*NM*NC;
    for (int i = tid; i < NM*NC; i += 128)
        op[i] = sp[i] + sp[8192+i] + sp[16384+i] + sp[24576+i];
    if (tid < NM)
        g_cntp[(ch*NB+b)*NM + tid] = scnt[tid] + scnt[32+tid] + scnt[64+tid] + scnt[96+tid];
}

// ---- pooled KV projection ----
__global__ __launch_bounds__(512) void k_kv(const float* __restrict__ kvw){
    __shared__ float rp[2*256];
    __shared__ float scn[2];
    int tid = threadIdx.x;
    int mg = blockIdx.x, b = blockIdx.y;
    if (tid < 2){
        float c = 0.f;
        for (int ch = 0; ch < NCH; ch++) c += g_cntp[(ch*NB+b)*NM + mg*2 + tid];
        scn[tid] = c;
    }
    __syncthreads();
    if (tid < 512){
        int mi = tid>>8;
        float s = 0.f;
        #pragma unroll 4
        for (int ch = 0; ch < NCH; ch++)
            s += g_poolp[((size_t)(ch*NB+b)*NM + mg*2 + mi)*NC + (tid&255)];
        rp[tid] = s / (scn[mi] + 1e-20f);
    }
    __syncthreads();
    int j = tid;
    float a0 = 0.f, a1 = 0.f;
    #pragma unroll 8
    for (int c = 0; c < 256; c++){
        float wv = __ldg(kvw + (size_t)c*512 + j);
        a0 = fmaf(rp[c], wv, a0);
        a1 = fmaf(rp[256+c], wv, a1);
    }
    float* dst = (j < 256) ? g_k : g_v;
    int jj = j & 255;
    dst[((size_t)b*NM + mg*2 + 0)*NC + jj] = a0;
    dst[((size_t)b*NM + mg*2 + 1)*NC + jj] = a1;
}

// ---- A^T = scale*(q_w@k^T)^T -> fp16 ----
__global__ __launch_bounds__(256) void k_prep(const float* __restrict__ qw){
    __shared__ float ks[32*32];
    int c = threadIdx.x, b = blockIdx.x, h = blockIdx.y;
    for (int i = c; i < 1024; i += 256)
        ks[i] = g_k[((size_t)b*NM + (i>>5))*NC + h*32 + (i&31)];
    __syncthreads();
    float q[32];
    const float* qp = qw + (size_t)c*NC + h*32;
    #pragma unroll
    for (int i = 0; i < 32; i++) q[i] = qp[i];
    for (int m = 0; m < 32; m++){
        float acc = 0.f;
        #pragma unroll
        for (int i = 0; i < 32; i++) acc = fmaf(q[i], ks[m*32+i], acc);
        g_Aq[((size_t)b*256 + h*32 + m)*256 + c] = __float2half(acc*0.17677669529663689f);
    }
}

// ---- fused: logits fp16 HMMA GEMM + softmax + PV + residual + LN2 -> fp16 y ----
__global__ __launch_bounds__(256,1) void k_attn(const float* __restrict__ x,
                                                const float* __restrict__ g2, const float* __restrict__ b2){
    extern __shared__ char dsm[];
    uint32_t sb = s2u(dsm);
    float* Ls   = (float*)dsm;
    float* v_s  = (float*)(dsm + 133120);
    float* cnt_s= (float*)(dsm + 165888);
    int tid = threadIdx.x, w = tid>>5, lane = tid&31;
    size_t row0 = (size_t)blockIdx.x*128;
    int b = blockIdx.x >> 6;
    const __half* Aq = g_Aq + (size_t)b*65536;

    for (int i = tid; i < 8192; i += 256) v_s[i] = g_v[(size_t)b*8192 + i];
    if (tid < 32){
        float c = 0.f;
        for (int ch = 0; ch < NCH; ch++) c += g_cntp[(ch*NB+b)*NM + tid];
        cnt_s[tid] = c;
    }

    int wm = w&3, wn = w>>2;
    float acc[2][16][4];
    #pragma unroll
    for (int i = 0; i < 2; i++)
        #pragma unroll
        for (int j = 0; j < 16; j++)
            #pragma unroll
            for (int q = 0; q < 4; q++) acc[i][j][q] = 0.f;

    // stage: A 128x64 half (16KB) + B 256x64 half (32KB) = 48KB
    auto load_stage = [&](int kt, int s){
        uint32_t base = sb + s*49152;
        #pragma unroll
        for (int it = 0; it < 12; it++){
            int i = tid + it*256;
            const __half* src; uint32_t dst;
            if (i < 1024){
                int r = i>>3, c = i&7;
                src = g_xq + (row0 + r)*NC + kt*64 + c*8;
                dst = base + r*128 + ((c ^ (r&7))<<4);
            } else {
                int jx = i - 1024;
                int r = jx>>3, c = jx&7;
                src = Aq + (size_t)r*NC + kt*64 + c*8;
                dst = base + 16384 + r*128 + ((c ^ (r&7))<<4);
            }
            CPA(dst, src);
        }
        CPCOMMIT();
    };

    load_stage(0, 0);
    for (int kt = 0; kt < 4; kt++){
        int s = kt & 1;
        if (kt+1 < 4){ load_stage(kt+1, s^1); CPWAIT1(); }
        else CPWAIT0();
        __syncthreads();
        uint32_t As = sb + s*49152;
        uint32_t Bs = As + 16384;
        #pragma unroll
        for (int kk = 0; kk < 4; kk++){
            uint32_t ah[2][4];
            #pragma unroll
            for (int mt = 0; mt < 2; mt++){
                int r = wm*32 + mt*16 + (lane&15);
                int ch = kk*2 + ((lane>>4)&1);
                LDSM4(ah[mt], As + r*128 + ((ch ^ (r&7))<<4));
            }
            #pragma unroll
            for (int nt2 = 0; nt2 < 8; nt2++){
                uint32_t bh[4];
                int r = wn*128 + nt2*16 + (lane&7) + ((lane>>4)&1)*8;
                int ch = kk*2 + ((lane>>3)&1);
                LDSM4(bh, Bs + r*128 + ((ch ^ (r&7))<<4));
                #pragma unroll
                for (int mt = 0; mt < 2; mt++)
                    #pragma unroll
                    for (int hf = 0; hf < 2; hf++)
                        MMAH(acc[mt][nt2*2+hf], ah[mt], &bh[hf*2]);
            }
        }
        __syncthreads();
    }

    int g = lane>>2, t4 = lane&3;
    #pragma unroll
    for (int mt = 0; mt < 2; mt++){
        int R = wm*32 + mt*16 + g;
        #pragma unroll
        for (int nt = 0; nt < 16; nt++){
            int C = wn*128 + nt*8 + t4*2;
            float* d = acc[mt][nt];
            *(float2*)(Ls + R*260 + C)     = make_float2(d[0], d[1]);
            *(float2*)(Ls + (R+8)*260 + C) = make_float2(d[2], d[3]);
        }
    }
    __syncthreads();

    float g2r[8], b2r[8];
    #pragma unroll
    for (int j = 0; j < 8; j++){ g2r[j] = g2[j*32+lane]; b2r[j] = b2[j*32+lane]; }
    bool valid = cnt_s[lane] >= 1.f;
    for (int t = 0; t < 16; t++){
        int rloc = w*16 + t;
        size_t row = row0 + rloc;
        float out[8];
        #pragma unroll
        for (int j = 0; j < 8; j++){
            float l = Ls[rloc*260 + j*32 + lane];
            float mxv = valid ? l : -3.0e38f;
            #pragma unroll
            for (int o = 16; o; o >>= 1) mxv = fmaxf(mxv, __shfl_xor_sync(~0u, mxv, o));
            float e = valid ? expf(l - mxv) : 0.f;
            float s = wsum(e);
            float p = e / s;
            float accv = 0.f;
            #pragma unroll
            for (int m = 0; m < 32; m++){
                float pm = __shfl_sync(~0u, p, m);
                accv = fmaf(pm, v_s[m*256 + j*32 + lane], accv);
            }
            out[j] = accv;
        }
        const float* xr = x + row*256;
        float x2v[8], s = 0.f, sq = 0.f;
        #pragma unroll
        for (int j = 0; j < 8; j++){
            float v = xr[j*32+lane] + out[j];
            x2v[j] = v; s += v; sq += v*v;
        }
        s = wsum(s); sq = wsum(sq);
        float mu = s*(1.f/256.f);
        float rs = rsqrtf(sq*(1.f/256.f) - mu*mu + 1e-5f);
        #pragma unroll
        for (int j = 0; j < 8; j++){
            int c = j*32 + lane;
            size_t o = row*256 + c;
            g_x2[o] = x2v[j];
            g_y[o] = __float2half((x2v[j]-mu)*rs*g2r[j] + b2r[j]);
        }
    }
}

// ---- fused MLP: y(128x256) -> h chunks (smem) -> out(128x256) + bias + residual ----
__global__ __launch_bounds__(256,1) void k_mlp(const float* __restrict__ b1v,
                                               const float* __restrict__ b2v,
                                               float* __restrict__ outf){
    extern __shared__ char dsm[];
    uint32_t sb = s2u(dsm);
    uint32_t ysb = sb, wbb = sb + 65536, hbb = sb + 131072;
    int tid = threadIdx.x, w = tid>>5, lane = tid&31;
    size_t row0 = (size_t)blockIdx.x*128;
    int wm = w&3;
    int wn1 = w>>2;
    int wn2 = w>>2;

    #pragma unroll
    for (int it = 0; it < 16; it++){
        int i = tid + it*256;
        int kt = i>>10, rem = i&1023;
        int r = rem>>3, c = rem&7;
        const __half* src = g_y + (row0 + r)*256 + kt*64 + c*8;
        uint32_t dst = ysb + kt*16384 + r*128 + ((c ^ (r&7))<<4);
        CPA(dst, src);
    }
    CPCOMMIT();
    CPWAIT0();
    __syncthreads();

    float acc2[2][16][4];
    #pragma unroll
    for (int i = 0; i < 2; i++)
        #pragma unroll
        for (int j = 0; j < 16; j++)
            #pragma unroll
            for (int q = 0; q < 4; q++) acc2[i][j][q] = 0.f;

    auto load_w1 = [&](int nc, int kt, int s){
        uint32_t base = wbb + s*16384;
        #pragma unroll
        for (int it = 0; it < 4; it++){
            int i = tid + it*256;
            int r = i>>3, c = i&7;
            const __half* src = g_w1hh + (size_t)(nc*128 + r)*256 + kt*64 + c*8;
            uint32_t dst = base + r*128 + ((c ^ (r&7))<<4);
            CPA(dst, src);
        }
        CPCOMMIT();
    };
    auto load_w2 = [&](int nc, int ks, int s){
        uint32_t base = wbb + s*32768;
        #pragma unroll
        for (int it = 0; it < 8; it++){
            int i = tid + it*256;
            int r = i>>3, c = i&7;
            const __half* src = g_w2hh + (size_t)r*1024 + nc*128 + ks*64 + c*8;
            uint32_t dst = base + r*128 + ((c ^ (r&7))<<4);
            CPA(dst, src);
        }
        CPCOMMIT();
    };

    int g = lane>>2, t4 = lane&3;

    for (int nc = 0; nc < 8; nc++){
        float acc1[2][8][4];
        #pragma unroll
        for (int i = 0; i < 2; i++)
            #pragma unroll
            for (int j = 0; j < 8; j++)
                #pragma unroll
                for (int q = 0; q < 4; q++) acc1[i][j][q] = 0.f;

        load_w1(nc, 0, 0);
        for (int kt = 0; kt < 4; kt++){
            int s = kt & 1;
            if (kt+1 < 4){ load_w1(nc, kt+1, s^1); CPWAIT1(); }
            else CPWAIT0();
            __syncthreads();
            uint32_t As = ysb + kt*16384;
            uint32_t Bs = wbb + s*16384;
            #pragma unroll
            for (int kk = 0; kk < 4; kk++){
                uint32_t ah[2][4], bhv[4][4];
                #pragma unroll
                for (int mt = 0; mt < 2; mt++){
                    int r = wm*32 + mt*16 + (lane&15);
                    int ch = kk*2 + ((lane>>4)&1);
                    LDSM4(ah[mt], As + r*128 + ((ch ^ (r&7))<<4));
                }
                #pragma unroll
                for (int nt2 = 0; nt2 < 4; nt2++){
                    int r = wn1*64 + nt2*16 + (lane&7) + ((lane>>4)&1)*8;
                    int ch = kk*2 + ((lane>>3)&1);
                    LDSM4(bhv[nt2], Bs + r*128 + ((ch ^ (r&7))<<4));
                }
                #pragma unroll
                for (int mt = 0; mt < 2; mt++)
                    #pragma unroll
                    for (int nt = 0; nt < 8; nt++)
                        MMAH(acc1[mt][nt], ah[mt], &bhv[nt>>1][(nt&1)*2]);
            }
            __syncthreads();
        }

        #pragma unroll
        for (int mt = 0; mt < 2; mt++){
            int R = wm*32 + mt*16 + g;
            #pragma unroll
            for (int nt = 0; nt < 8; nt++){
                int cl = wn1*64 + nt*8 + t4*2;
                int Cg = nc*128 + cl;
                float b0v = __ldg(b1v + Cg), b1vv = __ldg(b1v + Cg + 1);
                float* d = acc1[mt][nt];
                uint32_t base = hbb + wn1*16384 + ((nt ^ (R&7))<<4) + t4*4;
                uint32_t base8 = hbb + wn1*16384 + ((nt ^ ((R+8)&7))<<4) + t4*4;
                *(uint32_t*)(dsm + (base  - sb) + R*128)     = pkh(geluf(d[0]+b0v), geluf(d[1]+b1vv));
                *(uint32_t*)(dsm + (base8 - sb) + (R+8)*128) = pkh(geluf(d[2]+b0v), geluf(d[3]+b1vv));
            }
        }
        __syncthreads();

        load_w2(nc, 0, 0);
        for (int ks = 0; ks < 2; ks++){
            int s = ks & 1;
            if (ks+1 < 2){ load_w2(nc, ks+1, s^1); CPWAIT1(); }
            else CPWAIT0();
            __syncthreads();
            uint32_t As = hbb + ks*16384;
            uint32_t Bs = wbb + s*32768;
            #pragma unroll
            for (int kk = 0; kk < 4; kk++){
                uint32_t ah[2][4];
                #pragma unroll
                for (int mt = 0; mt < 2; mt++){
                    int r = wm*32 + mt*16 + (lane&15);
                    int ch = kk*2 + ((lane>>4)&1);
                    LDSM4(ah[mt], As + r*128 + ((ch ^ (r&7))<<4));
                }
                #pragma unroll
                for (int nt2 = 0; nt2 < 8; nt2++){
                    uint32_t bh[4];
                    int r = wn2*128 + nt2*16 + (lane&7) + ((lane>>4)&1)*8;
                    int ch = kk*2 + ((lane>>3)&1);
                    LDSM4(bh, Bs + r*128 + ((ch ^ (r&7))<<4));
                    #pragma unroll
                    for (int mt = 0; mt < 2; mt++)
                        #pragma unroll
                        for (int hf = 0; hf < 2; hf++)
                            MMAH(acc2[mt][nt2*2+hf], ah[mt], &bh[hf*2]);
                }
            }
            __syncthreads();
        }
    }

    #pragma unroll
    for (int mt = 0; mt < 2; mt++){
        size_t R0 = row0 + wm*32 + mt*16 + g;
        #pragma unroll
        for (int nt = 0; nt < 16; nt++){
            int C = wn2*128 + nt*8 + t4*2;
            float* d = acc2[mt][nt];
            float b0v = __ldg(b2v + C), b1vv = __ldg(b2v + C + 1);
            float2 x0 = *(float2*)(g_x2 + R0*256 + C);
            float2 x1 = *(float2*)(g_x2 + (R0+8)*256 + C);
            *(float2*)(outf + R0*256 + C)     = make_float2(d[0]+b0v+x0.x, d[1]+b1vv+x0.y);
            *(float2*)(outf + (R0+8)*256 + C) = make_float2(d[2]+b0v+x1.x, d[3]+b1vv+x1.y);
        }
    }
}

extern "C" void kernel_launch(void* const* d_in, const int* in_sizes, int n_in,
                              void* d_out, int out_size) {
    const float* x   = (const float*)d_in[0];
    const float* rot = (const float*)d_in[1];
    const float* n1g = (const float*)d_in[2];
    const float* n1b = (const float*)d_in[3];
    const float* qw  = (const float*)d_in[4];
    const float* kvw = (const float*)d_in[5];
    const float* n2g = (const float*)d_in[6];
    const float* n2b = (const float*)d_in[7];
    const float* w1  = (const float*)d_in[8];
    const float* b1  = (const float*)d_in[9];
    const float* w2  = (const float*)d_in[10];
    const float* b2  = (const float*)d_in[11];
    float* out = (float*)d_out;

    const int POOL_SM = (4*32*256 + 128)*4;
    const int ASM = 166016;
    const int MSM = 163840;
    cudaFuncSetAttribute(k_pool, cudaFuncAttributeMaxDynamicSharedMemorySize, POOL_SM);
    cudaFuncSetAttribute(k_attn, cudaFuncAttributeMaxDynamicSharedMemorySize, ASM);
    cudaFuncSetAttribute(k_mlp,  cudaFuncAttributeMaxDynamicSharedMemorySize, MSM);

    k_prepw<<<1280, 256>>>(w1, w2);
    k_ln1<<<(NB*NN)/128, 256>>>(x, rot, n1g, n1b);
    k_pool<<<dim3(NCH, NB), 128, POOL_SM>>>();
    k_kv<<<dim3(16, NB), 512>>>(kvw);
    k_prep<<<dim3(NB, 8), 256>>>(qw);
    k_attn<<<(NB*NN)/128, 256, ASM>>>(x, n2g, n2b);
    k_mlp<<<(NB*NN)/128, 256, MSM>>>(b1, b2, out);
}

// round 12
// speedup vs baseline: 7.4359x; 1.0494x over previous
#include <cuda_runtime.h>
#include <cuda_fp16.h>
#include <math.h>
#include <stdint.h>

#define NB 16
#define NN 8192
#define NC 256
#define NM 32
#define NCH 16
#define TOKCH (NN/NCH)

__device__ __half g_xq[NB*NN*NC];
__device__ unsigned int g_bkt[NB*NN];
__device__ float g_poolp[NCH*NB*NM*NC];
__device__ float g_cntp [NCH*NB*NM];
__device__ float g_k[NB*NM*NC];
__device__ float g_v[NB*NM*NC];
__device__ __half g_Aq[NB*NC*NC];
__device__ float g_mu[NB*NN];
__device__ float g_sg[NB*NN];
__device__ __half g_y[NB*NN*NC];
__device__ __half g_w1hh[1024*256];
__device__ __half g_w2hh[256*1024];

__device__ __forceinline__ uint32_t s2u(const void* p){
    uint32_t a; asm("{ .reg .u64 t; cvta.to.shared.u64 t, %1; cvt.u32.u64 %0, t; }" : "=r"(a) : "l"(p)); return a;
}
#define CPA(dst, src) asm volatile("cp.async.cg.shared.global [%0], [%1], 16;" :: "r"(dst), "l"(src))
#define CPCOMMIT()    asm volatile("cp.async.commit_group;" ::: "memory")
#define CPWAIT1()     asm volatile("cp.async.wait_group 1;" ::: "memory")
#define CPWAIT0()     asm volatile("cp.async.wait_group 0;" ::: "memory")
#define LDSM4(r, a) asm volatile("ldmatrix.sync.aligned.m8n8.x4.shared.b16 {%0,%1,%2,%3}, [%4];" \
    : "=r"((r)[0]), "=r"((r)[1]), "=r"((r)[2]), "=r"((r)[3]) : "r"(a))
#define MMAH(d, a, b) asm volatile( \
    "mma.sync.aligned.m16n8k16.row.col.f32.f16.f16.f32 " \
    "{%0,%1,%2,%3}, {%4,%5,%6,%7}, {%8,%9}, {%0,%1,%2,%3};" \
    : "+f"((d)[0]), "+f"((d)[1]), "+f"((d)[2]), "+f"((d)[3]) \
    : "r"((a)[0]), "r"((a)[1]), "r"((a)[2]), "r"((a)[3]), "r"((b)[0]), "r"((b)[1]))

__device__ __forceinline__ uint32_t pkh(float f0, float f1){
    __half2 h = __floats2half2_rn(f0, f1);
    return *(uint32_t*)&h;
}
__device__ __forceinline__ float geluf(float u){ return 0.5f*u*(1.f + erff(u*0.70710678118654752f)); }
__device__ __forceinline__ float wsum(float v){
    #pragma unroll
    for (int o=16;o;o>>=1) v += __shfl_xor_sync(~0u,v,o);
    return v;
}

// ---- weight transpose: w1 -> fp16 [n][k], w2 -> fp16 [n][k] ----
__global__ void k_prepw(const float* __restrict__ w1, const float* __restrict__ w2){
    int n = blockIdx.x, t = threadIdx.x;
    if (n < 1024){
        float v = w1[(size_t)t*1024 + n];
        g_w1hh[n*256+t] = __float2half(v);
    } else {
        int n2 = n-1024;
        for (int k = t; k < 1024; k += 256){
            float v = w2[(size_t)k*256 + n2];
            g_w2hh[n2*1024+k] = __float2half(v);
        }
    }
}

// ---- LN1 + LSH + fp16 x ----
__global__ __launch_bounds__(256) void k_ln1(const float* __restrict__ x, const float* __restrict__ rot,
                                             const float* __restrict__ g1, const float* __restrict__ b1){
    __shared__ float rT[16*256], sg[256], sb[256];
    int tid = threadIdx.x;
    for (int i = tid; i < 4096; i += 256) rT[(i&15)*256 + (i>>4)] = rot[i];
    sg[tid] = g1[tid]; sb[tid] = b1[tid];
    __syncthreads();
    int w = tid>>5, lane = tid&31;
    int base = blockIdx.x*128 + w*16;
    for (int t0 = 0; t0 < 16; t0++){
        int row = base + t0;
        const float* xr = x + (size_t)row*NC;
        float xv[8], s = 0.f, sq = 0.f;
        #pragma unroll
        for (int j = 0; j < 8; j++){ float v = xr[lane+32*j]; xv[j] = v; s += v; sq += v*v; }
        s = wsum(s); sq = wsum(sq);
        float m = s*(1.f/256.f);
        float rs = rsqrtf(sq*(1.f/256.f) - m*m + 1e-5f);
        float r16[16];
        #pragma unroll
        for (int i = 0; i < 16; i++) r16[i] = 0.f;
        #pragma unroll
        for (int j = 0; j < 8; j++){
            int c = lane + 32*j;
            float xn = (xv[j]-m)*rs*sg[c] + sb[c];
            g_xq[(size_t)row*NC + c] = __float2half(xn);
            #pragma unroll
            for (int i = 0; i < 16; i++) r16[i] += xn * rT[i*256 + c];
        }
        #pragma unroll
        for (int i = 0; i < 16; i++){
            #pragma unroll
            for (int o = 16; o; o >>= 1) r16[i] += __shfl_xor_sync(~0u, r16[i], o);
        }
        if (!lane){
            unsigned pkb = 0;
            #pragma unroll
            for (int h = 0; h < 4; h++){
                float best = r16[h*4]; int bi = 0;
                #pragma unroll
                for (int i = 1; i < 8; i++){
                    float v = (i < 4) ? r16[h*4+i] : -r16[h*4+i-4];
                    if (v > best){ best = v; bi = i; }
                }
                pkb |= (unsigned)bi << (8*h);
            }
            g_bkt[row] = pkb;
        }
    }
}

// ---- pooling (reads fp16 x) ----
__global__ __launch_bounds__(128) void k_pool(){
    extern __shared__ float sp[];
    float* scnt = sp + 4*32*256;
    int tid = threadIdx.x, w = tid>>5, lane = tid&31;
    int ch = blockIdx.x, b = blockIdx.y;
    for (int i = tid; i < 4*32*256; i += 128) sp[i] = 0.f;
    if (tid < 128) scnt[tid] = 0.f;
    __syncthreads();
    float* myp = sp + w*32*256;
    float* myc = scnt + w*32;
    int n0 = ch*TOKCH + w*(TOKCH/4);
    for (int it = 0; it < TOKCH/4; it++){
        int row = b*NN + n0 + it;
        unsigned pkb = g_bkt[row];
        const __half* xhp = g_xq + (size_t)row*NC;
        float xv[8];
        #pragma unroll
        for (int j = 0; j < 8; j++) xv[j] = __half2float(xhp[lane+32*j]);
        #pragma unroll
        for (int h = 0; h < 4; h++){
            int hm = h*8 + ((pkb >> (8*h)) & 255);
            float* dst = myp + hm*256;
            #pragma unroll
            for (int j = 0; j < 8; j++) dst[lane+32*j] += xv[j];
            if (!lane) myc[hm] += 1.f;
        }
    }
    __syncthreads();
    float* op = g_poolp + (size_t)(ch*NB + b)*NM*NC;
    for (int i = tid; i < NM*NC; i += 128)
        op[i] = sp[i] + sp[8192+i] + sp[16384+i] + sp[24576+i];
    if (tid < NM)
        g_cntp[(ch*NB+b)*NM + tid] = scnt[tid] + scnt[32+tid] + scnt[64+tid] + scnt[96+tid];
}

// ---- pooled KV projection ----
__global__ __launch_bounds__(512) void k_kv(const float* __restrict__ kvw){
    __shared__ float rp[2*256];
    __shared__ float scn[2];
    int tid = threadIdx.x;
    int mg = blockIdx.x, b = blockIdx.y;
    if (tid < 2){
        float c = 0.f;
        for (int ch = 0; ch < NCH; ch++) c += g_cntp[(ch*NB+b)*NM + mg*2 + tid];
        scn[tid] = c;
    }
    __syncthreads();
    if (tid < 512){
        int mi = tid>>8;
        float s = 0.f;
        #pragma unroll 4
        for (int ch = 0; ch < NCH; ch++)
            s += g_poolp[((size_t)(ch*NB+b)*NM + mg*2 + mi)*NC + (tid&255)];
        rp[tid] = s / (scn[mi] + 1e-20f);
    }
    __syncthreads();
    int j = tid;
    float a0 = 0.f, a1 = 0.f;
    #pragma unroll 8
    for (int c = 0; c < 256; c++){
        float wv = __ldg(kvw + (size_t)c*512 + j);
        a0 = fmaf(rp[c], wv, a0);
        a1 = fmaf(rp[256+c], wv, a1);
    }
    float* dst = (j < 256) ? g_k : g_v;
    int jj = j & 255;
    dst[((size_t)b*NM + mg*2 + 0)*NC + jj] = a0;
    dst[((size_t)b*NM + mg*2 + 1)*NC + jj] = a1;
}

// ---- A^T = scale*(q_w@k^T)^T -> fp16 ----
__global__ __launch_bounds__(256) void k_prep(const float* __restrict__ qw){
    __shared__ float ks[32*32];
    int c = threadIdx.x, b = blockIdx.x, h = blockIdx.y;
    for (int i = c; i < 1024; i += 256)
        ks[i] = g_k[((size_t)b*NM + (i>>5))*NC + h*32 + (i&31)];
    __syncthreads();
    float q[32];
    const float* qp = qw + (size_t)c*NC + h*32;
    #pragma unroll
    for (int i = 0; i < 32; i++) q[i] = qp[i];
    for (int m = 0; m < 32; m++){
        float acc = 0.f;
        #pragma unroll
        for (int i = 0; i < 32; i++) acc = fmaf(q[i], ks[m*32+i], acc);
        g_Aq[((size_t)b*256 + h*32 + m)*256 + c] = __float2half(acc*0.17677669529663689f);
    }
}

// ---- fused: logits fp16 HMMA GEMM + softmax + PV + residual + LN2 -> fp16 y (+ mu/sigma) ----
__global__ __launch_bounds__(256,1) void k_attn(const float* __restrict__ x,
                                                const float* __restrict__ g2, const float* __restrict__ b2){
    extern __shared__ char dsm[];
    uint32_t sb = s2u(dsm);
    float* Ls   = (float*)dsm;
    float* v_s  = (float*)(dsm + 133120);
    float* cnt_s= (float*)(dsm + 165888);
    int tid = threadIdx.x, w = tid>>5, lane = tid&31;
    size_t row0 = (size_t)blockIdx.x*128;
    int b = blockIdx.x >> 6;
    const __half* Aq = g_Aq + (size_t)b*65536;

    for (int i = tid; i < 8192; i += 256) v_s[i] = g_v[(size_t)b*8192 + i];
    if (tid < 32){
        float c = 0.f;
        for (int ch = 0; ch < NCH; ch++) c += g_cntp[(ch*NB+b)*NM + tid];
        cnt_s[tid] = c;
    }

    int wm = w&3, wn = w>>2;
    float acc[2][16][4];
    #pragma unroll
    for (int i = 0; i < 2; i++)
        #pragma unroll
        for (int j = 0; j < 16; j++)
            #pragma unroll
            for (int q = 0; q < 4; q++) acc[i][j][q] = 0.f;

    auto load_stage = [&](int kt, int s){
        uint32_t base = sb + s*49152;
        #pragma unroll
        for (int it = 0; it < 12; it++){
            int i = tid + it*256;
            const __half* src; uint32_t dst;
            if (i < 1024){
                int r = i>>3, c = i&7;
                src = g_xq + (row0 + r)*NC + kt*64 + c*8;
                dst = base + r*128 + ((c ^ (r&7))<<4);
            } else {
                int jx = i - 1024;
                int r = jx>>3, c = jx&7;
                src = Aq + (size_t)r*NC + kt*64 + c*8;
                dst = base + 16384 + r*128 + ((c ^ (r&7))<<4);
            }
            CPA(dst, src);
        }
        CPCOMMIT();
    };

    load_stage(0, 0);
    for (int kt = 0; kt < 4; kt++){
        int s = kt & 1;
        if (kt+1 < 4){ load_stage(kt+1, s^1); CPWAIT1(); }
        else CPWAIT0();
        __syncthreads();
        uint32_t As = sb + s*49152;
        uint32_t Bs = As + 16384;
        #pragma unroll
        for (int kk = 0; kk < 4; kk++){
            uint32_t ah[2][4];
            #pragma unroll
            for (int mt = 0; mt < 2; mt++){
                int r = wm*32 + mt*16 + (lane&15);
                int ch = kk*2 + ((lane>>4)&1);
                LDSM4(ah[mt], As + r*128 + ((ch ^ (r&7))<<4));
            }
            #pragma unroll
            for (int nt2 = 0; nt2 < 8; nt2++){
                uint32_t bh[4];
                int r = wn*128 + nt2*16 + (lane&7) + ((lane>>4)&1)*8;
                int ch = kk*2 + ((lane>>3)&1);
                LDSM4(bh, Bs + r*128 + ((ch ^ (r&7))<<4));
                #pragma unroll
                for (int mt = 0; mt < 2; mt++)
                    #pragma unroll
                    for (int hf = 0; hf < 2; hf++)
                        MMAH(acc[mt][nt2*2+hf], ah[mt], &bh[hf*2]);
            }
        }
        __syncthreads();
    }

    int g = lane>>2, t4 = lane&3;
    #pragma unroll
    for (int mt = 0; mt < 2; mt++){
        int R = wm*32 + mt*16 + g;
        #pragma unroll
        for (int nt = 0; nt < 16; nt++){
            int C = wn*128 + nt*8 + t4*2;
            float* d = acc[mt][nt];
            *(float2*)(Ls + R*260 + C)     = make_float2(d[0], d[1]);
            *(float2*)(Ls + (R+8)*260 + C) = make_float2(d[2], d[3]);
        }
    }
    __syncthreads();

    float g2r[8], b2r[8];
    #pragma unroll
    for (int j = 0; j < 8; j++){ g2r[j] = g2[j*32+lane]; b2r[j] = b2[j*32+lane]; }
    bool valid = cnt_s[lane] >= 1.f;
    for (int t = 0; t < 16; t++){
        int rloc = w*16 + t;
        size_t row = row0 + rloc;
        float out[8];
        #pragma unroll
        for (int j = 0; j < 8; j++){
            float l = Ls[rloc*260 + j*32 + lane];
            float mxv = valid ? l : -3.0e38f;
            #pragma unroll
            for (int o = 16; o; o >>= 1) mxv = fmaxf(mxv, __shfl_xor_sync(~0u, mxv, o));
            float e = valid ? expf(l - mxv) : 0.f;
            float s = wsum(e);
            float p = e / s;
            float accv = 0.f;
            #pragma unroll
            for (int m = 0; m < 32; m++){
                float pm = __shfl_sync(~0u, p, m);
                accv = fmaf(pm, v_s[m*256 + j*32 + lane], accv);
            }
            out[j] = accv;
        }
        const float* xr = x + row*256;
        float x2v[8], s = 0.f, sq = 0.f;
        #pragma unroll
        for (int j = 0; j < 8; j++){
            float v = xr[j*32+lane] + out[j];
            x2v[j] = v; s += v; sq += v*v;
        }
        s = wsum(s); sq = wsum(sq);
        float mu = s*(1.f/256.f);
        float rs = rsqrtf(sq*(1.f/256.f) - mu*mu + 1e-5f);
        if (!lane){ g_mu[row] = mu; g_sg[row] = 1.f/rs; }
        #pragma unroll
        for (int j = 0; j < 8; j++){
            int c = j*32 + lane;
            g_y[row*256 + c] = __float2half((x2v[j]-mu)*rs*g2r[j] + b2r[j]);
        }
    }
}

// ---- fused MLP: y -> h chunks (smem) -> out + bias + residual(reconstructed x2) ----
__global__ __launch_bounds__(256,1) void k_mlp(const float* __restrict__ b1v,
                                               const float* __restrict__ b2v,
                                               const float* __restrict__ gamma2,
                                               const float* __restrict__ beta2,
                                               float* __restrict__ outf){
    extern __shared__ char dsm[];
    uint32_t sb = s2u(dsm);
    uint32_t ysb = sb, wbb = sb + 65536, hbb = sb + 131072;
    float* ig2s = (float*)(dsm + 163840);   // 1/gamma2, 256
    float* bt2s = (float*)(dsm + 164864);   // beta2, 256
    int tid = threadIdx.x, w = tid>>5, lane = tid&31;
    size_t row0 = (size_t)blockIdx.x*128;
    int wm = w&3;
    int wn1 = w>>2;
    int wn2 = w>>2;

    ig2s[tid] = 1.f / gamma2[tid];
    bt2s[tid] = beta2[tid];

    #pragma unroll
    for (int it = 0; it < 16; it++){
        int i = tid + it*256;
        int kt = i>>10, rem = i&1023;
        int r = rem>>3, c = rem&7;
        const __half* src = g_y + (row0 + r)*256 + kt*64 + c*8;
        uint32_t dst = ysb + kt*16384 + r*128 + ((c ^ (r&7))<<4);
        CPA(dst, src);
    }
    CPCOMMIT();
    CPWAIT0();
    __syncthreads();

    float acc2[2][16][4];
    #pragma unroll
    for (int i = 0; i < 2; i++)
        #pragma unroll
        for (int j = 0; j < 16; j++)
            #pragma unroll
            for (int q = 0; q < 4; q++) acc2[i][j][q] = 0.f;

    auto load_w1 = [&](int nc, int kt, int s){
        uint32_t base = wbb + s*16384;
        #pragma unroll
        for (int it = 0; it < 4; it++){
            int i = tid + it*256;
            int r = i>>3, c = i&7;
            const __half* src = g_w1hh + (size_t)(nc*128 + r)*256 + kt*64 + c*8;
            uint32_t dst = base + r*128 + ((c ^ (r&7))<<4);
            CPA(dst, src);
        }
        CPCOMMIT();
    };
    auto load_w2 = [&](int nc, int ks, int s){
        uint32_t base = wbb + s*32768;
        #pragma unroll
        for (int it = 0; it < 8; it++){
            int i = tid + it*256;
            int r = i>>3, c = i&7;
            const __half* src = g_w2hh + (size_t)r*1024 + nc*128 + ks*64 + c*8;
            uint32_t dst = base + r*128 + ((c ^ (r&7))<<4);
            CPA(dst, src);
        }
        CPCOMMIT();
    };

    int g = lane>>2, t4 = lane&3;

    for (int nc = 0; nc < 8; nc++){
        float acc1[2][8][4];
        #pragma unroll
        for (int i = 0; i < 2; i++)
            #pragma unroll
            for (int j = 0; j < 8; j++)
                #pragma unroll
                for (int q = 0; q < 4; q++) acc1[i][j][q] = 0.f;

        load_w1(nc, 0, 0);
        for (int kt = 0; kt < 4; kt++){
            int s = kt & 1;
            if (kt+1 < 4){ load_w1(nc, kt+1, s^1); CPWAIT1(); }
            else CPWAIT0();
            __syncthreads();
            uint32_t As = ysb + kt*16384;
            uint32_t Bs = wbb + s*16384;
            #pragma unroll
            for (int kk = 0; kk < 4; kk++){
                uint32_t ah[2][4], bhv[4][4];
                #pragma unroll
                for (int mt = 0; mt < 2; mt++){
                    int r = wm*32 + mt*16 + (lane&15);
                    int ch = kk*2 + ((lane>>4)&1);
                    LDSM4(ah[mt], As + r*128 + ((ch ^ (r&7))<<4));
                }
                #pragma unroll
                for (int nt2 = 0; nt2 < 4; nt2++){
                    int r = wn1*64 + nt2*16 + (lane&7) + ((lane>>4)&1)*8;
                    int ch = kk*2 + ((lane>>3)&1);
                    LDSM4(bhv[nt2], Bs + r*128 + ((ch ^ (r&7))<<4));
                }
                #pragma unroll
                for (int mt = 0; mt < 2; mt++)
                    #pragma unroll
                    for (int nt = 0; nt < 8; nt++)
                        MMAH(acc1[mt][nt], ah[mt], &bhv[nt>>1][(nt&1)*2]);
            }
            __syncthreads();
        }

        #pragma unroll
        for (int mt = 0; mt < 2; mt++){
            int R = wm*32 + mt*16 + g;
            #pragma unroll
            for (int nt = 0; nt < 8; nt++){
                int cl = wn1*64 + nt*8 + t4*2;
                int Cg = nc*128 + cl;
                float b0v = __ldg(b1v + Cg), b1vv = __ldg(b1v + Cg + 1);
                float* d = acc1[mt][nt];
                uint32_t base = hbb + wn1*16384 + ((nt ^ (R&7))<<4) + t4*4;
                uint32_t base8 = hbb + wn1*16384 + ((nt ^ ((R+8)&7))<<4) + t4*4;
                *(uint32_t*)(dsm + (base  - sb) + R*128)     = pkh(geluf(d[0]+b0v), geluf(d[1]+b1vv));
                *(uint32_t*)(dsm + (base8 - sb) + (R+8)*128) = pkh(geluf(d[2]+b0v), geluf(d[3]+b1vv));
            }
        }
        __syncthreads();

        load_w2(nc, 0, 0);
        for (int ks = 0; ks < 2; ks++){
            int s = ks & 1;
            if (ks+1 < 2){ load_w2(nc, ks+1, s^1); CPWAIT1(); }
            else CPWAIT0();
            __syncthreads();
            uint32_t As = hbb + ks*16384;
            uint32_t Bs = wbb + s*32768;
            #pragma unroll
            for (int kk = 0; kk < 4; kk++){
                uint32_t ah[2][4];
                #pragma unroll
                for (int mt = 0; mt < 2; mt++){
                    int r = wm*32 + mt*16 + (lane&15);
                    int ch = kk*2 + ((lane>>4)&1);
                    LDSM4(ah[mt], As + r*128 + ((ch ^ (r&7))<<4));
                }
                #pragma unroll
                for (int nt2 = 0; nt2 < 8; nt2++){
                    uint32_t bh[4];
                    int r = wn2*128 + nt2*16 + (lane&7) + ((lane>>4)&1)*8;
                    int ch = kk*2 + ((lane>>3)&1);
                    LDSM4(bh, Bs + r*128 + ((ch ^ (r&7))<<4));
                    #pragma unroll
                    for (int mt = 0; mt < 2; mt++)
                        #pragma unroll
                        for (int hf = 0; hf < 2; hf++)
                            MMAH(acc2[mt][nt2*2+hf], ah[mt], &bh[hf*2]);
                }
            }
            __syncthreads();
        }
    }

    // epilogue: out = acc2 + b2 + x2, x2 reconstructed from y in smem
    #pragma unroll
    for (int mt = 0; mt < 2; mt++){
        int Rl = wm*32 + mt*16 + g;
        size_t R0 = row0 + Rl;
        float mu0 = g_mu[R0],   sg0 = g_sg[R0];
        float mu8 = g_mu[R0+8], sg8 = g_sg[R0+8];
        #pragma unroll
        for (int nt = 0; nt < 16; nt++){
            int C = wn2*128 + nt*8 + t4*2;
            float* d = acc2[mt][nt];
            float b0v = __ldg(b2v + C), b1vv = __ldg(b2v + C + 1);
            float ig0 = ig2s[C], ig1 = ig2s[C+1];
            float bt0 = bt2s[C], bt1 = bt2s[C+1];
            uint32_t yoff0 = (C>>6)*16384 + Rl*128     + (((((C>>3)&7)) ^ (Rl&7))<<4)     + (C&7)*2;
            uint32_t yoff8 = (C>>6)*16384 + (Rl+8)*128 + (((((C>>3)&7)) ^ ((Rl+8)&7))<<4) + (C&7)*2;
            __half2 y0 = *(__half2*)(dsm + yoff0);
            __half2 y8 = *(__half2*)(dsm + yoff8);
            float x2a = (__half2float(y0.x) - bt0)*ig0*sg0 + mu0;
            float x2b = (__half2float(y0.y) - bt1)*ig1*sg0 + mu0;
            float x2c = (__half2float(y8.x) - bt0)*ig0*sg8 + mu8;
            float x2d = (__half2float(y8.y) - bt1)*ig1*sg8 + mu8;
            *(float2*)(outf + R0*256 + C)     = make_float2(d[0]+b0v+x2a, d[1]+b1vv+x2b);
            *(float2*)(outf + (R0+8)*256 + C) = make_float2(d[2]+b0v+x2c, d[3]+b1vv+x2d);
        }
    }
}

extern "C" void kernel_launch(void* const* d_in, const int* in_sizes, int n_in,
                              void* d_out, int out_size) {
    const float* x   = (const float*)d_in[0];
    const float* rot = (const float*)d_in[1];
    const float* n1g = (const float*)d_in[2];
    const float* n1b = (const float*)d_in[3];
    const float* qw  = (const float*)d_in[4];
    const float* kvw = (const float*)d_in[5];
    const float* n2g = (const float*)d_in[6];
    const float* n2b = (const float*)d_in[7];
    const float* w1  = (const float*)d_in[8];
    const float* b1  = (const float*)d_in[9];
    const float* w2  = (const float*)d_in[10];
    const float* b2  = (const float*)d_in[11];
    float* out = (float*)d_out;

    const int POOL_SM = (4*32*256 + 128)*4;
    const int ASM = 166016;
    const int MSM = 165888;
    cudaFuncSetAttribute(k_pool, cudaFuncAttributeMaxDynamicSharedMemorySize, POOL_SM);
    cudaFuncSetAttribute(k_attn, cudaFuncAttributeMaxDynamicSharedMemorySize, ASM);
    cudaFuncSetAttribute(k_mlp,  cudaFuncAttributeMaxDynamicSharedMemorySize, MSM);

    k_prepw<<<1280, 256>>>(w1, w2);
    k_ln1<<<(NB*NN)/128, 256>>>(x, rot, n1g, n1b);
    k_pool<<<dim3(NCH, NB), 128, POOL_SM>>>();
    k_kv<<<dim3(16, NB), 512>>>(kvw);
    k_prep<<<dim3(NB, 8), 256>>>(qw);
    k_attn<<<(NB*NN)/128, 256, ASM>>>(x, n2g, n2b);
    k_mlp<<<(NB*NN)/128, 256, MSM>>>(b1, b2, n2g, n2b, out);
}

// round 13
// speedup vs baseline: 7.4804x; 1.0060x over previous
#include <cuda_runtime.h>
#include <cuda_fp16.h>
#include <math.h>
#include <stdint.h>

#define NB 16
#define NN 8192
#define NC 256
#define NM 32
#define NCH 16
#define TOKCH (NN/NCH)

__device__ __half g_xq[NB*NN*NC];
__device__ unsigned int g_bkt[NB*NN];
__device__ float g_poolp[NCH*NB*NM*NC];
__device__ float g_cntp [NCH*NB*NM];
__device__ float g_k[NB*NM*NC];
__device__ float g_v[NB*NM*NC];
__device__ __half g_Aq[NB*NC*NC];
__device__ float g_mu[NB*NN];
__device__ float g_sg[NB*NN];
__device__ __half g_y[NB*NN*NC];
__device__ __half g_w1hh[1024*256];
__device__ __half g_w2hh[256*1024];

__device__ __forceinline__ uint32_t s2u(const void* p){
    uint32_t a; asm("{ .reg .u64 t; cvta.to.shared.u64 t, %1; cvt.u32.u64 %0, t; }" : "=r"(a) : "l"(p)); return a;
}
#define CPA(dst, src) asm volatile("cp.async.cg.shared.global [%0], [%1], 16;" :: "r"(dst), "l"(src))
#define CPCOMMIT()    asm volatile("cp.async.commit_group;" ::: "memory")
#define CPWAIT1()     asm volatile("cp.async.wait_group 1;" ::: "memory")
#define CPWAIT0()     asm volatile("cp.async.wait_group 0;" ::: "memory")
#define LDSM4(r, a) asm volatile("ldmatrix.sync.aligned.m8n8.x4.shared.b16 {%0,%1,%2,%3}, [%4];" \
    : "=r"((r)[0]), "=r"((r)[1]), "=r"((r)[2]), "=r"((r)[3]) : "r"(a))
#define MMAH(d, a, b) asm volatile( \
    "mma.sync.aligned.m16n8k16.row.col.f32.f16.f16.f32 " \
    "{%0,%1,%2,%3}, {%4,%5,%6,%7}, {%8,%9}, {%0,%1,%2,%3};" \
    : "+f"((d)[0]), "+f"((d)[1]), "+f"((d)[2]), "+f"((d)[3]) \
    : "r"((a)[0]), "r"((a)[1]), "r"((a)[2]), "r"((a)[3]), "r"((b)[0]), "r"((b)[1]))

__device__ __forceinline__ uint32_t pkh(float f0, float f1){
    __half2 h = __floats2half2_rn(f0, f1);
    return *(uint32_t*)&h;
}
__device__ __forceinline__ float geluf(float u){ return 0.5f*u*(1.f + erff(u*0.70710678118654752f)); }
__device__ __forceinline__ float wsum(float v){
    #pragma unroll
    for (int o=16;o;o>>=1) v += __shfl_xor_sync(~0u,v,o);
    return v;
}

// ---- weight transpose: w1 -> fp16 [n][k], w2 -> fp16 [n][k] ----
__global__ void k_prepw(const float* __restrict__ w1, const float* __restrict__ w2){
    int n = blockIdx.x, t = threadIdx.x;
    if (n < 1024){
        float v = w1[(size_t)t*1024 + n];
        g_w1hh[n*256+t] = __float2half(v);
    } else {
        int n2 = n-1024;
        for (int k = t; k < 1024; k += 256){
            float v = w2[(size_t)k*256 + n2];
            g_w2hh[n2*1024+k] = __float2half(v);
        }
    }
}

// ---- LN1 + LSH + fp16 x ----
__global__ __launch_bounds__(256) void k_ln1(const float* __restrict__ x, const float* __restrict__ rot,
                                             const float* __restrict__ g1, const float* __restrict__ b1){
    __shared__ float rT[16*256], sg[256], sb[256];
    int tid = threadIdx.x;
    for (int i = tid; i < 4096; i += 256) rT[(i&15)*256 + (i>>4)] = rot[i];
    sg[tid] = g1[tid]; sb[tid] = b1[tid];
    __syncthreads();
    int w = tid>>5, lane = tid&31;
    int base = blockIdx.x*128 + w*16;
    for (int t0 = 0; t0 < 16; t0++){
        int row = base + t0;
        const float* xr = x + (size_t)row*NC;
        float xv[8], s = 0.f, sq = 0.f;
        #pragma unroll
        for (int j = 0; j < 8; j++){ float v = xr[lane+32*j]; xv[j] = v; s += v; sq += v*v; }
        s = wsum(s); sq = wsum(sq);
        float m = s*(1.f/256.f);
        float rs = rsqrtf(sq*(1.f/256.f) - m*m + 1e-5f);
        float r16[16];
        #pragma unroll
        for (int i = 0; i < 16; i++) r16[i] = 0.f;
        #pragma unroll
        for (int j = 0; j < 8; j++){
            int c = lane + 32*j;
            float xn = (xv[j]-m)*rs*sg[c] + sb[c];
            g_xq[(size_t)row*NC + c] = __float2half(xn);
            #pragma unroll
            for (int i = 0; i < 16; i++) r16[i] += xn * rT[i*256 + c];
        }
        #pragma unroll
        for (int i = 0; i < 16; i++){
            #pragma unroll
            for (int o = 16; o; o >>= 1) r16[i] += __shfl_xor_sync(~0u, r16[i], o);
        }
        if (!lane){
            unsigned pkb = 0;
            #pragma unroll
            for (int h = 0; h < 4; h++){
                float best = r16[h*4]; int bi = 0;
                #pragma unroll
                for (int i = 1; i < 8; i++){
                    float v = (i < 4) ? r16[h*4+i] : -r16[h*4+i-4];
                    if (v > best){ best = v; bi = i; }
                }
                pkb |= (unsigned)bi << (8*h);
            }
            g_bkt[row] = pkb;
        }
    }
}

// ---- pooling (reads fp16 x) ----
__global__ __launch_bounds__(128) void k_pool(){
    extern __shared__ float sp[];
    float* scnt = sp + 4*32*256;
    int tid = threadIdx.x, w = tid>>5, lane = tid&31;
    int ch = blockIdx.x, b = blockIdx.y;
    for (int i = tid; i < 4*32*256; i += 128) sp[i] = 0.f;
    if (tid < 128) scnt[tid] = 0.f;
    __syncthreads();
    float* myp = sp + w*32*256;
    float* myc = scnt + w*32;
    int n0 = ch*TOKCH + w*(TOKCH/4);
    for (int it = 0; it < TOKCH/4; it++){
        int row = b*NN + n0 + it;
        unsigned pkb = g_bkt[row];
        const __half* xhp = g_xq + (size_t)row*NC;
        float xv[8];
        #pragma unroll
        for (int j = 0; j < 8; j++) xv[j] = __half2float(xhp[lane+32*j]);
        #pragma unroll
        for (int h = 0; h < 4; h++){
            int hm = h*8 + ((pkb >> (8*h)) & 255);
            float* dst = myp + hm*256;
            #pragma unroll
            for (int j = 0; j < 8; j++) dst[lane+32*j] += xv[j];
            if (!lane) myc[hm] += 1.f;
        }
    }
    __syncthreads();
    float* op = g_poolp + (size_t)(ch*NB + b)*NM*NC;
    for (int i = tid; i < NM*NC; i += 128)
        op[i] = sp[i] + sp[8192+i] + sp[16384+i] + sp[24576+i];
    if (tid < NM)
        g_cntp[(ch*NB+b)*NM + tid] = scnt[tid] + scnt[32+tid] + scnt[64+tid] + scnt[96+tid];
}

// ---- pooled KV projection ----
__global__ __launch_bounds__(512) void k_kv(const float* __restrict__ kvw){
    __shared__ float rp[2*256];
    __shared__ float scn[2];
    int tid = threadIdx.x;
    int mg = blockIdx.x, b = blockIdx.y;
    if (tid < 2){
        float c = 0.f;
        for (int ch = 0; ch < NCH; ch++) c += g_cntp[(ch*NB+b)*NM + mg*2 + tid];
        scn[tid] = c;
    }
    __syncthreads();
    if (tid < 512){
        int mi = tid>>8;
        float s = 0.f;
        #pragma unroll 4
        for (int ch = 0; ch < NCH; ch++)
            s += g_poolp[((size_t)(ch*NB+b)*NM + mg*2 + mi)*NC + (tid&255)];
        rp[tid] = s / (scn[mi] + 1e-20f);
    }
    __syncthreads();
    int j = tid;
    float a0 = 0.f, a1 = 0.f;
    #pragma unroll 8
    for (int c = 0; c < 256; c++){
        float wv = __ldg(kvw + (size_t)c*512 + j);
        a0 = fmaf(rp[c], wv, a0);
        a1 = fmaf(rp[256+c], wv, a1);
    }
    float* dst = (j < 256) ? g_k : g_v;
    int jj = j & 255;
    dst[((size_t)b*NM + mg*2 + 0)*NC + jj] = a0;
    dst[((size_t)b*NM + mg*2 + 1)*NC + jj] = a1;
}

// ---- A^T = scale*(q_w@k^T)^T -> fp16 ----
__global__ __launch_bounds__(256) void k_prep(const float* __restrict__ qw){
    __shared__ float ks[32*32];
    int c = threadIdx.x, b = blockIdx.x, h = blockIdx.y;
    for (int i = c; i < 1024; i += 256)
        ks[i] = g_k[((size_t)b*NM + (i>>5))*NC + h*32 + (i&31)];
    __syncthreads();
    float q[32];
    const float* qp = qw + (size_t)c*NC + h*32;
    #pragma unroll
    for (int i = 0; i < 32; i++) q[i] = qp[i];
    for (int m = 0; m < 32; m++){
        float acc = 0.f;
        #pragma unroll
        for (int i = 0; i < 32; i++) acc = fmaf(q[i], ks[m*32+i], acc);
        g_Aq[((size_t)b*256 + h*32 + m)*256 + c] = __float2half(acc*0.17677669529663689f);
    }
}

// ---- fused: logits fp16 HMMA GEMM + softmax + PV + residual + LN2 -> fp16 y (+ mu/sigma) ----
__global__ __launch_bounds__(256,1) void k_attn(const float* __restrict__ x,
                                                const float* __restrict__ g2, const float* __restrict__ b2){
    extern __shared__ char dsm[];
    uint32_t sb = s2u(dsm);
    float* Ls   = (float*)dsm;
    float* v_s  = (float*)(dsm + 133120);
    float* cnt_s= (float*)(dsm + 165888);
    int tid = threadIdx.x, w = tid>>5, lane = tid&31;
    size_t row0 = (size_t)blockIdx.x*128;
    int b = blockIdx.x >> 6;
    const __half* Aq = g_Aq + (size_t)b*65536;

    for (int i = tid; i < 8192; i += 256) v_s[i] = g_v[(size_t)b*8192 + i];
    if (tid < 32){
        float c = 0.f;
        for (int ch = 0; ch < NCH; ch++) c += g_cntp[(ch*NB+b)*NM + tid];
        cnt_s[tid] = c;
    }

    int wm = w&3, wn = w>>2;
    float acc[2][16][4];
    #pragma unroll
    for (int i = 0; i < 2; i++)
        #pragma unroll
        for (int j = 0; j < 16; j++)
            #pragma unroll
            for (int q = 0; q < 4; q++) acc[i][j][q] = 0.f;

    auto load_stage = [&](int kt, int s){
        uint32_t base = sb + s*49152;
        #pragma unroll
        for (int it = 0; it < 12; it++){
            int i = tid + it*256;
            const __half* src; uint32_t dst;
            if (i < 1024){
                int r = i>>3, c = i&7;
                src = g_xq + (row0 + r)*NC + kt*64 + c*8;
                dst = base + r*128 + ((c ^ (r&7))<<4);
            } else {
                int jx = i - 1024;
                int r = jx>>3, c = jx&7;
                src = Aq + (size_t)r*NC + kt*64 + c*8;
                dst = base + 16384 + r*128 + ((c ^ (r&7))<<4);
            }
            CPA(dst, src);
        }
        CPCOMMIT();
    };

    load_stage(0, 0);
    for (int kt = 0; kt < 4; kt++){
        int s = kt & 1;
        if (kt+1 < 4){ load_stage(kt+1, s^1); CPWAIT1(); }
        else CPWAIT0();
        __syncthreads();
        uint32_t As = sb + s*49152;
        uint32_t Bs = As + 16384;
        #pragma unroll
        for (int kk = 0; kk < 4; kk++){
            uint32_t ah[2][4];
            #pragma unroll
            for (int mt = 0; mt < 2; mt++){
                int r = wm*32 + mt*16 + (lane&15);
                int ch = kk*2 + ((lane>>4)&1);
                LDSM4(ah[mt], As + r*128 + ((ch ^ (r&7))<<4));
            }
            #pragma unroll
            for (int nt2 = 0; nt2 < 8; nt2++){
                uint32_t bh[4];
                int r = wn*128 + nt2*16 + (lane&7) + ((lane>>4)&1)*8;
                int ch = kk*2 + ((lane>>3)&1);
                LDSM4(bh, Bs + r*128 + ((ch ^ (r&7))<<4));
                #pragma unroll
                for (int mt = 0; mt < 2; mt++)
                    #pragma unroll
                    for (int hf = 0; hf < 2; hf++)
                        MMAH(acc[mt][nt2*2+hf], ah[mt], &bh[hf*2]);
            }
        }
        __syncthreads();
    }

    int g = lane>>2, t4 = lane&3;
    #pragma unroll
    for (int mt = 0; mt < 2; mt++){
        int R = wm*32 + mt*16 + g;
        #pragma unroll
        for (int nt = 0; nt < 16; nt++){
            int C = wn*128 + nt*8 + t4*2;
            float* d = acc[mt][nt];
            *(float2*)(Ls + R*260 + C)     = make_float2(d[0], d[1]);
            *(float2*)(Ls + (R+8)*260 + C) = make_float2(d[2], d[3]);
        }
    }
    __syncthreads();

    float g2r[8], b2r[8];
    #pragma unroll
    for (int j = 0; j < 8; j++){ g2r[j] = g2[j*32+lane]; b2r[j] = b2[j*32+lane]; }
    bool valid = cnt_s[lane] >= 1.f;
    for (int t = 0; t < 16; t++){
        int rloc = w*16 + t;
        size_t row = row0 + rloc;
        float out[8];
        #pragma unroll
        for (int j = 0; j < 8; j++){
            float l = Ls[rloc*260 + j*32 + lane];
            float mxv = valid ? l : -3.0e38f;
            #pragma unroll
            for (int o = 16; o; o >>= 1) mxv = fmaxf(mxv, __shfl_xor_sync(~0u, mxv, o));
            float e = valid ? expf(l - mxv) : 0.f;
            float s = wsum(e);
            float p = e / s;
            float accv = 0.f;
            #pragma unroll
            for (int m = 0; m < 32; m++){
                float pm = __shfl_sync(~0u, p, m);
                accv = fmaf(pm, v_s[m*256 + j*32 + lane], accv);
            }
            out[j] = accv;
        }
        const float* xr = x + row*256;
        float x2v[8], s = 0.f, sq = 0.f;
        #pragma unroll
        for (int j = 0; j < 8; j++){
            float v = xr[j*32+lane] + out[j];
            x2v[j] = v; s += v; sq += v*v;
        }
        s = wsum(s); sq = wsum(sq);
        float mu = s*(1.f/256.f);
        float rs = rsqrtf(sq*(1.f/256.f) - mu*mu + 1e-5f);
        if (!lane){ g_mu[row] = mu; g_sg[row] = 1.f/rs; }
        #pragma unroll
        for (int j = 0; j < 8; j++){
            int c = j*32 + lane;
            g_y[row*256 + c] = __float2half((x2v[j]-mu)*rs*g2r[j] + b2r[j]);
        }
    }
}

// ---- fused MLP, 64-row tile, 2 CTAs/SM ----
// smem: ys[0,32K) 4 k-chunks of 64x64; wbb[32K,64K) 2 stages 16KB; hbb[64K,80K) 2 k-halves 64x64
__global__ __launch_bounds__(256,2) void k_mlp(const float* __restrict__ b1v,
                                               const float* __restrict__ b2v,
                                               const float* __restrict__ gamma2,
                                               const float* __restrict__ beta2,
                                               float* __restrict__ outf){
    extern __shared__ char dsm[];
    uint32_t sb = s2u(dsm);
    uint32_t ysb = sb, wbb = sb + 32768, hbb = sb + 65536;
    int tid = threadIdx.x, w = tid>>5, lane = tid&31;
    size_t row0 = (size_t)blockIdx.x*64;
    int wm = w&1, wn = w>>1;   // 2 m-groups x 4 n-groups

    // load y tile 64x256 as 4 k-chunks
    #pragma unroll
    for (int it = 0; it < 8; it++){
        int i = tid + it*256;          // 0..2047
        int kt = i>>9, rem = i&511;
        int r = rem>>3, c = rem&7;
        const __half* src = g_y + (row0 + r)*256 + kt*64 + c*8;
        uint32_t dst = ysb + kt*8192 + r*128 + ((c ^ (r&7))<<4);
        CPA(dst, src);
    }
    CPCOMMIT();
    CPWAIT0();
    __syncthreads();

    float acc2[2][8][4];
    #pragma unroll
    for (int i = 0; i < 2; i++)
        #pragma unroll
        for (int j = 0; j < 8; j++)
            #pragma unroll
            for (int q = 0; q < 4; q++) acc2[i][j][q] = 0.f;

    auto load_w1 = [&](int nc, int kt, int s){
        uint32_t base = wbb + s*16384;
        #pragma unroll
        for (int it = 0; it < 4; it++){
            int i = tid + it*256;
            int r = i>>3, c = i&7;
            const __half* src = g_w1hh + (size_t)(nc*128 + r)*256 + kt*64 + c*8;
            uint32_t dst = base + r*128 + ((c ^ (r&7))<<4);
            CPA(dst, src);
        }
        CPCOMMIT();
    };
    // combo cb: ks = cb>>1 (k half), nh = cb&1 (n half)
    auto load_w2 = [&](int nc, int cb, int s){
        int ks = cb>>1, nh = cb&1;
        uint32_t base = wbb + s*16384;
        #pragma unroll
        for (int it = 0; it < 4; it++){
            int i = tid + it*256;
            int r = i>>3, c = i&7;
            const __half* src = g_w2hh + (size_t)(nh*128 + r)*1024 + nc*128 + ks*64 + c*8;
            uint32_t dst = base + r*128 + ((c ^ (r&7))<<4);
            CPA(dst, src);
        }
        CPCOMMIT();
    };

    int g = lane>>2, t4 = lane&3;

    for (int nc = 0; nc < 8; nc++){
        // ---------- MLP1: acc1 = y @ w1[nc]^T, output 64 x 128 ----------
        float acc1[2][4][4];
        #pragma unroll
        for (int i = 0; i < 2; i++)
            #pragma unroll
            for (int j = 0; j < 4; j++)
                #pragma unroll
                for (int q = 0; q < 4; q++) acc1[i][j][q] = 0.f;

        load_w1(nc, 0, 0);
        for (int kt = 0; kt < 4; kt++){
            int s = kt & 1;
            if (kt+1 < 4){ load_w1(nc, kt+1, s^1); CPWAIT1(); }
            else CPWAIT0();
            __syncthreads();
            uint32_t As = ysb + kt*8192;
            uint32_t Bs = wbb + s*16384;
            #pragma unroll
            for (int kk = 0; kk < 4; kk++){
                uint32_t ah[2][4];
                #pragma unroll
                for (int mt = 0; mt < 2; mt++){
                    int r = wm*32 + mt*16 + (lane&15);
                    int ch = kk*2 + ((lane>>4)&1);
                    LDSM4(ah[mt], As + r*128 + ((ch ^ (r&7))<<4));
                }
                #pragma unroll
                for (int nt2 = 0; nt2 < 2; nt2++){
                    uint32_t bh[4];
                    int r = wn*32 + nt2*16 + (lane&7) + ((lane>>4)&1)*8;
                    int ch = kk*2 + ((lane>>3)&1);
                    LDSM4(bh, Bs + r*128 + ((ch ^ (r&7))<<4));
                    #pragma unroll
                    for (int mt = 0; mt < 2; mt++)
                        #pragma unroll
                        for (int hf = 0; hf < 2; hf++)
                            MMAH(acc1[mt][nt2*2+hf], ah[mt], &bh[hf*2]);
                }
            }
            __syncthreads();
        }

        // ---------- gelu + bias -> hbb (two 64x64 k-halves, 128B rows) ----------
        #pragma unroll
        for (int mt = 0; mt < 2; mt++){
            int R = wm*32 + mt*16 + g;
            #pragma unroll
            for (int nt = 0; nt < 4; nt++){
                int cl = wn*32 + nt*8 + t4*2;        // 0..127
                int Cg = nc*128 + cl;
                float b0v = __ldg(b1v + Cg), b1vv = __ldg(b1v + Cg + 1);
                float* d = acc1[mt][nt];
                int ksub = cl>>6, c8 = (cl>>3)&7, cb2 = cl&7;
                uint32_t o0 = hbb + ksub*8192 + R*128     + ((c8 ^ (R&7))<<4)     + cb2*2;
                uint32_t o8 = hbb + ksub*8192 + (R+8)*128 + ((c8 ^ ((R+8)&7))<<4) + cb2*2;
                *(uint32_t*)(dsm + (o0 - sb)) = pkh(geluf(d[0]+b0v), geluf(d[1]+b1vv));
                *(uint32_t*)(dsm + (o8 - sb)) = pkh(geluf(d[2]+b0v), geluf(d[3]+b1vv));
            }
        }
        __syncthreads();

        // ---------- MLP2 partial: acc2 += h_chunk @ w2^T over 4 (ks,nh) combos ----------
        load_w2(nc, 0, 0);
        for (int cb = 0; cb < 4; cb++){
            int s = cb & 1;
            if (cb+1 < 4){ load_w2(nc, cb+1, s^1); CPWAIT1(); }
            else CPWAIT0();
            __syncthreads();
            int ks = cb>>1, nh = cb&1;
            uint32_t As = hbb + ks*8192;
            uint32_t Bs = wbb + s*16384;
            #pragma unroll
            for (int kk = 0; kk < 4; kk++){
                uint32_t ah[2][4];
                #pragma unroll
                for (int mt = 0; mt < 2; mt++){
                    int r = wm*32 + mt*16 + (lane&15);
                    int ch = kk*2 + ((lane>>4)&1);
                    LDSM4(ah[mt], As + r*128 + ((ch ^ (r&7))<<4));
                }
                #pragma unroll
                for (int nt2 = 0; nt2 < 2; nt2++){
                    uint32_t bh[4];
                    int r = wn*32 + nt2*16 + (lane&7) + ((lane>>4)&1)*8;
                    int ch = kk*2 + ((lane>>3)&1);
                    LDSM4(bh, Bs + r*128 + ((ch ^ (r&7))<<4));
                    #pragma unroll
                    for (int mt = 0; mt < 2; mt++)
                        #pragma unroll
                        for (int hf = 0; hf < 2; hf++)
                            MMAH(acc2[mt][nh*4 + nt2*2 + hf], ah[mt], &bh[hf*2]);
                }
            }
            __syncthreads();
        }
    }

    // epilogue: out = acc2 + b2 + x2 (x2 reconstructed from y in smem)
    #pragma unroll
    for (int mt = 0; mt < 2; mt++){
        int Rl = wm*32 + mt*16 + g;
        size_t R0 = row0 + Rl;
        float mu0 = g_mu[R0],   sg0 = g_sg[R0];
        float mu8 = g_mu[R0+8], sg8 = g_sg[R0+8];
        #pragma unroll
        for (int j = 0; j < 8; j++){
            int nh = j>>2, nt2 = (j>>1)&1, hf = j&1;
            int C = nh*128 + wn*32 + nt2*16 + hf*8 + t4*2;
            float* d = acc2[mt][j];
            float b0v = __ldg(b2v + C), b1vv = __ldg(b2v + C + 1);
            float gg0 = __ldg(gamma2 + C), gg1 = __ldg(gamma2 + C + 1);
            float bt0 = __ldg(beta2 + C),  bt1 = __ldg(beta2 + C + 1);
            float ig0 = 1.f/gg0, ig1 = 1.f/gg1;
            uint32_t y0off = (C>>6)*8192 + Rl*128     + (((((C>>3)&7)) ^ (Rl&7))<<4)     + (C&7)*2;
            uint32_t y8off = (C>>6)*8192 + (Rl+8)*128 + (((((C>>3)&7)) ^ ((Rl+8)&7))<<4) + (C&7)*2;
            __half2 y0 = *(__half2*)(dsm + y0off);
            __half2 y8 = *(__half2*)(dsm + y8off);
            float x2a = (__half2float(y0.x) - bt0)*ig0*sg0 + mu0;
            float x2b = (__half2float(y0.y) - bt1)*ig1*sg0 + mu0;
            float x2c = (__half2float(y8.x) - bt0)*ig0*sg8 + mu8;
            float x2d = (__half2float(y8.y) - bt1)*ig1*sg8 + mu8;
            *(float2*)(outf + R0*256 + C)     = make_float2(d[0]+b0v+x2a, d[1]+b1vv+x2b);
            *(float2*)(outf + (R0+8)*256 + C) = make_float2(d[2]+b0v+x2c, d[3]+b1vv+x2d);
        }
    }
}

extern "C" void kernel_launch(void* const* d_in, const int* in_sizes, int n_in,
                              void* d_out, int out_size) {
    const float* x   = (const float*)d_in[0];
    const float* rot = (const float*)d_in[1];
    const float* n1g = (const float*)d_in[2];
    const float* n1b = (const float*)d_in[3];
    const float* qw  = (const float*)d_in[4];
    const float* kvw = (const float*)d_in[5];
    const float* n2g = (const float*)d_in[6];
    const float* n2b = (const float*)d_in[7];
    const float* w1  = (const float*)d_in[8];
    const float* b1  = (const float*)d_in[9];
    const float* w2  = (const float*)d_in[10];
    const float* b2  = (const float*)d_in[11];
    float* out = (float*)d_out;

    const int POOL_SM = (4*32*256 + 128)*4;
    const int ASM = 166016;
    const int MSM = 81920;
    cudaFuncSetAttribute(k_pool, cudaFuncAttributeMaxDynamicSharedMemorySize, POOL_SM);
    cudaFuncSetAttribute(k_attn, cudaFuncAttributeMaxDynamicSharedMemorySize, ASM);
    cudaFuncSetAttribute(k_mlp,  cudaFuncAttributeMaxDynamicSharedMemorySize, MSM);

    k_prepw<<<1280, 256>>>(w1, w2);
    k_ln1<<<(NB*NN)/128, 256>>>(x, rot, n1g, n1b);
    k_pool<<<dim3(NCH, NB), 128, POOL_SM>>>();
    k_kv<<<dim3(16, NB), 512>>>(kvw);
    k_prep<<<dim3(NB, 8), 256>>>(qw);
    k_attn<<<(NB*NN)/128, 256, ASM>>>(x, n2g, n2b);
    k_mlp<<<(NB*NN)/64, 256, MSM>>>(b1, b2, n2g, n2b, out);
}